// round 1
// baseline (speedup 1.0000x reference)
#include <cuda_runtime.h>
#include <math.h>
#include <stdint.h>

#define NN 50000
#define EE 1600000
#define FIN 770
#define HH 64
#define RR 3

// ---------------- scratch (device globals; no allocation allowed) ------------
__device__ float g_xr[(size_t)RR * NN * HH];   // per-relation transformed nodes
__device__ float g_bufa[(size_t)NN * HH];
__device__ float g_bufb[(size_t)NN * HH];
__device__ float g_ea[(size_t)NN * HH];        // x3 @ ew1_top
__device__ float g_eb[(size_t)NN * HH];        // x3 @ ew1_bot
__device__ float g_invc[RR * NN];
__device__ int   g_cnt[RR * NN];
__device__ int   g_row[EE];
__device__ int   g_col[EE];
__device__ int   g_et[EE];
__device__ int   g_is64;

// ---------------- edge dtype detection + conversion --------------------------
__global__ void k_detect(const unsigned int* __restrict__ ei) {
    if (threadIdx.x == 0 && blockIdx.x == 0) {
        int is64 = 1;
        for (int i = 0; i < 64; i++) {
            if (ei[2 * i + 1] != 0u) { is64 = 0; break; }
        }
        g_is64 = is64;
    }
}

__global__ void k_convert(const void* __restrict__ ei, const void* __restrict__ et) {
    int i = blockIdx.x * blockDim.x + threadIdx.x;
    if (i >= EE) return;
    if (g_is64) {
        const long long* p = (const long long*)ei;
        g_row[i] = (int)p[i];
        g_col[i] = (int)p[EE + i];
        g_et[i]  = (int)((const long long*)et)[i];
    } else {
        const int* p = (const int*)ei;
        g_row[i] = p[i];
        g_col[i] = p[EE + i];
        g_et[i]  = ((const int*)et)[i];
    }
}

// ---------------- degree counts (shared by all 3 layers) ----------------------
__global__ void k_zero_cnt() {
    int i = blockIdx.x * blockDim.x + threadIdx.x;
    if (i < RR * NN) g_cnt[i] = 0;
}
__global__ void k_count() {
    int e = blockIdx.x * blockDim.x + threadIdx.x;
    if (e >= EE) return;
    atomicAdd(&g_cnt[g_et[e] * NN + g_col[e]], 1);
}
__global__ void k_invc() {
    int i = blockIdx.x * blockDim.x + threadIdx.x;
    if (i >= RR * NN) return;
    int c = g_cnt[i];
    g_invc[i] = 1.0f / (float)(c > 0 ? c : 1);
}

// ---------------- generic batched GEMM: out[g] = X[M,K] @ W[g][K,64] (+bias) --
struct G4 {
    const float* W[4];
    const float* bias[4];
    float*       out[4];
};

__global__ void k_gemm(const float* __restrict__ X, int M, int K, G4 g) {
    const float* __restrict__ W    = g.W[blockIdx.y];
    const float* __restrict__ bias = g.bias[blockIdx.y];
    float*       __restrict__ out  = g.out[blockIdx.y];

    __shared__ __align__(16) float As[16][68];   // As[k][m]
    __shared__ __align__(16) float Bs[16][68];   // Bs[k][n]

    int tid = threadIdx.x;          // 256 threads
    int tx = tid & 15, ty = tid >> 4;
    int m0 = blockIdx.x * 64;

    float acc[4][4];
#pragma unroll
    for (int i = 0; i < 4; i++)
#pragma unroll
        for (int j = 0; j < 4; j++) acc[i][j] = 0.f;

    for (int k0 = 0; k0 < K; k0 += 16) {
        // A tile: 64 rows x 16 k, each thread loads 4 consecutive k
#pragma unroll
        for (int i = 0; i < 4; i++) {
            int l = tid * 4 + i;
            int m = l >> 4, k = l & 15;
            float v = 0.f;
            if (m0 + m < M && k0 + k < K) v = X[(size_t)(m0 + m) * K + k0 + k];
            As[k][m] = v;
        }
        // B tile: 16 k x 64 n
#pragma unroll
        for (int i = 0; i < 4; i++) {
            int l = tid * 4 + i;
            int k = l >> 6, n = l & 63;
            float v = 0.f;
            if (k0 + k < K) v = W[(size_t)(k0 + k) * 64 + n];
            Bs[k][n] = v;
        }
        __syncthreads();
#pragma unroll
        for (int kk = 0; kk < 16; kk++) {
            float4 a4 = *(const float4*)&As[kk][ty * 4];
            float4 b4 = *(const float4*)&Bs[kk][tx * 4];
            float av[4] = {a4.x, a4.y, a4.z, a4.w};
            float bv[4] = {b4.x, b4.y, b4.z, b4.w};
#pragma unroll
            for (int i = 0; i < 4; i++)
#pragma unroll
                for (int j = 0; j < 4; j++) acc[i][j] += av[i] * bv[j];
        }
        __syncthreads();
    }

#pragma unroll
    for (int i = 0; i < 4; i++) {
        int m = m0 + ty * 4 + i;
        if (m < M) {
#pragma unroll
            for (int j = 0; j < 4; j++) {
                int n = tx * 4 + j;
                float v = acc[i][j];
                if (bias) v += bias[n];
                out[(size_t)m * 64 + n] = v;
            }
        }
    }
}

// ---------------- edge aggregation: acc[dst] += xr[et][src] * invc[et,dst] ----
__global__ void k_aggregate(const float* __restrict__ xr, float* __restrict__ acc) {
    int idx = blockIdx.x * 256 + threadIdx.x;
    int e = idx >> 4;
    int t = idx & 15;
    if (e >= EE) return;
    int r = g_et[e], s = g_row[e], d = g_col[e];
    float sc = g_invc[r * NN + d];
    float4 m = *(const float4*)&xr[((size_t)r * NN + s) * HH + t * 4];
    float* a = &acc[(size_t)d * HH + t * 4];
    atomicAdd(a + 0, m.x * sc);
    atomicAdd(a + 1, m.y * sc);
    atomicAdd(a + 2, m.z * sc);
    atomicAdd(a + 3, m.w * sc);
}

__global__ void k_relu(float* __restrict__ a, int n) {
    int i = blockIdx.x * blockDim.x + threadIdx.x;
    if (i < n) a[i] = fmaxf(a[i], 0.f);
}

// ---------------- layernorm (warp per node, H=64) -----------------------------
__global__ void k_ln(const float* __restrict__ in, float* __restrict__ outp,
                     const float* __restrict__ gg, const float* __restrict__ bb) {
    int w = (blockIdx.x * blockDim.x + threadIdx.x) >> 5;
    int lane = threadIdx.x & 31;
    if (w >= NN) return;
    float v0 = in[(size_t)w * 64 + lane];
    float v1 = in[(size_t)w * 64 + lane + 32];
    float s = v0 + v1;
#pragma unroll
    for (int off = 16; off; off >>= 1) s += __shfl_xor_sync(~0u, s, off);
    float mu = s * (1.f / 64.f);
    float d0 = v0 - mu, d1 = v1 - mu;
    float q = d0 * d0 + d1 * d1;
#pragma unroll
    for (int off = 16; off; off >>= 1) q += __shfl_xor_sync(~0u, q, off);
    float rs = rsqrtf(q * (1.f / 64.f) + 1e-5f);
    outp[(size_t)w * 64 + lane]      = d0 * rs * gg[lane] + bb[lane];
    outp[(size_t)w * 64 + lane + 32] = d1 * rs * gg[lane + 32] + bb[lane + 32];
}

// ---------------- edge classifier (warp per edge) ------------------------------
__global__ void k_edge(const float* __restrict__ ea, const float* __restrict__ ebt,
                       const float* __restrict__ eb1, const float* __restrict__ ew2,
                       const float* __restrict__ eb2, float* __restrict__ outp) {
    __shared__ float s_b1[64], s_w2[192], s_b2[3];
    int tid = threadIdx.x;
    if (tid < 64)  s_b1[tid] = eb1[tid];
    if (tid < 192) s_w2[tid] = ew2[tid];
    if (tid < 3)   s_b2[tid] = eb2[tid];
    __syncthreads();

    int e = (blockIdx.x * blockDim.x + tid) >> 5;
    int lane = tid & 31;
    if (e >= EE) return;
    int r = g_row[e], c = g_col[e];
    float h0 = fmaxf(ea[(size_t)r * 64 + lane]      + ebt[(size_t)c * 64 + lane]      + s_b1[lane], 0.f);
    float h1 = fmaxf(ea[(size_t)r * 64 + lane + 32] + ebt[(size_t)c * 64 + lane + 32] + s_b1[lane + 32], 0.f);
    float p0 = h0 * s_w2[lane * 3 + 0] + h1 * s_w2[(lane + 32) * 3 + 0];
    float p1 = h0 * s_w2[lane * 3 + 1] + h1 * s_w2[(lane + 32) * 3 + 1];
    float p2 = h0 * s_w2[lane * 3 + 2] + h1 * s_w2[(lane + 32) * 3 + 2];
#pragma unroll
    for (int off = 16; off; off >>= 1) {
        p0 += __shfl_xor_sync(~0u, p0, off);
        p1 += __shfl_xor_sync(~0u, p1, off);
        p2 += __shfl_xor_sync(~0u, p2, off);
    }
    if (lane == 0) {
        float l0 = p0 + s_b2[0], l1 = p1 + s_b2[1], l2 = p2 + s_b2[2];
        float mx = fmaxf(l0, fmaxf(l1, l2));
        float lse = logf(expf(l0 - mx) + expf(l1 - mx) + expf(l2 - mx)) + mx;
        outp[(size_t)e * 3 + 0] = l0 - lse;
        outp[(size_t)e * 3 + 1] = l1 - lse;
        outp[(size_t)e * 3 + 2] = l2 - lse;
    }
}

// ---------------- node classifier (warp per node) ------------------------------
__global__ void k_node(const float* __restrict__ x3, const float* __restrict__ nw1,
                       const float* __restrict__ nb1, const float* __restrict__ nw2,
                       const float* __restrict__ nb2, float* __restrict__ outp) {
    __shared__ float s_w1[64 * 32];
    __shared__ float s_b1[32], s_w2[64], s_b2[2];
    int tid = threadIdx.x;
    for (int i = tid; i < 2048; i += blockDim.x) s_w1[i] = nw1[i];
    if (tid < 32) s_b1[tid] = nb1[tid];
    if (tid < 64) s_w2[tid] = nw2[tid];
    if (tid < 2)  s_b2[tid] = nb2[tid];
    __syncthreads();

    int nidx = (blockIdx.x * blockDim.x + tid) >> 5;
    int lane = tid & 31;
    if (nidx >= NN) return;
    float xa = x3[(size_t)nidx * 64 + lane];
    float xb = x3[(size_t)nidx * 64 + lane + 32];
    float acc = s_b1[lane];
#pragma unroll
    for (int k = 0; k < 32; k++) {
        float xv = __shfl_sync(~0u, xa, k);
        acc += xv * s_w1[k * 32 + lane];
    }
#pragma unroll
    for (int k = 0; k < 32; k++) {
        float xv = __shfl_sync(~0u, xb, k);
        acc += xv * s_w1[(k + 32) * 32 + lane];
    }
    float nh = fmaxf(acc, 0.f);
    float p0 = nh * s_w2[lane * 2 + 0];
    float p1 = nh * s_w2[lane * 2 + 1];
#pragma unroll
    for (int off = 16; off; off >>= 1) {
        p0 += __shfl_xor_sync(~0u, p0, off);
        p1 += __shfl_xor_sync(~0u, p1, off);
    }
    if (lane == 0) {
        float l0 = p0 + s_b2[0], l1 = p1 + s_b2[1];
        float mx = fmaxf(l0, l1);
        float lse = logf(expf(l0 - mx) + expf(l1 - mx)) + mx;
        outp[(size_t)3 * EE + (size_t)nidx * 2 + 0] = l0 - lse;
        outp[(size_t)3 * EE + (size_t)nidx * 2 + 1] = l1 - lse;
    }
}

// ---------------- host orchestration ------------------------------------------
extern "C" void kernel_launch(void* const* d_in, const int* in_sizes, int n_in,
                              void* d_out, int out_size) {
    const float* x     = (const float*)d_in[0];
    const void*  eidx  = d_in[1];
    const void*  etyp  = d_in[2];
    const float* W1    = (const float*)d_in[3];
    const float* root1 = (const float*)d_in[4];
    const float* b1    = (const float*)d_in[5];
    const float* W2    = (const float*)d_in[6];
    const float* root2 = (const float*)d_in[7];
    const float* b2    = (const float*)d_in[8];
    const float* W3    = (const float*)d_in[9];
    const float* root3 = (const float*)d_in[10];
    const float* b3    = (const float*)d_in[11];
    const float* ln_g  = (const float*)d_in[12];
    const float* ln_b  = (const float*)d_in[13];
    const float* ew1   = (const float*)d_in[14];
    const float* eb1   = (const float*)d_in[15];
    const float* ew2   = (const float*)d_in[16];
    const float* eb2   = (const float*)d_in[17];
    const float* nw1   = (const float*)d_in[18];
    const float* nb1   = (const float*)d_in[19];
    const float* nw2   = (const float*)d_in[20];
    const float* nb2   = (const float*)d_in[21];
    float* out = (float*)d_out;

    float *p_xr, *p_bufa, *p_bufb, *p_ea, *p_eb;
    cudaGetSymbolAddress((void**)&p_xr,   g_xr);
    cudaGetSymbolAddress((void**)&p_bufa, g_bufa);
    cudaGetSymbolAddress((void**)&p_bufb, g_bufb);
    cudaGetSymbolAddress((void**)&p_ea,   g_ea);
    cudaGetSymbolAddress((void**)&p_eb,   g_eb);

    // edge structure prep (once per launch)
    k_detect<<<1, 32>>>((const unsigned int*)eidx);
    k_convert<<<(EE + 255) / 256, 256>>>(eidx, etyp);
    k_zero_cnt<<<(RR * NN + 255) / 256, 256>>>();
    k_count<<<(EE + 255) / 256, 256>>>();
    k_invc<<<(RR * NN + 255) / 256, 256>>>();

    dim3 grid4((NN + 63) / 64, 4);
    dim3 grid2((NN + 63) / 64, 2);
    int aggBlocks  = (EE * 16 + 255) / 256;
    int reluBlocks = (NN * HH + 255) / 256;
    int warpNBlocks = (NN * 32 + 255) / 256;

    // ---- layer 1 ----
    G4 g;
    g.W[0] = W1;
    g.W[1] = W1 + (size_t)FIN * HH;
    g.W[2] = W1 + 2 * (size_t)FIN * HH;
    g.W[3] = root1;
    g.bias[0] = g.bias[1] = g.bias[2] = nullptr; g.bias[3] = b1;
    g.out[0] = p_xr;
    g.out[1] = p_xr + (size_t)NN * HH;
    g.out[2] = p_xr + 2 * (size_t)NN * HH;
    g.out[3] = p_bufa;
    k_gemm<<<grid4, 256>>>(x, NN, FIN, g);
    k_aggregate<<<aggBlocks, 256>>>(p_xr, p_bufa);
    k_relu<<<reluBlocks, 256>>>(p_bufa, NN * HH);

    // ---- layer 2 ----
    g.W[0] = W2;
    g.W[1] = W2 + (size_t)HH * HH;
    g.W[2] = W2 + 2 * (size_t)HH * HH;
    g.W[3] = root2;
    g.bias[3] = b2;
    g.out[3] = p_bufb;
    k_gemm<<<grid4, 256>>>(p_bufa, NN, HH, g);
    k_aggregate<<<aggBlocks, 256>>>(p_xr, p_bufb);
    k_relu<<<reluBlocks, 256>>>(p_bufb, NN * HH);

    // ---- layer 3 ----
    g.W[0] = W3;
    g.W[1] = W3 + (size_t)HH * HH;
    g.W[2] = W3 + 2 * (size_t)HH * HH;
    g.W[3] = root3;
    g.bias[3] = b3;
    g.out[3] = p_bufa;
    k_gemm<<<grid4, 256>>>(p_bufb, NN, HH, g);
    k_aggregate<<<aggBlocks, 256>>>(p_xr, p_bufa);
    k_ln<<<warpNBlocks, 256>>>(p_bufa, p_bufb, ln_g, ln_b);   // x3 in p_bufb

    // ---- edge head precompute: ea = x3 @ ew1_top, eb = x3 @ ew1_bot ----
    G4 ge;
    ge.W[0] = ew1;
    ge.W[1] = ew1 + (size_t)HH * HH;
    ge.W[2] = ew1; ge.W[3] = ew1;           // unused
    ge.bias[0] = ge.bias[1] = ge.bias[2] = ge.bias[3] = nullptr;
    ge.out[0] = p_ea; ge.out[1] = p_eb; ge.out[2] = p_ea; ge.out[3] = p_ea;
    k_gemm<<<grid2, 256>>>(p_bufb, NN, HH, ge);

    // ---- heads ----
    k_edge<<<(EE * 32 + 255) / 256, 256>>>(p_ea, p_eb, eb1, ew2, eb2, out);
    k_node<<<warpNBlocks, 256>>>(p_bufb, nw1, nb1, nw2, nb2, out);
}

// round 3
// speedup vs baseline: 1.9204x; 1.9204x over previous
#include <cuda_runtime.h>
#include <math.h>
#include <stdint.h>

#define NN 50000
#define EE 1600000
#define FIN 770
#define RR 3
#define KP1 800

// ---------------- scratch ------------------------------------------------------
__device__ float g_xpad[(size_t)NN * KP1];     // x padded to 800 cols (16B aligned rows)
__device__ float g_xr[(size_t)RR * NN * 64];
__device__ float g_bufa[(size_t)NN * 64];
__device__ float g_bufb[(size_t)NN * 64];
__device__ float g_ea[(size_t)NN * 64];
__device__ float g_eb[(size_t)NN * 64];
__device__ float g_invc[RR * NN];
__device__ int   g_cnt[RR * NN];
__device__ int   g_row[EE];
__device__ int   g_col[EE];
__device__ int   g_et[EE];
__device__ int   g_is64;
__device__ float g_wt1[256 * KP1];
__device__ float g_wt2[256 * 64];
__device__ float g_wt3[256 * 64];
__device__ float g_wte[128 * 64];

// ---------------- helpers ------------------------------------------------------
__device__ __forceinline__ uint32_t smem_u32(const void* p) {
    uint32_t a;
    asm("{ .reg .u64 t; cvta.to.shared.u64 t, %1; cvt.u32.u64 %0, t; }" : "=r"(a) : "l"(p));
    return a;
}
__device__ __forceinline__ void cp16(uint32_t dst, const void* src, int sz) {
    asm volatile("cp.async.cg.shared.global [%0], [%1], 16, %2;"
                 :: "r"(dst), "l"(src), "r"(sz) : "memory");
}
__device__ __forceinline__ uint32_t cvt_tf32(float f) {
    uint32_t r;
    asm("cvt.rna.tf32.f32 %0, %1;" : "=r"(r) : "f"(f));
    return r;
}
__device__ __forceinline__ float tf32r(float x) {
    return __uint_as_float(cvt_tf32(x));
}
__device__ __forceinline__ void mma8(float* c, const uint32_t* a, uint32_t b0, uint32_t b1) {
    asm volatile(
        "mma.sync.aligned.m16n8k8.row.col.f32.tf32.tf32.f32 "
        "{%0,%1,%2,%3}, {%4,%5,%6,%7}, {%8,%9}, {%0,%1,%2,%3};"
        : "+f"(c[0]), "+f"(c[1]), "+f"(c[2]), "+f"(c[3])
        : "r"(a[0]), "r"(a[1]), "r"(a[2]), "r"(a[3]), "r"(b0), "r"(b1));
}

// ---------------- edge dtype detection + conversion ----------------------------
__global__ void k_detect(const unsigned int* __restrict__ ei) {
    if (threadIdx.x == 0 && blockIdx.x == 0) {
        int is64 = 1;
        for (int i = 0; i < 64; i++)
            if (ei[2 * i + 1] != 0u) { is64 = 0; break; }
        g_is64 = is64;
    }
}
__global__ void k_convert(const void* __restrict__ ei, const void* __restrict__ et) {
    int i = blockIdx.x * blockDim.x + threadIdx.x;
    if (i >= EE) return;
    if (g_is64) {
        const long long* p = (const long long*)ei;
        g_row[i] = (int)p[i];
        g_col[i] = (int)p[EE + i];
        g_et[i]  = (int)((const long long*)et)[i];
    } else {
        const int* p = (const int*)ei;
        g_row[i] = p[i];
        g_col[i] = p[EE + i];
        g_et[i]  = ((const int*)et)[i];
    }
}
__global__ void k_zero_cnt() {
    int i = blockIdx.x * blockDim.x + threadIdx.x;
    if (i < RR * NN) g_cnt[i] = 0;
}
__global__ void k_count() {
    int e = blockIdx.x * blockDim.x + threadIdx.x;
    if (e >= EE) return;
    atomicAdd(&g_cnt[g_et[e] * NN + g_col[e]], 1);
}
__global__ void k_invc() {
    int i = blockIdx.x * blockDim.x + threadIdx.x;
    if (i >= RR * NN) return;
    int c = g_cnt[i];
    g_invc[i] = 1.0f / (float)(c > 0 ? c : 1);
}

// ---------------- x padding: [N,770] -> [N,800] --------------------------------
__global__ void k_pad(const float* __restrict__ x) {
    size_t i = (size_t)blockIdx.x * blockDim.x + threadIdx.x;
    if (i >= (size_t)NN * KP1) return;
    int n = (int)(i / KP1), k = (int)(i % KP1);
    g_xpad[i] = (k < FIN) ? x[(size_t)n * FIN + k] : 0.f;
}

// ---------------- weight packing (tf32-rounded, K-major [N,Kp]) -----------------
__global__ void k_pack_big(const float* __restrict__ W, const float* __restrict__ root) {
    int i = blockIdx.x * 256 + threadIdx.x;
    if (i >= 256 * KP1) return;
    int n = i / KP1, k = i % KP1;
    float v = 0.f;
    if (k < FIN)
        v = (n < 192) ? W[(size_t)(n >> 6) * FIN * 64 + (size_t)k * 64 + (n & 63)]
                      : root[(size_t)k * 64 + (n - 192)];
    g_wt1[i] = tf32r(v);
}
__global__ void k_pack_small(const float* __restrict__ W, const float* __restrict__ root,
                             float* __restrict__ outw) {
    int i = blockIdx.x * 256 + threadIdx.x;
    if (i >= 256 * 64) return;
    int n = i >> 6, k = i & 63;
    float v = (n < 192) ? W[(n >> 6) * 4096 + k * 64 + (n & 63)]
                        : root[k * 64 + (n - 192)];
    outw[i] = tf32r(v);
}
__global__ void k_pack_eh(const float* __restrict__ ew1) {
    int i = blockIdx.x * 256 + threadIdx.x;
    if (i >= 128 * 64) return;
    int n = i >> 6, k = i & 63;
    float v = (n < 64) ? ew1[k * 64 + n] : ew1[(64 + k) * 64 + (n - 64)];
    g_wte[i] = tf32r(v);
}

// ---------------- tf32 mma.sync GEMM: [M,Kp] @ [N,Kp]^T, N = NT*64 --------------
// SMEM (floats): A[2][128][36] at 0, B[2][NT*64][36] at 9216
// Row stride 36 floats (144B): bank = (4*row + k) mod 32 -> conflict-free frags.
template<int NT>
__device__ __forceinline__ void issue_chunk(const float* __restrict__ X,
                                            const float* __restrict__ Wt,
                                            int M, int Kp, int m0, int c, uint32_t sb) {
    int tid = threadIdx.x;
    int k0 = c * 32;
    uint32_t ab = sb + (uint32_t)(c & 1) * 18432u;
    uint32_t bb = sb + 36864u + (uint32_t)(c & 1) * (uint32_t)(NT * 64 * 144);
#pragma unroll
    for (int i = 0; i < 2; i++) {
        int u = tid * 2 + i;                 // 1024 units: 128 rows x 8
        int row = u >> 3, j = u & 7;
        int ok = (m0 + row) < M;
        const float* src = ok ? (X + (size_t)(m0 + row) * Kp + k0 + j * 4) : X;
        cp16(ab + row * 144 + j * 16, src, ok ? 16 : 0);
    }
#pragma unroll
    for (int v = 0; v < NT; v++) {
        int u = v * 512 + tid;               // NT*512 units: NT*64 rows x 8
        int row = u >> 3, j = u & 7;
        cp16(bb + row * 144 + j * 16, Wt + (size_t)row * Kp + k0 + j * 4, 16);
    }
    asm volatile("cp.async.commit_group;" ::: "memory");
}

template<int NT>
__global__ __launch_bounds__(512) void k_mma(
    const float* __restrict__ X, const float* __restrict__ Wt,
    int M, int Kp,
    float* __restrict__ o0, float* __restrict__ o1,
    float* __restrict__ o2, float* __restrict__ o3,
    const float* __restrict__ bias3)
{
    extern __shared__ float smf[];
    uint32_t sb = smem_u32(smf);
    const int MT = NT / 2 ? NT / 2 : 1;      // NT=4 -> 2, NT=2 -> 1
    int tid = threadIdx.x, wid = tid >> 5, lane = tid & 31;
    int g = lane >> 2, tig = lane & 3;
    int wn = wid % NT, wm = wid / NT;
    int rowbase = wm * MT * 16;
    int m0 = blockIdx.x * 128;
    int NC = Kp / 32;

    float acc[MT][8][4];
#pragma unroll
    for (int mt = 0; mt < MT; mt++)
#pragma unroll
        for (int nt = 0; nt < 8; nt++)
#pragma unroll
            for (int q = 0; q < 4; q++) acc[mt][nt][q] = 0.f;

    issue_chunk<NT>(X, Wt, M, Kp, m0, 0, sb);

    for (int c = 0; c < NC; c++) {
        if (c + 1 < NC) {
            issue_chunk<NT>(X, Wt, M, Kp, m0, c + 1, sb);
            asm volatile("cp.async.wait_group 1;" ::: "memory");
        } else {
            asm volatile("cp.async.wait_group 0;" ::: "memory");
        }
        __syncthreads();

        int af = (c & 1) * 4608;                       // float offsets
        int bf = 9216 + (c & 1) * (NT * 64 * 36);
#pragma unroll
        for (int k8 = 0; k8 < 4; k8++) {
            uint32_t A[MT][4];
#pragma unroll
            for (int mt = 0; mt < MT; mt++) {
                int r0 = rowbase + mt * 16 + g;
                int base = af + r0 * 36 + k8 * 8 + tig;
                A[mt][0] = cvt_tf32(smf[base]);
                A[mt][1] = cvt_tf32(smf[base + 8 * 36]);
                A[mt][2] = cvt_tf32(smf[base + 4]);
                A[mt][3] = cvt_tf32(smf[base + 8 * 36 + 4]);
            }
#pragma unroll
            for (int nt = 0; nt < 8; nt++) {
                int n = wn * 64 + nt * 8 + g;
                int base = bf + n * 36 + k8 * 8 + tig;
                uint32_t b0 = __float_as_uint(smf[base]);      // pre-rounded tf32
                uint32_t b1 = __float_as_uint(smf[base + 4]);
#pragma unroll
                for (int mt = 0; mt < MT; mt++)
                    mma8(acc[mt][nt], A[mt], b0, b1);
            }
        }
        __syncthreads();
    }

    // epilogue
    float* outs4[4] = {o0, o1, o2, o3};
    float* o = outs4[wn];
#pragma unroll
    for (int mt = 0; mt < MT; mt++) {
        int mA = m0 + rowbase + mt * 16 + g;
        int mB = mA + 8;
#pragma unroll
        for (int nt = 0; nt < 8; nt++) {
            int col = nt * 8 + tig * 2;
            float c0 = acc[mt][nt][0], c1 = acc[mt][nt][1];
            float c2 = acc[mt][nt][2], c3 = acc[mt][nt][3];
            if (bias3 && wn == NT - 1) {
                float bb0 = bias3[col], bb1 = bias3[col + 1];
                c0 += bb0; c1 += bb1; c2 += bb0; c3 += bb1;
            }
            if (mA < M) *(float2*)(o + (size_t)mA * 64 + col) = make_float2(c0, c1);
            if (mB < M) *(float2*)(o + (size_t)mB * 64 + col) = make_float2(c2, c3);
        }
    }
}

// ---------------- edge aggregation: acc[dst] += xr[et][src] * invc[et,dst] -----
__global__ void k_aggregate(const float* __restrict__ xr, float* __restrict__ acc) {
    int idx = blockIdx.x * 256 + threadIdx.x;
    int e = idx >> 4;
    int t = idx & 15;
    if (e >= EE) return;
    int r = g_et[e], s = g_row[e], d = g_col[e];
    float sc = g_invc[r * NN + d];
    float4 m = *(const float4*)&xr[((size_t)r * NN + s) * 64 + t * 4];
    float* a = &acc[(size_t)d * 64 + t * 4];
    asm volatile("red.global.add.v4.f32 [%0], {%1, %2, %3, %4};"
                 :: "l"(a), "f"(m.x * sc), "f"(m.y * sc), "f"(m.z * sc), "f"(m.w * sc)
                 : "memory");
}

__global__ void k_relu(float* __restrict__ a, int n) {
    int i = blockIdx.x * blockDim.x + threadIdx.x;
    if (i < n) a[i] = fmaxf(a[i], 0.f);
}

// ---------------- layernorm (warp per node, H=64) ------------------------------
__global__ void k_ln(const float* __restrict__ in, float* __restrict__ outp,
                     const float* __restrict__ gg, const float* __restrict__ bb) {
    int w = (blockIdx.x * blockDim.x + threadIdx.x) >> 5;
    int lane = threadIdx.x & 31;
    if (w >= NN) return;
    float v0 = in[(size_t)w * 64 + lane];
    float v1 = in[(size_t)w * 64 + lane + 32];
    float s = v0 + v1;
#pragma unroll
    for (int off = 16; off; off >>= 1) s += __shfl_xor_sync(~0u, s, off);
    float mu = s * (1.f / 64.f);
    float d0 = v0 - mu, d1 = v1 - mu;
    float q = d0 * d0 + d1 * d1;
#pragma unroll
    for (int off = 16; off; off >>= 1) q += __shfl_xor_sync(~0u, q, off);
    float rs = rsqrtf(q * (1.f / 64.f) + 1e-5f);
    outp[(size_t)w * 64 + lane]      = d0 * rs * gg[lane] + bb[lane];
    outp[(size_t)w * 64 + lane + 32] = d1 * rs * gg[lane + 32] + bb[lane + 32];
}

// ---------------- edge classifier (warp per edge) ------------------------------
__global__ void k_edge(const float* __restrict__ ea, const float* __restrict__ ebt,
                       const float* __restrict__ eb1, const float* __restrict__ ew2,
                       const float* __restrict__ eb2, float* __restrict__ outp) {
    __shared__ float s_b1[64], s_w2[192], s_b2[3];
    int tid = threadIdx.x;
    if (tid < 64)  s_b1[tid] = eb1[tid];
    if (tid < 192) s_w2[tid] = ew2[tid];
    if (tid < 3)   s_b2[tid] = eb2[tid];
    __syncthreads();

    int e = (blockIdx.x * blockDim.x + tid) >> 5;
    int lane = tid & 31;
    if (e >= EE) return;
    int r = g_row[e], c = g_col[e];
    float h0 = fmaxf(ea[(size_t)r * 64 + lane]      + ebt[(size_t)c * 64 + lane]      + s_b1[lane], 0.f);
    float h1 = fmaxf(ea[(size_t)r * 64 + lane + 32] + ebt[(size_t)c * 64 + lane + 32] + s_b1[lane + 32], 0.f);
    float p0 = h0 * s_w2[lane * 3 + 0] + h1 * s_w2[(lane + 32) * 3 + 0];
    float p1 = h0 * s_w2[lane * 3 + 1] + h1 * s_w2[(lane + 32) * 3 + 1];
    float p2 = h0 * s_w2[lane * 3 + 2] + h1 * s_w2[(lane + 32) * 3 + 2];
#pragma unroll
    for (int off = 16; off; off >>= 1) {
        p0 += __shfl_xor_sync(~0u, p0, off);
        p1 += __shfl_xor_sync(~0u, p1, off);
        p2 += __shfl_xor_sync(~0u, p2, off);
    }
    if (lane == 0) {
        float l0 = p0 + s_b2[0], l1 = p1 + s_b2[1], l2 = p2 + s_b2[2];
        float mx = fmaxf(l0, fmaxf(l1, l2));
        float lse = logf(expf(l0 - mx) + expf(l1 - mx) + expf(l2 - mx)) + mx;
        outp[(size_t)e * 3 + 0] = l0 - lse;
        outp[(size_t)e * 3 + 1] = l1 - lse;
        outp[(size_t)e * 3 + 2] = l2 - lse;
    }
}

// ---------------- node classifier (warp per node) ------------------------------
__global__ void k_node(const float* __restrict__ x3, const float* __restrict__ nw1,
                       const float* __restrict__ nb1, const float* __restrict__ nw2,
                       const float* __restrict__ nb2, float* __restrict__ outp) {
    __shared__ float s_w1[64 * 32];
    __shared__ float s_b1[32], s_w2[64], s_b2[2];
    int tid = threadIdx.x;
    for (int i = tid; i < 2048; i += blockDim.x) s_w1[i] = nw1[i];
    if (tid < 32) s_b1[tid] = nb1[tid];
    if (tid < 64) s_w2[tid] = nw2[tid];
    if (tid < 2)  s_b2[tid] = nb2[tid];
    __syncthreads();

    int nidx = (blockIdx.x * blockDim.x + tid) >> 5;
    int lane = tid & 31;
    if (nidx >= NN) return;
    float xa = x3[(size_t)nidx * 64 + lane];
    float xb = x3[(size_t)nidx * 64 + lane + 32];
    float acc = s_b1[lane];
#pragma unroll
    for (int k = 0; k < 32; k++) {
        float xv = __shfl_sync(~0u, xa, k);
        acc += xv * s_w1[k * 32 + lane];
    }
#pragma unroll
    for (int k = 0; k < 32; k++) {
        float xv = __shfl_sync(~0u, xb, k);
        acc += xv * s_w1[(k + 32) * 32 + lane];
    }
    float nh = fmaxf(acc, 0.f);
    float p0 = nh * s_w2[lane * 2 + 0];
    float p1 = nh * s_w2[lane * 2 + 1];
#pragma unroll
    for (int off = 16; off; off >>= 1) {
        p0 += __shfl_xor_sync(~0u, p0, off);
        p1 += __shfl_xor_sync(~0u, p1, off);
    }
    if (lane == 0) {
        float l0 = p0 + s_b2[0], l1 = p1 + s_b2[1];
        float mx = fmaxf(l0, l1);
        float lse = logf(expf(l0 - mx) + expf(l1 - mx)) + mx;
        outp[(size_t)3 * EE + (size_t)nidx * 2 + 0] = l0 - lse;
        outp[(size_t)3 * EE + (size_t)nidx * 2 + 1] = l1 - lse;
    }
}

// ---------------- host orchestration -------------------------------------------
extern "C" void kernel_launch(void* const* d_in, const int* in_sizes, int n_in,
                              void* d_out, int out_size) {
    const float* x     = (const float*)d_in[0];
    const void*  eidx  = d_in[1];
    const void*  etyp  = d_in[2];
    const float* W1    = (const float*)d_in[3];
    const float* root1 = (const float*)d_in[4];
    const float* b1    = (const float*)d_in[5];
    const float* W2    = (const float*)d_in[6];
    const float* root2 = (const float*)d_in[7];
    const float* b2    = (const float*)d_in[8];
    const float* W3    = (const float*)d_in[9];
    const float* root3 = (const float*)d_in[10];
    const float* b3    = (const float*)d_in[11];
    const float* ln_g  = (const float*)d_in[12];
    const float* ln_b  = (const float*)d_in[13];
    const float* ew1   = (const float*)d_in[14];
    const float* eb1   = (const float*)d_in[15];
    const float* ew2   = (const float*)d_in[16];
    const float* eb2   = (const float*)d_in[17];
    const float* nw1   = (const float*)d_in[18];
    const float* nb1   = (const float*)d_in[19];
    const float* nw2   = (const float*)d_in[20];
    const float* nb2   = (const float*)d_in[21];
    float* out = (float*)d_out;

    float *p_xpad, *p_xr, *p_bufa, *p_bufb, *p_ea, *p_eb, *p_wt1, *p_wt2, *p_wt3, *p_wte;
    cudaGetSymbolAddress((void**)&p_xpad, g_xpad);
    cudaGetSymbolAddress((void**)&p_xr,   g_xr);
    cudaGetSymbolAddress((void**)&p_bufa, g_bufa);
    cudaGetSymbolAddress((void**)&p_bufb, g_bufb);
    cudaGetSymbolAddress((void**)&p_ea,   g_ea);
    cudaGetSymbolAddress((void**)&p_eb,   g_eb);
    cudaGetSymbolAddress((void**)&p_wt1,  g_wt1);
    cudaGetSymbolAddress((void**)&p_wt2,  g_wt2);
    cudaGetSymbolAddress((void**)&p_wt3,  g_wt3);
    cudaGetSymbolAddress((void**)&p_wte,  g_wte);

    const int SMEM4 = (9216 + 2 * 256 * 36) * 4;   // 110592 B
    const int SMEM2 = (9216 + 2 * 128 * 36) * 4;   //  73728 B
    cudaFuncSetAttribute(k_mma<4>, cudaFuncAttributeMaxDynamicSharedMemorySize, SMEM4);
    cudaFuncSetAttribute(k_mma<2>, cudaFuncAttributeMaxDynamicSharedMemorySize, SMEM2);

    // edge structure prep + x padding
    k_detect<<<1, 32>>>((const unsigned int*)eidx);
    k_convert<<<(EE + 255) / 256, 256>>>(eidx, etyp);
    k_zero_cnt<<<(RR * NN + 255) / 256, 256>>>();
    k_count<<<(EE + 255) / 256, 256>>>();
    k_invc<<<(RR * NN + 255) / 256, 256>>>();
    k_pad<<<(int)(((size_t)NN * KP1 + 255) / 256), 256>>>(x);

    int tiles = (NN + 127) / 128;            // 391
    int aggBlocks  = (EE * 16 + 255) / 256;
    int reluBlocks = (NN * 64 + 255) / 256;
    int warpNBlocks = (NN * 32 + 255) / 256;
    size_t NH = (size_t)NN * 64;

    // ---- layer 1 ----
    k_pack_big<<<(256 * KP1 + 255) / 256, 256>>>(W1, root1);
    k_mma<4><<<tiles, 512, SMEM4>>>(p_xpad, p_wt1, NN, KP1,
                                    p_xr, p_xr + NH, p_xr + 2 * NH, p_bufa, b1);
    k_aggregate<<<aggBlocks, 256>>>(p_xr, p_bufa);
    k_relu<<<reluBlocks, 256>>>(p_bufa, NN * 64);

    // ---- layer 2 ----
    k_pack_small<<<(256 * 64 + 255) / 256, 256>>>(W2, root2, p_wt2);
    k_mma<4><<<tiles, 512, SMEM4>>>(p_bufa, p_wt2, NN, 64,
                                    p_xr, p_xr + NH, p_xr + 2 * NH, p_bufb, b2);
    k_aggregate<<<aggBlocks, 256>>>(p_xr, p_bufb);
    k_relu<<<reluBlocks, 256>>>(p_bufb, NN * 64);

    // ---- layer 3 ----
    k_pack_small<<<(256 * 64 + 255) / 256, 256>>>(W3, root3, p_wt3);
    k_mma<4><<<tiles, 512, SMEM4>>>(p_bufb, p_wt3, NN, 64,
                                    p_xr, p_xr + NH, p_xr + 2 * NH, p_bufa, b3);
    k_aggregate<<<aggBlocks, 256>>>(p_xr, p_bufa);
    k_ln<<<warpNBlocks, 256>>>(p_bufa, p_bufb, ln_g, ln_b);    // x3 -> p_bufb

    // ---- edge head precompute ----
    k_pack_eh<<<(128 * 64 + 255) / 256, 256>>>(ew1);
    k_mma<2><<<tiles, 512, SMEM2>>>(p_bufb, p_wte, NN, 64,
                                    p_ea, p_eb, nullptr, nullptr, nullptr);

    // ---- heads ----
    k_edge<<<(EE * 32 + 255) / 256, 256>>>(p_ea, p_eb, eb1, ew2, eb2, out);
    k_node<<<warpNBlocks, 256>>>(p_bufb, nw1, nb1, nw2, nb2, out);
}

// round 4
// speedup vs baseline: 2.9817x; 1.5527x over previous
#include <cuda_runtime.h>
#include <math.h>
#include <stdint.h>

#define NN 50000
#define EE 1600000
#define FIN 770
#define RR 3
#define KP1 800
#define SEG (RR * NN)          // 150000
#define SCANB ((SEG + 255) / 256)   // 586

// ---------------- scratch ------------------------------------------------------
__device__ float g_xr[(size_t)RR * NN * 64];
__device__ float g_bufa[(size_t)NN * 64];
__device__ float g_bufb[(size_t)NN * 64];
__device__ float g_ea[(size_t)NN * 64];
__device__ float g_eb[(size_t)NN * 64];
__device__ float g_invc[SEG];
__device__ int   g_cnt[SEG];
__device__ int   g_off[SEG];
__device__ int   g_fill[SEG];
__device__ int   g_bsum[1024];
__device__ int   g_srcl[EE];
__device__ int   g_row[EE];
__device__ int   g_col[EE];
__device__ int   g_et[EE];
__device__ int   g_is64;
__device__ float g_wt1[256 * KP1];
__device__ float g_wt2[256 * 64];
__device__ float g_wt3[256 * 64];
__device__ float g_wte[128 * 64];

// ---------------- helpers ------------------------------------------------------
__device__ __forceinline__ uint32_t smem_u32(const void* p) {
    uint32_t a;
    asm("{ .reg .u64 t; cvta.to.shared.u64 t, %1; cvt.u32.u64 %0, t; }" : "=r"(a) : "l"(p));
    return a;
}
__device__ __forceinline__ void cp16(uint32_t dst, const void* src, int sz) {
    asm volatile("cp.async.cg.shared.global [%0], [%1], 16, %2;"
                 :: "r"(dst), "l"(src), "r"(sz) : "memory");
}
__device__ __forceinline__ void cp8(uint32_t dst, const void* src, int sz) {
    asm volatile("cp.async.ca.shared.global [%0], [%1], 8, %2;"
                 :: "r"(dst), "l"(src), "r"(sz) : "memory");
}
__device__ __forceinline__ uint32_t cvt_tf32(float f) {
    uint32_t r;
    asm("cvt.rna.tf32.f32 %0, %1;" : "=r"(r) : "f"(f));
    return r;
}
__device__ __forceinline__ float tf32r(float x) { return __uint_as_float(cvt_tf32(x)); }
__device__ __forceinline__ void mma8(float* c, const uint32_t* a, uint32_t b0, uint32_t b1) {
    asm volatile(
        "mma.sync.aligned.m16n8k8.row.col.f32.tf32.tf32.f32 "
        "{%0,%1,%2,%3}, {%4,%5,%6,%7}, {%8,%9}, {%0,%1,%2,%3};"
        : "+f"(c[0]), "+f"(c[1]), "+f"(c[2]), "+f"(c[3])
        : "r"(a[0]), "r"(a[1]), "r"(a[2]), "r"(a[3]), "r"(b0), "r"(b1));
}

// ---------------- edge dtype detection + conversion ----------------------------
__global__ void k_detect(const unsigned int* __restrict__ ei) {
    if (threadIdx.x == 0 && blockIdx.x == 0) {
        int is64 = 1;
        for (int i = 0; i < 64; i++)
            if (ei[2 * i + 1] != 0u) { is64 = 0; break; }
        g_is64 = is64;
    }
}
__global__ void k_convert(const void* __restrict__ ei, const void* __restrict__ et) {
    int i = blockIdx.x * blockDim.x + threadIdx.x;
    if (i >= EE) return;
    if (g_is64) {
        const long long* p = (const long long*)ei;
        g_row[i] = (int)p[i];
        g_col[i] = (int)p[EE + i];
        g_et[i]  = (int)((const long long*)et)[i];
    } else {
        const int* p = (const int*)ei;
        g_row[i] = p[i];
        g_col[i] = p[EE + i];
        g_et[i]  = ((const int*)et)[i];
    }
}
__global__ void k_zero2() {
    int i = blockIdx.x * blockDim.x + threadIdx.x;
    if (i < SEG) { g_cnt[i] = 0; g_fill[i] = 0; }
}
__global__ void k_count() {
    int e = blockIdx.x * blockDim.x + threadIdx.x;
    if (e >= EE) return;
    atomicAdd(&g_cnt[g_et[e] * NN + g_col[e]], 1);
}
__global__ void k_invc() {
    int i = blockIdx.x * blockDim.x + threadIdx.x;
    if (i >= SEG) return;
    int c = g_cnt[i];
    g_invc[i] = 1.0f / (float)(c > 0 ? c : 1);
}

// ---------------- CSR build: hierarchical exclusive scan + scatter --------------
__global__ void k_bsum() {
    __shared__ int sh[256];
    int i = blockIdx.x * 256 + threadIdx.x;
    sh[threadIdx.x] = (i < SEG) ? g_cnt[i] : 0;
    __syncthreads();
    for (int o = 128; o > 0; o >>= 1) {
        if (threadIdx.x < o) sh[threadIdx.x] += sh[threadIdx.x + o];
        __syncthreads();
    }
    if (threadIdx.x == 0) g_bsum[blockIdx.x] = sh[0];
}
__global__ void k_bscan() {
    __shared__ int sh[1024];
    int tid = threadIdx.x;
    int v = (tid < SCANB) ? g_bsum[tid] : 0;
    sh[tid] = v;
    __syncthreads();
    for (int o = 1; o < 1024; o <<= 1) {
        int t = (tid >= o) ? sh[tid - o] : 0;
        __syncthreads();
        sh[tid] += t;
        __syncthreads();
    }
    if (tid < SCANB) g_bsum[tid] = sh[tid] - v;   // exclusive
}
__global__ void k_off() {
    __shared__ int sh[256];
    int tid = threadIdx.x;
    int i = blockIdx.x * 256 + tid;
    int v = (i < SEG) ? g_cnt[i] : 0;
    sh[tid] = v;
    __syncthreads();
    for (int o = 1; o < 256; o <<= 1) {
        int t = (tid >= o) ? sh[tid - o] : 0;
        __syncthreads();
        sh[tid] += t;
        __syncthreads();
    }
    if (i < SEG) g_off[i] = sh[tid] - v + g_bsum[blockIdx.x];
}
__global__ void k_scatter() {
    int e = blockIdx.x * blockDim.x + threadIdx.x;
    if (e >= EE) return;
    int idx = g_et[e] * NN + g_col[e];
    int pos = g_off[idx] + atomicAdd(&g_fill[idx], 1);
    g_srcl[pos] = g_row[e];
}

// ---------------- weight packing (tf32-rounded, K-major [N,Kp]) -----------------
__global__ void k_pack_big(const float* __restrict__ W, const float* __restrict__ root) {
    int i = blockIdx.x * 256 + threadIdx.x;
    if (i >= 256 * KP1) return;
    int n = i / KP1, k = i % KP1;
    float v = 0.f;
    if (k < FIN)
        v = (n < 192) ? W[(size_t)(n >> 6) * FIN * 64 + (size_t)k * 64 + (n & 63)]
                      : root[(size_t)k * 64 + (n - 192)];
    g_wt1[i] = tf32r(v);
}
__global__ void k_pack_small(const float* __restrict__ W, const float* __restrict__ root,
                             float* __restrict__ outw) {
    int i = blockIdx.x * 256 + threadIdx.x;
    if (i >= 256 * 64) return;
    int n = i >> 6, k = i & 63;
    float v = (n < 192) ? W[(n >> 6) * 4096 + k * 64 + (n & 63)]
                        : root[k * 64 + (n - 192)];
    outw[i] = tf32r(v);
}
__global__ void k_pack_eh(const float* __restrict__ ew1) {
    int i = blockIdx.x * 256 + threadIdx.x;
    if (i >= 128 * 64) return;
    int n = i >> 6, k = i & 63;
    float v = (n < 64) ? ew1[k * 64 + n] : ew1[(64 + k) * 64 + (n - 64)];
    g_wte[i] = tf32r(v);
}

// ---------------- tf32 mma.sync GEMM: [M,K] @ [N,Kp]^T, N = NT*64 ---------------
// SMEM (floats): A[2][128][36] at 0, B[2][NT*64][36] at 9216
template<int NT>
__device__ __forceinline__ void issue_chunk(const float* __restrict__ X,
                                            const float* __restrict__ Wt,
                                            int M, int K, int Kp, int m0, int c, uint32_t sb) {
    int tid = threadIdx.x;
    int k0 = c * 32;
    uint32_t ab = sb + (uint32_t)(c & 1) * 18432u;
    uint32_t bb = sb + 36864u + (uint32_t)(c & 1) * (uint32_t)(NT * 64 * 144);
    // A tile: 128 rows x 16 units of 8B (x rows are 8B-aligned for K=770)
#pragma unroll
    for (int i = 0; i < 4; i++) {
        int u = tid * 4 + i;                 // 2048 units
        int row = u >> 4, j = u & 15;
        int kk = k0 + j * 2;
        int ok = ((m0 + row) < M) && (kk < K);
        const float* src = ok ? (X + (size_t)(m0 + row) * K + kk) : X;
        int sz = ok ? ((K - kk >= 2) ? 8 : 4) : 0;
        cp8(ab + row * 144 + j * 8, src, sz);
    }
#pragma unroll
    for (int v = 0; v < NT; v++) {
        int u = v * 512 + tid;               // NT*64 rows x 8 units of 16B
        int row = u >> 3, j = u & 7;
        cp16(bb + row * 144 + j * 16, Wt + (size_t)row * Kp + k0 + j * 4, 16);
    }
    asm volatile("cp.async.commit_group;" ::: "memory");
}

template<int NT>
__global__ __launch_bounds__(512) void k_mma(
    const float* __restrict__ X, const float* __restrict__ Wt,
    int M, int K, int Kp,
    float* __restrict__ o0, float* __restrict__ o1,
    float* __restrict__ o2, float* __restrict__ o3,
    const float* __restrict__ bias3)
{
    extern __shared__ float smf[];
    uint32_t sb = smem_u32(smf);
    const int MT = NT / 2 ? NT / 2 : 1;
    int tid = threadIdx.x, wid = tid >> 5, lane = tid & 31;
    int g = lane >> 2, tig = lane & 3;
    int wn = wid % NT, wm = wid / NT;
    int rowbase = wm * MT * 16;
    int m0 = blockIdx.x * 128;
    int NC = (K + 31) / 32;

    float acc[MT][8][4];
#pragma unroll
    for (int mt = 0; mt < MT; mt++)
#pragma unroll
        for (int nt = 0; nt < 8; nt++)
#pragma unroll
            for (int q = 0; q < 4; q++) acc[mt][nt][q] = 0.f;

    issue_chunk<NT>(X, Wt, M, K, Kp, m0, 0, sb);

    for (int c = 0; c < NC; c++) {
        if (c + 1 < NC) {
            issue_chunk<NT>(X, Wt, M, K, Kp, m0, c + 1, sb);
            asm volatile("cp.async.wait_group 1;" ::: "memory");
        } else {
            asm volatile("cp.async.wait_group 0;" ::: "memory");
        }
        __syncthreads();

        int af = (c & 1) * 4608;
        int bf = 9216 + (c & 1) * (NT * 64 * 36);
#pragma unroll
        for (int k8 = 0; k8 < 4; k8++) {
            uint32_t A[MT][4];
#pragma unroll
            for (int mt = 0; mt < MT; mt++) {
                int r0 = rowbase + mt * 16 + g;
                int base = af + r0 * 36 + k8 * 8 + tig;
                A[mt][0] = cvt_tf32(smf[base]);
                A[mt][1] = cvt_tf32(smf[base + 8 * 36]);
                A[mt][2] = cvt_tf32(smf[base + 4]);
                A[mt][3] = cvt_tf32(smf[base + 8 * 36 + 4]);
            }
#pragma unroll
            for (int nt = 0; nt < 8; nt++) {
                int n = wn * 64 + nt * 8 + g;
                int base = bf + n * 36 + k8 * 8 + tig;
                uint32_t b0 = __float_as_uint(smf[base]);
                uint32_t b1 = __float_as_uint(smf[base + 4]);
#pragma unroll
                for (int mt = 0; mt < MT; mt++)
                    mma8(acc[mt][nt], A[mt], b0, b1);
            }
        }
        __syncthreads();
    }

    float* outs4[4] = {o0, o1, o2, o3};
    float* o = outs4[wn];
#pragma unroll
    for (int mt = 0; mt < MT; mt++) {
        int mA = m0 + rowbase + mt * 16 + g;
        int mB = mA + 8;
#pragma unroll
        for (int nt = 0; nt < 8; nt++) {
            int col = nt * 8 + tig * 2;
            float c0 = acc[mt][nt][0], c1 = acc[mt][nt][1];
            float c2 = acc[mt][nt][2], c3 = acc[mt][nt][3];
            if (bias3 && wn == NT - 1) {
                float bb0 = bias3[col], bb1 = bias3[col + 1];
                c0 += bb0; c1 += bb1; c2 += bb0; c3 += bb1;
            }
            if (mA < M) *(float2*)(o + (size_t)mA * 64 + col) = make_float2(c0, c1);
            if (mB < M) *(float2*)(o + (size_t)mB * 64 + col) = make_float2(c2, c3);
        }
    }
}

// ---------------- CSR aggregation: warp per dst, no atomics ---------------------
__global__ void k_agg(const float* __restrict__ xr, float* __restrict__ io, int do_relu) {
    int w = (blockIdx.x * blockDim.x + threadIdx.x) >> 5;
    int lane = threadIdx.x & 31;
    if (w >= NN) return;
    float a0 = 0.f, a1 = 0.f;
#pragma unroll
    for (int r = 0; r < RR; r++) {
        int idx = r * NN + w;
        int beg = g_off[idx], n = g_cnt[idx];
        const float* xrr = xr + (size_t)r * NN * 64;
        float s0 = 0.f, s1 = 0.f;
        for (int b = 0; b < n; b += 32) {
            int src = (b + lane < n) ? g_srcl[beg + b + lane] : 0;
            int m = min(32, n - b);
            int j = 0;
            for (; j + 4 <= m; j += 4) {
                int i0 = __shfl_sync(~0u, src, j);
                int i1 = __shfl_sync(~0u, src, j + 1);
                int i2 = __shfl_sync(~0u, src, j + 2);
                int i3 = __shfl_sync(~0u, src, j + 3);
                const float* p0 = xrr + (size_t)i0 * 64;
                const float* p1 = xrr + (size_t)i1 * 64;
                const float* p2 = xrr + (size_t)i2 * 64;
                const float* p3 = xrr + (size_t)i3 * 64;
                float v00 = p0[lane], v01 = p0[lane + 32];
                float v10 = p1[lane], v11 = p1[lane + 32];
                float v20 = p2[lane], v21 = p2[lane + 32];
                float v30 = p3[lane], v31 = p3[lane + 32];
                s0 += v00 + v10 + v20 + v30;
                s1 += v01 + v11 + v21 + v31;
            }
            for (; j < m; j++) {
                int i0 = __shfl_sync(~0u, src, j);
                const float* p0 = xrr + (size_t)i0 * 64;
                s0 += p0[lane];
                s1 += p0[lane + 32];
            }
        }
        float ic = g_invc[idx];
        a0 += s0 * ic;
        a1 += s1 * ic;
    }
    float v0 = io[(size_t)w * 64 + lane] + a0;
    float v1 = io[(size_t)w * 64 + lane + 32] + a1;
    if (do_relu) { v0 = fmaxf(v0, 0.f); v1 = fmaxf(v1, 0.f); }
    io[(size_t)w * 64 + lane]      = v0;
    io[(size_t)w * 64 + lane + 32] = v1;
}

// ---------------- layernorm (warp per node, H=64) ------------------------------
__global__ void k_ln(const float* __restrict__ in, float* __restrict__ outp,
                     const float* __restrict__ gg, const float* __restrict__ bb) {
    int w = (blockIdx.x * blockDim.x + threadIdx.x) >> 5;
    int lane = threadIdx.x & 31;
    if (w >= NN) return;
    float v0 = in[(size_t)w * 64 + lane];
    float v1 = in[(size_t)w * 64 + lane + 32];
    float s = v0 + v1;
#pragma unroll
    for (int off = 16; off; off >>= 1) s += __shfl_xor_sync(~0u, s, off);
    float mu = s * (1.f / 64.f);
    float d0 = v0 - mu, d1 = v1 - mu;
    float q = d0 * d0 + d1 * d1;
#pragma unroll
    for (int off = 16; off; off >>= 1) q += __shfl_xor_sync(~0u, q, off);
    float rs = rsqrtf(q * (1.f / 64.f) + 1e-5f);
    outp[(size_t)w * 64 + lane]      = d0 * rs * gg[lane] + bb[lane];
    outp[(size_t)w * 64 + lane + 32] = d1 * rs * gg[lane + 32] + bb[lane + 32];
}

// ---------------- edge classifier (16 lanes per edge) ---------------------------
__global__ void k_edge(const float4* __restrict__ ea4, const float4* __restrict__ eb4,
                       const float* __restrict__ eb1, const float* __restrict__ ew2,
                       const float* __restrict__ eb2, float* __restrict__ outp) {
    __shared__ float s_b1[64], s_w2[192], s_b2[3];
    int tid = threadIdx.x;
    if (tid < 64)  s_b1[tid] = eb1[tid];
    if (tid < 192) s_w2[tid] = ew2[tid];
    if (tid < 3)   s_b2[tid] = eb2[tid];
    __syncthreads();

    int gid = blockIdx.x * blockDim.x + tid;
    int e = gid >> 4, sub = tid & 15;
    if (e >= EE) return;
    int r = g_row[e], c = g_col[e];
    float4 va = ea4[(size_t)r * 16 + sub];
    float4 vb = eb4[(size_t)c * 16 + sub];
    float h[4];
    h[0] = fmaxf(va.x + vb.x + s_b1[sub * 4 + 0], 0.f);
    h[1] = fmaxf(va.y + vb.y + s_b1[sub * 4 + 1], 0.f);
    h[2] = fmaxf(va.z + vb.z + s_b1[sub * 4 + 2], 0.f);
    h[3] = fmaxf(va.w + vb.w + s_b1[sub * 4 + 3], 0.f);
    float p0 = 0.f, p1 = 0.f, p2 = 0.f;
#pragma unroll
    for (int i = 0; i < 4; i++) {
        int f = sub * 4 + i;
        p0 += h[i] * s_w2[f * 3 + 0];
        p1 += h[i] * s_w2[f * 3 + 1];
        p2 += h[i] * s_w2[f * 3 + 2];
    }
#pragma unroll
    for (int off = 8; off; off >>= 1) {
        p0 += __shfl_xor_sync(~0u, p0, off);
        p1 += __shfl_xor_sync(~0u, p1, off);
        p2 += __shfl_xor_sync(~0u, p2, off);
    }
    if (sub == 0) {
        float l0 = p0 + s_b2[0], l1 = p1 + s_b2[1], l2 = p2 + s_b2[2];
        float mx = fmaxf(l0, fmaxf(l1, l2));
        float lse = __logf(__expf(l0 - mx) + __expf(l1 - mx) + __expf(l2 - mx)) + mx;
        outp[(size_t)e * 3 + 0] = l0 - lse;
        outp[(size_t)e * 3 + 1] = l1 - lse;
        outp[(size_t)e * 3 + 2] = l2 - lse;
    }
}

// ---------------- node classifier (warp per node) ------------------------------
__global__ void k_node(const float* __restrict__ x3, const float* __restrict__ nw1,
                       const float* __restrict__ nb1, const float* __restrict__ nw2,
                       const float* __restrict__ nb2, float* __restrict__ outp) {
    __shared__ float s_w1[64 * 32];
    __shared__ float s_b1[32], s_w2[64], s_b2[2];
    int tid = threadIdx.x;
    for (int i = tid; i < 2048; i += blockDim.x) s_w1[i] = nw1[i];
    if (tid < 32) s_b1[tid] = nb1[tid];
    if (tid < 64) s_w2[tid] = nw2[tid];
    if (tid < 2)  s_b2[tid] = nb2[tid];
    __syncthreads();

    int nidx = (blockIdx.x * blockDim.x + tid) >> 5;
    int lane = tid & 31;
    if (nidx >= NN) return;
    float xa = x3[(size_t)nidx * 64 + lane];
    float xb = x3[(size_t)nidx * 64 + lane + 32];
    float acc = s_b1[lane];
#pragma unroll
    for (int k = 0; k < 32; k++) {
        float xv = __shfl_sync(~0u, xa, k);
        acc += xv * s_w1[k * 32 + lane];
    }
#pragma unroll
    for (int k = 0; k < 32; k++) {
        float xv = __shfl_sync(~0u, xb, k);
        acc += xv * s_w1[(k + 32) * 32 + lane];
    }
    float nh = fmaxf(acc, 0.f);
    float p0 = nh * s_w2[lane * 2 + 0];
    float p1 = nh * s_w2[lane * 2 + 1];
#pragma unroll
    for (int off = 16; off; off >>= 1) {
        p0 += __shfl_xor_sync(~0u, p0, off);
        p1 += __shfl_xor_sync(~0u, p1, off);
    }
    if (lane == 0) {
        float l0 = p0 + s_b2[0], l1 = p1 + s_b2[1];
        float mx = fmaxf(l0, l1);
        float lse = __logf(__expf(l0 - mx) + __expf(l1 - mx)) + mx;
        outp[(size_t)3 * EE + (size_t)nidx * 2 + 0] = l0 - lse;
        outp[(size_t)3 * EE + (size_t)nidx * 2 + 1] = l1 - lse;
    }
}

// ---------------- host orchestration -------------------------------------------
extern "C" void kernel_launch(void* const* d_in, const int* in_sizes, int n_in,
                              void* d_out, int out_size) {
    const float* x     = (const float*)d_in[0];
    const void*  eidx  = d_in[1];
    const void*  etyp  = d_in[2];
    const float* W1    = (const float*)d_in[3];
    const float* root1 = (const float*)d_in[4];
    const float* b1    = (const float*)d_in[5];
    const float* W2    = (const float*)d_in[6];
    const float* root2 = (const float*)d_in[7];
    const float* b2    = (const float*)d_in[8];
    const float* W3    = (const float*)d_in[9];
    const float* root3 = (const float*)d_in[10];
    const float* b3    = (const float*)d_in[11];
    const float* ln_g  = (const float*)d_in[12];
    const float* ln_b  = (const float*)d_in[13];
    const float* ew1   = (const float*)d_in[14];
    const float* eb1   = (const float*)d_in[15];
    const float* ew2   = (const float*)d_in[16];
    const float* eb2   = (const float*)d_in[17];
    const float* nw1   = (const float*)d_in[18];
    const float* nb1   = (const float*)d_in[19];
    const float* nw2   = (const float*)d_in[20];
    const float* nb2   = (const float*)d_in[21];
    float* out = (float*)d_out;

    float *p_xr, *p_bufa, *p_bufb, *p_ea, *p_eb, *p_wt1, *p_wt2, *p_wt3, *p_wte;
    cudaGetSymbolAddress((void**)&p_xr,   g_xr);
    cudaGetSymbolAddress((void**)&p_bufa, g_bufa);
    cudaGetSymbolAddress((void**)&p_bufb, g_bufb);
    cudaGetSymbolAddress((void**)&p_ea,   g_ea);
    cudaGetSymbolAddress((void**)&p_eb,   g_eb);
    cudaGetSymbolAddress((void**)&p_wt1,  g_wt1);
    cudaGetSymbolAddress((void**)&p_wt2,  g_wt2);
    cudaGetSymbolAddress((void**)&p_wt3,  g_wt3);
    cudaGetSymbolAddress((void**)&p_wte,  g_wte);

    const int SMEM4 = (9216 + 2 * 256 * 36) * 4;   // 110592 B
    const int SMEM2 = (9216 + 2 * 128 * 36) * 4;   //  73728 B
    cudaFuncSetAttribute(k_mma<4>, cudaFuncAttributeMaxDynamicSharedMemorySize, SMEM4);
    cudaFuncSetAttribute(k_mma<2>, cudaFuncAttributeMaxDynamicSharedMemorySize, SMEM2);

    // edge structure prep + CSR build
    k_detect<<<1, 32>>>((const unsigned int*)eidx);
    k_convert<<<(EE + 255) / 256, 256>>>(eidx, etyp);
    k_zero2<<<(SEG + 255) / 256, 256>>>();
    k_count<<<(EE + 255) / 256, 256>>>();
    k_invc<<<(SEG + 255) / 256, 256>>>();
    k_bsum<<<SCANB, 256>>>();
    k_bscan<<<1, 1024>>>();
    k_off<<<SCANB, 256>>>();
    k_scatter<<<(EE + 255) / 256, 256>>>();

    int tiles = (NN + 127) / 128;            // 391
    int warpNBlocks = (NN * 32 + 255) / 256;
    size_t NH = (size_t)NN * 64;

    // ---- layer 1 ----
    k_pack_big<<<(256 * KP1 + 255) / 256, 256>>>(W1, root1);
    k_mma<4><<<tiles, 512, SMEM4>>>(x, p_wt1, NN, FIN, KP1,
                                    p_xr, p_xr + NH, p_xr + 2 * NH, p_bufa, b1);
    k_agg<<<warpNBlocks, 256>>>(p_xr, p_bufa, 1);

    // ---- layer 2 ----
    k_pack_small<<<(256 * 64 + 255) / 256, 256>>>(W2, root2, p_wt2);
    k_mma<4><<<tiles, 512, SMEM4>>>(p_bufa, p_wt2, NN, 64, 64,
                                    p_xr, p_xr + NH, p_xr + 2 * NH, p_bufb, b2);
    k_agg<<<warpNBlocks, 256>>>(p_xr, p_bufb, 1);

    // ---- layer 3 ----
    k_pack_small<<<(256 * 64 + 255) / 256, 256>>>(W3, root3, p_wt3);
    k_mma<4><<<tiles, 512, SMEM4>>>(p_bufb, p_wt3, NN, 64, 64,
                                    p_xr, p_xr + NH, p_xr + 2 * NH, p_bufa, b3);
    k_agg<<<warpNBlocks, 256>>>(p_xr, p_bufa, 0);
    k_ln<<<warpNBlocks, 256>>>(p_bufa, p_bufb, ln_g, ln_b);    // x3 -> p_bufb

    // ---- edge head precompute ----
    k_pack_eh<<<(128 * 64 + 255) / 256, 256>>>(ew1);
    k_mma<2><<<tiles, 512, SMEM2>>>(p_bufb, p_wte, NN, 64, 64,
                                    p_ea, p_eb, nullptr, nullptr, nullptr);

    // ---- heads ----
    k_edge<<<(EE * 16 + 255) / 256, 256>>>((const float4*)p_ea, (const float4*)p_eb,
                                           eb1, ew2, eb2, out);
    k_node<<<warpNBlocks, 256>>>(p_bufb, nw1, nb1, nw2, nb2, out);
}

// round 5
// speedup vs baseline: 2.9882x; 1.0022x over previous
#include <cuda_runtime.h>
#include <math.h>
#include <stdint.h>

#define NN 50000
#define EE 1600000
#define FIN 770
#define RR 3
#define KP1 800
#define SEG (RR * NN)               // 150000
#define SCANB ((SEG + 255) / 256)   // 586

// ---------------- scratch ------------------------------------------------------
__device__ float g_xr[(size_t)RR * NN * 64];
__device__ float g_bufa[(size_t)NN * 64];
__device__ float g_bufb[(size_t)NN * 64];
__device__ float g_ea[(size_t)NN * 64];
__device__ float g_eb[(size_t)NN * 64];
__device__ float g_invc[SEG];
__device__ int   g_cnt[SEG];
__device__ int   g_off[SEG];
__device__ int   g_fill[SEG];
__device__ int   g_bsum[1024];
__device__ int   g_srcl[EE];
__device__ int   g_dstl[EE];
__device__ int   g_eidl[EE];
__device__ int   g_row[EE];
__device__ int   g_col[EE];
__device__ int   g_et[EE];
__device__ int   g_is64;
__device__ float g_wt1[256 * KP1];
__device__ float g_wt2[256 * 64];
__device__ float g_wt3[256 * 64];
__device__ float g_wte[128 * 64];

// ---------------- helpers ------------------------------------------------------
__device__ __forceinline__ uint32_t smem_u32(const void* p) {
    uint32_t a;
    asm("{ .reg .u64 t; cvta.to.shared.u64 t, %1; cvt.u32.u64 %0, t; }" : "=r"(a) : "l"(p));
    return a;
}
__device__ __forceinline__ void cp16(uint32_t dst, const void* src, int sz) {
    asm volatile("cp.async.cg.shared.global [%0], [%1], 16, %2;"
                 :: "r"(dst), "l"(src), "r"(sz) : "memory");
}
__device__ __forceinline__ void cp8(uint32_t dst, const void* src, int sz) {
    asm volatile("cp.async.ca.shared.global [%0], [%1], 8, %2;"
                 :: "r"(dst), "l"(src), "r"(sz) : "memory");
}
__device__ __forceinline__ uint32_t cvt_tf32(float f) {
    uint32_t r;
    asm("cvt.rna.tf32.f32 %0, %1;" : "=r"(r) : "f"(f));
    return r;
}
__device__ __forceinline__ float tf32r(float x) { return __uint_as_float(cvt_tf32(x)); }
__device__ __forceinline__ void mma8(float* c, const uint32_t* a, uint32_t b0, uint32_t b1) {
    asm volatile(
        "mma.sync.aligned.m16n8k8.row.col.f32.tf32.tf32.f32 "
        "{%0,%1,%2,%3}, {%4,%5,%6,%7}, {%8,%9}, {%0,%1,%2,%3};"
        : "+f"(c[0]), "+f"(c[1]), "+f"(c[2]), "+f"(c[3])
        : "r"(a[0]), "r"(a[1]), "r"(a[2]), "r"(a[3]), "r"(b0), "r"(b1));
}

// ---------------- edge prep -----------------------------------------------------
__global__ void k_detect(const unsigned int* __restrict__ ei) {
    if (threadIdx.x == 0 && blockIdx.x == 0) {
        int is64 = 1;
        for (int i = 0; i < 64; i++)
            if (ei[2 * i + 1] != 0u) { is64 = 0; break; }
        g_is64 = is64;
    }
}
__global__ void k_zero2() {
    int i = blockIdx.x * blockDim.x + threadIdx.x;
    if (i < SEG) { g_cnt[i] = 0; g_fill[i] = 0; }
}
// convert + degree count fused
__global__ void k_convert(const void* __restrict__ ei, const void* __restrict__ et) {
    int i = blockIdx.x * blockDim.x + threadIdx.x;
    if (i >= EE) return;
    int r, c, t;
    if (g_is64) {
        const long long* p = (const long long*)ei;
        r = (int)p[i];
        c = (int)p[EE + i];
        t = (int)((const long long*)et)[i];
    } else {
        const int* p = (const int*)ei;
        r = p[i];
        c = p[EE + i];
        t = ((const int*)et)[i];
    }
    g_row[i] = r; g_col[i] = c; g_et[i] = t;
    atomicAdd(&g_cnt[t * NN + c], 1);
}

// ---------------- CSR build: hierarchical exclusive scan + scatter --------------
__global__ void k_bsum() {
    __shared__ int sh[256];
    int i = blockIdx.x * 256 + threadIdx.x;
    sh[threadIdx.x] = (i < SEG) ? g_cnt[i] : 0;
    __syncthreads();
    for (int o = 128; o > 0; o >>= 1) {
        if (threadIdx.x < o) sh[threadIdx.x] += sh[threadIdx.x + o];
        __syncthreads();
    }
    if (threadIdx.x == 0) g_bsum[blockIdx.x] = sh[0];
}
__global__ void k_bscan() {
    __shared__ int sh[1024];
    int tid = threadIdx.x;
    int v = (tid < SCANB) ? g_bsum[tid] : 0;
    sh[tid] = v;
    __syncthreads();
    for (int o = 1; o < 1024; o <<= 1) {
        int t = (tid >= o) ? sh[tid - o] : 0;
        __syncthreads();
        sh[tid] += t;
        __syncthreads();
    }
    if (tid < SCANB) g_bsum[tid] = sh[tid] - v;   // exclusive
}
__global__ void k_off() {
    __shared__ int sh[256];
    int tid = threadIdx.x;
    int i = blockIdx.x * 256 + tid;
    int v = (i < SEG) ? g_cnt[i] : 0;
    sh[tid] = v;
    __syncthreads();
    for (int o = 1; o < 256; o <<= 1) {
        int t = (tid >= o) ? sh[tid - o] : 0;
        __syncthreads();
        sh[tid] += t;
        __syncthreads();
    }
    if (i < SEG) {
        g_off[i] = sh[tid] - v + g_bsum[blockIdx.x];
        g_invc[i] = 1.0f / (float)(v > 0 ? v : 1);
    }
}
__global__ void k_scatter() {
    int e = blockIdx.x * blockDim.x + threadIdx.x;
    if (e >= EE) return;
    int c = g_col[e];
    int idx = g_et[e] * NN + c;
    int pos = g_off[idx] + atomicAdd(&g_fill[idx], 1);
    g_srcl[pos] = g_row[e];
    g_dstl[pos] = c;
    g_eidl[pos] = e;
}

// ---------------- weight packing (tf32-rounded, K-major, k8-permuted) -----------
// within each 8-k group, slot s holds k = (s>>1) + (s&1)*4  (so frag (tig,tig+4)
// becomes adjacent pair at slots 2*tig, 2*tig+1 -> float2 LDS)
__device__ __forceinline__ int slot2k(int grp, int s) {
    return grp * 8 + (s >> 1) + ((s & 1) << 2);
}
__global__ void k_pack_big(const float* __restrict__ W, const float* __restrict__ root) {
    int i = blockIdx.x * 256 + threadIdx.x;
    if (i >= 256 * KP1) return;
    int n = i / KP1, s = i % KP1;
    int k = slot2k(s >> 3, s & 7);
    float v = 0.f;
    if (k < FIN)
        v = (n < 192) ? W[(size_t)(n >> 6) * FIN * 64 + (size_t)k * 64 + (n & 63)]
                      : root[(size_t)k * 64 + (n - 192)];
    g_wt1[i] = tf32r(v);
}
__global__ void k_pack_small(const float* __restrict__ W, const float* __restrict__ root,
                             float* __restrict__ outw) {
    int i = blockIdx.x * 256 + threadIdx.x;
    if (i >= 256 * 64) return;
    int n = i >> 6, s = i & 63;
    int k = slot2k(s >> 3, s & 7);
    float v = (n < 192) ? W[(n >> 6) * 4096 + k * 64 + (n & 63)]
                        : root[k * 64 + (n - 192)];
    outw[i] = tf32r(v);
}
__global__ void k_pack_eh(const float* __restrict__ ew1) {
    int i = blockIdx.x * 256 + threadIdx.x;
    if (i >= 128 * 64) return;
    int n = i >> 6, s = i & 63;
    int k = slot2k(s >> 3, s & 7);
    float v = (n < 64) ? ew1[k * 64 + n] : ew1[(64 + k) * 64 + (n - 64)];
    g_wte[i] = tf32r(v);
}

// ---------------- tf32 mma.sync GEMM: [M,K] @ [N,Kp]^T, N = NT*64 ---------------
// 256 threads, 8 warps: wn = wid%NT, wm = wid/NT, MT = NT rows-of-16 per warp.
// SMEM: A[2][128][36]f at 0 (byte 0, per-buf 18432), B[2][NT*64][40]f at byte 36864.
template<int NT>
__device__ __forceinline__ void issue_chunk(const float* __restrict__ X,
                                            const float* __restrict__ Wt,
                                            int M, int K, int Kp, int m0, int c, uint32_t sb) {
    int tid = threadIdx.x;
    int k0 = c * 32;
    uint32_t ab = sb + (uint32_t)(c & 1) * 18432u;
    uint32_t bb = sb + 36864u + (uint32_t)(c & 1) * (uint32_t)(NT * 10240);
#pragma unroll
    for (int i = 0; i < 8; i++) {
        int u = i * 256 + tid;               // 2048 units: 128 rows x 16 of 8B
        int row = u >> 4, j = u & 15;
        int kk = k0 + j * 2;
        int ok = ((m0 + row) < M) && (kk < K);
        const float* src = ok ? (X + (size_t)(m0 + row) * K + kk) : X;
        int sz = ok ? ((K - kk >= 2) ? 8 : 4) : 0;
        cp8(ab + row * 144 + j * 8, src, sz);
    }
#pragma unroll
    for (int i = 0; i < 2 * NT; i++) {
        int u = i * 256 + tid;               // NT*64 rows x 8 units of 16B
        int row = u >> 3, j = u & 7;
        cp16(bb + row * 160 + j * 16, Wt + (size_t)row * Kp + k0 + j * 4, 16);
    }
    asm volatile("cp.async.commit_group;" ::: "memory");
}

template<int NT>
__global__ __launch_bounds__(256, 1) void k_mma(
    const float* __restrict__ X, const float* __restrict__ Wt,
    int M, int K, int Kp,
    float* __restrict__ o0, float* __restrict__ o1,
    float* __restrict__ o2, float* __restrict__ o3,
    const float* __restrict__ bias3)
{
    extern __shared__ float smf[];
    uint32_t sb = smem_u32(smf);
    const int MT = NT;
    int tid = threadIdx.x, wid = tid >> 5, lane = tid & 31;
    int g = lane >> 2, tig = lane & 3;
    int wn = wid % NT, wm = wid / NT;
    int rowbase = wm * MT * 16;
    int m0 = blockIdx.x * 128;
    int NC = (K + 31) / 32;

    float acc[MT][8][4];
#pragma unroll
    for (int mt = 0; mt < MT; mt++)
#pragma unroll
        for (int nt = 0; nt < 8; nt++)
#pragma unroll
            for (int q = 0; q < 4; q++) acc[mt][nt][q] = 0.f;

    issue_chunk<NT>(X, Wt, M, K, Kp, m0, 0, sb);

    for (int c = 0; c < NC; c++) {
        if (c + 1 < NC) {
            issue_chunk<NT>(X, Wt, M, K, Kp, m0, c + 1, sb);
            asm volatile("cp.async.wait_group 1;" ::: "memory");
        } else {
            asm volatile("cp.async.wait_group 0;" ::: "memory");
        }
        __syncthreads();

        int af = (c & 1) * 4608;                     // float offsets
        int bf = 9216 + (c & 1) * (NT * 2560);
#pragma unroll
        for (int k8 = 0; k8 < 4; k8++) {
            uint32_t A[MT][4];
#pragma unroll
            for (int mt = 0; mt < MT; mt++) {
                int base = af + (rowbase + mt * 16 + g) * 36 + k8 * 8 + tig;
                A[mt][0] = cvt_tf32(smf[base]);
                A[mt][1] = cvt_tf32(smf[base + 8 * 36]);
                A[mt][2] = cvt_tf32(smf[base + 4]);
                A[mt][3] = cvt_tf32(smf[base + 8 * 36 + 4]);
            }
#pragma unroll
            for (int nt = 0; nt < 8; nt++) {
                int nb = bf + (wn * 64 + nt * 8 + g) * 40 + k8 * 8 + tig * 2;
                float2 bv = *(const float2*)&smf[nb];     // permuted pack: (k, k+4)
                uint32_t b0 = __float_as_uint(bv.x);
                uint32_t b1 = __float_as_uint(bv.y);
#pragma unroll
                for (int mt = 0; mt < MT; mt++)
                    mma8(acc[mt][nt], A[mt], b0, b1);
            }
        }
        __syncthreads();
    }

    float* outs4[4] = {o0, o1, o2, o3};
    float* o = outs4[wn];
#pragma unroll
    for (int mt = 0; mt < MT; mt++) {
        int mA = m0 + rowbase + mt * 16 + g;
        int mB = mA + 8;
#pragma unroll
        for (int nt = 0; nt < 8; nt++) {
            int col = nt * 8 + tig * 2;
            float c0 = acc[mt][nt][0], c1 = acc[mt][nt][1];
            float c2 = acc[mt][nt][2], c3 = acc[mt][nt][3];
            if (bias3 && wn == NT - 1) {
                float bb0 = bias3[col], bb1 = bias3[col + 1];
                c0 += bb0; c1 += bb1; c2 += bb0; c3 += bb1;
            }
            if (mA < M) *(float2*)(o + (size_t)mA * 64 + col) = make_float2(c0, c1);
            if (mB < M) *(float2*)(o + (size_t)mB * 64 + col) = make_float2(c2, c3);
        }
    }
}

// ---------------- CSR aggregation: warp per dst, 8-wide batches -----------------
__global__ void k_agg(const float* __restrict__ xr, float* __restrict__ io, int do_relu) {
    int w = (blockIdx.x * blockDim.x + threadIdx.x) >> 5;
    int lane = threadIdx.x & 31;
    if (w >= NN) return;
    float a0 = 0.f, a1 = 0.f;
#pragma unroll
    for (int r = 0; r < RR; r++) {
        int idx = r * NN + w;
        int beg = g_off[idx], n = g_cnt[idx];
        const float* xrr = xr + (size_t)r * NN * 64;
        float s0 = 0.f, s1 = 0.f;
        for (int b = 0; b < n; b += 32) {
            int src = (b + lane < n) ? g_srcl[beg + b + lane] : 0;
            int m = min(32, n - b);
            int j = 0;
            for (; j + 8 <= m; j += 8) {
                const float* p[8];
#pragma unroll
                for (int q = 0; q < 8; q++)
                    p[q] = xrr + (size_t)__shfl_sync(~0u, src, j + q) * 64;
                float t0 = 0.f, t1 = 0.f;
#pragma unroll
                for (int q = 0; q < 8; q++) {
                    t0 += p[q][lane];
                    t1 += p[q][lane + 32];
                }
                s0 += t0; s1 += t1;
            }
            for (; j + 4 <= m; j += 4) {
                const float* p[4];
#pragma unroll
                for (int q = 0; q < 4; q++)
                    p[q] = xrr + (size_t)__shfl_sync(~0u, src, j + q) * 64;
#pragma unroll
                for (int q = 0; q < 4; q++) {
                    s0 += p[q][lane];
                    s1 += p[q][lane + 32];
                }
            }
            for (; j < m; j++) {
                const float* p0 = xrr + (size_t)__shfl_sync(~0u, src, j) * 64;
                s0 += p0[lane];
                s1 += p0[lane + 32];
            }
        }
        float ic = g_invc[idx];
        a0 += s0 * ic;
        a1 += s1 * ic;
    }
    float v0 = io[(size_t)w * 64 + lane] + a0;
    float v1 = io[(size_t)w * 64 + lane + 32] + a1;
    if (do_relu) { v0 = fmaxf(v0, 0.f); v1 = fmaxf(v1, 0.f); }
    io[(size_t)w * 64 + lane]      = v0;
    io[(size_t)w * 64 + lane + 32] = v1;
}

// ---------------- fused layernorm + node classifier (warp per node) -------------
__global__ void k_ln_node(const float* __restrict__ in, float* __restrict__ x3out,
                          const float* __restrict__ gg, const float* __restrict__ bb,
                          const float* __restrict__ nw1, const float* __restrict__ nb1,
                          const float* __restrict__ nw2, const float* __restrict__ nb2,
                          float* __restrict__ outp) {
    __shared__ float s_w1[64 * 32];
    __shared__ float s_b1[32], s_w2[64], s_b2[2], s_g[64], s_bb[64];
    int tid = threadIdx.x;
    for (int i = tid; i < 2048; i += blockDim.x) s_w1[i] = nw1[i];
    if (tid < 32) s_b1[tid] = nb1[tid];
    if (tid < 64) { s_w2[tid] = nw2[tid]; s_g[tid] = gg[tid]; s_bb[tid] = bb[tid]; }
    if (tid < 2)  s_b2[tid] = nb2[tid];
    __syncthreads();

    int w = (blockIdx.x * blockDim.x + tid) >> 5;
    int lane = tid & 31;
    if (w >= NN) return;
    float v0 = in[(size_t)w * 64 + lane];
    float v1 = in[(size_t)w * 64 + lane + 32];
    float s = v0 + v1;
#pragma unroll
    for (int off = 16; off; off >>= 1) s += __shfl_xor_sync(~0u, s, off);
    float mu = s * (1.f / 64.f);
    float d0 = v0 - mu, d1 = v1 - mu;
    float q = d0 * d0 + d1 * d1;
#pragma unroll
    for (int off = 16; off; off >>= 1) q += __shfl_xor_sync(~0u, q, off);
    float rs = rsqrtf(q * (1.f / 64.f) + 1e-5f);
    float xa = d0 * rs * s_g[lane] + s_bb[lane];
    float xb = d1 * rs * s_g[lane + 32] + s_bb[lane + 32];
    x3out[(size_t)w * 64 + lane]      = xa;
    x3out[(size_t)w * 64 + lane + 32] = xb;

    // node head: nh = relu(x3 @ nw1 + nb1); out = log_softmax(nh @ nw2 + nb2)
    float acc = s_b1[lane];
#pragma unroll
    for (int k = 0; k < 32; k++) {
        float xv = __shfl_sync(~0u, xa, k);
        acc += xv * s_w1[k * 32 + lane];
    }
#pragma unroll
    for (int k = 0; k < 32; k++) {
        float xv = __shfl_sync(~0u, xb, k);
        acc += xv * s_w1[(k + 32) * 32 + lane];
    }
    float nh = fmaxf(acc, 0.f);
    float p0 = nh * s_w2[lane * 2 + 0];
    float p1 = nh * s_w2[lane * 2 + 1];
#pragma unroll
    for (int off = 16; off; off >>= 1) {
        p0 += __shfl_xor_sync(~0u, p0, off);
        p1 += __shfl_xor_sync(~0u, p1, off);
    }
    if (lane == 0) {
        float l0 = p0 + s_b2[0], l1 = p1 + s_b2[1];
        float mx = fmaxf(l0, l1);
        float lse = __logf(__expf(l0 - mx) + __expf(l1 - mx)) + mx;
        outp[(size_t)3 * EE + (size_t)w * 2 + 0] = l0 - lse;
        outp[(size_t)3 * EE + (size_t)w * 2 + 1] = l1 - lse;
    }
}

// ---------------- edge classifier, CSR order (16 lanes per entry) ---------------
__global__ void k_edge(const float4* __restrict__ ea4, const float4* __restrict__ eb4,
                       const float* __restrict__ eb1, const float* __restrict__ ew2,
                       const float* __restrict__ eb2, float* __restrict__ outp) {
    __shared__ float s_b1[64], s_w2[192], s_b2[3];
    int tid = threadIdx.x;
    if (tid < 64)  s_b1[tid] = eb1[tid];
    if (tid < 192) s_w2[tid] = ew2[tid];
    if (tid < 3)   s_b2[tid] = eb2[tid];
    __syncthreads();

    int gid = blockIdx.x * blockDim.x + tid;
    int p = gid >> 4, sub = tid & 15;
    if (p >= EE) return;
    int r  = g_srcl[p];          // src (random gather)
    int c  = g_dstl[p];          // dst (high locality in CSR order)
    int id = g_eidl[p];
    float4 va = ea4[(size_t)r * 16 + sub];
    float4 vb = eb4[(size_t)c * 16 + sub];
    float h[4];
    h[0] = fmaxf(va.x + vb.x + s_b1[sub * 4 + 0], 0.f);
    h[1] = fmaxf(va.y + vb.y + s_b1[sub * 4 + 1], 0.f);
    h[2] = fmaxf(va.z + vb.z + s_b1[sub * 4 + 2], 0.f);
    h[3] = fmaxf(va.w + vb.w + s_b1[sub * 4 + 3], 0.f);
    float p0 = 0.f, p1 = 0.f, p2 = 0.f;
#pragma unroll
    for (int i = 0; i < 4; i++) {
        int f = sub * 4 + i;
        p0 += h[i] * s_w2[f * 3 + 0];
        p1 += h[i] * s_w2[f * 3 + 1];
        p2 += h[i] * s_w2[f * 3 + 2];
    }
#pragma unroll
    for (int off = 8; off; off >>= 1) {
        p0 += __shfl_xor_sync(~0u, p0, off);
        p1 += __shfl_xor_sync(~0u, p1, off);
        p2 += __shfl_xor_sync(~0u, p2, off);
    }
    if (sub == 0) {
        float l0 = p0 + s_b2[0], l1 = p1 + s_b2[1], l2 = p2 + s_b2[2];
        float mx = fmaxf(l0, fmaxf(l1, l2));
        float lse = __logf(__expf(l0 - mx) + __expf(l1 - mx) + __expf(l2 - mx)) + mx;
        outp[(size_t)id * 3 + 0] = l0 - lse;
        outp[(size_t)id * 3 + 1] = l1 - lse;
        outp[(size_t)id * 3 + 2] = l2 - lse;
    }
}

// ---------------- host orchestration -------------------------------------------
extern "C" void kernel_launch(void* const* d_in, const int* in_sizes, int n_in,
                              void* d_out, int out_size) {
    const float* x     = (const float*)d_in[0];
    const void*  eidx  = d_in[1];
    const void*  etyp  = d_in[2];
    const float* W1    = (const float*)d_in[3];
    const float* root1 = (const float*)d_in[4];
    const float* b1    = (const float*)d_in[5];
    const float* W2    = (const float*)d_in[6];
    const float* root2 = (const float*)d_in[7];
    const float* b2    = (const float*)d_in[8];
    const float* W3    = (const float*)d_in[9];
    const float* root3 = (const float*)d_in[10];
    const float* b3    = (const float*)d_in[11];
    const float* ln_g  = (const float*)d_in[12];
    const float* ln_b  = (const float*)d_in[13];
    const float* ew1   = (const float*)d_in[14];
    const float* eb1   = (const float*)d_in[15];
    const float* ew2   = (const float*)d_in[16];
    const float* eb2   = (const float*)d_in[17];
    const float* nw1   = (const float*)d_in[18];
    const float* nb1   = (const float*)d_in[19];
    const float* nw2   = (const float*)d_in[20];
    const float* nb2   = (const float*)d_in[21];
    float* out = (float*)d_out;

    float *p_xr, *p_bufa, *p_bufb, *p_ea, *p_eb, *p_wt1, *p_wt2, *p_wt3, *p_wte;
    cudaGetSymbolAddress((void**)&p_xr,   g_xr);
    cudaGetSymbolAddress((void**)&p_bufa, g_bufa);
    cudaGetSymbolAddress((void**)&p_bufb, g_bufb);
    cudaGetSymbolAddress((void**)&p_ea,   g_ea);
    cudaGetSymbolAddress((void**)&p_eb,   g_eb);
    cudaGetSymbolAddress((void**)&p_wt1,  g_wt1);
    cudaGetSymbolAddress((void**)&p_wt2,  g_wt2);
    cudaGetSymbolAddress((void**)&p_wt3,  g_wt3);
    cudaGetSymbolAddress((void**)&p_wte,  g_wte);

    const int SMEM4 = 36864 + 2 * 4 * 10240;   // 118784 B
    const int SMEM2 = 36864 + 2 * 2 * 10240;   //  77824 B
    cudaFuncSetAttribute(k_mma<4>, cudaFuncAttributeMaxDynamicSharedMemorySize, SMEM4);
    cudaFuncSetAttribute(k_mma<2>, cudaFuncAttributeMaxDynamicSharedMemorySize, SMEM2);

    // edge structure prep + CSR build
    k_detect<<<1, 32>>>((const unsigned int*)eidx);
    k_zero2<<<(SEG + 255) / 256, 256>>>();
    k_convert<<<(EE + 255) / 256, 256>>>(eidx, etyp);
    k_bsum<<<SCANB, 256>>>();
    k_bscan<<<1, 1024>>>();
    k_off<<<SCANB, 256>>>();
    k_scatter<<<(EE + 255) / 256, 256>>>();

    int tiles = (NN + 127) / 128;            // 391
    int warpNBlocks = (NN * 32 + 255) / 256;
    size_t NH = (size_t)NN * 64;

    // ---- layer 1 ----
    k_pack_big<<<(256 * KP1 + 255) / 256, 256>>>(W1, root1);
    k_mma<4><<<tiles, 256, SMEM4>>>(x, p_wt1, NN, FIN, KP1,
                                    p_xr, p_xr + NH, p_xr + 2 * NH, p_bufa, b1);
    k_agg<<<warpNBlocks, 256>>>(p_xr, p_bufa, 1);

    // ---- layer 2 ----
    k_pack_small<<<(256 * 64 + 255) / 256, 256>>>(W2, root2, p_wt2);
    k_mma<4><<<tiles, 256, SMEM4>>>(p_bufa, p_wt2, NN, 64, 64,
                                    p_xr, p_xr + NH, p_xr + 2 * NH, p_bufb, b2);
    k_agg<<<warpNBlocks, 256>>>(p_xr, p_bufb, 1);

    // ---- layer 3 ----
    k_pack_small<<<(256 * 64 + 255) / 256, 256>>>(W3, root3, p_wt3);
    k_mma<4><<<tiles, 256, SMEM4>>>(p_bufb, p_wt3, NN, 64, 64,
                                    p_xr, p_xr + NH, p_xr + 2 * NH, p_bufa, b3);
    k_agg<<<warpNBlocks, 256>>>(p_xr, p_bufa, 0);

    // ---- LN + node head fused; x3 -> p_bufb ----
    k_ln_node<<<warpNBlocks, 256>>>(p_bufa, p_bufb, ln_g, ln_b,
                                    nw1, nb1, nw2, nb2, out);

    // ---- edge head precompute ----
    k_pack_eh<<<(128 * 64 + 255) / 256, 256>>>(ew1);
    k_mma<2><<<tiles, 256, SMEM2>>>(p_bufb, p_wte, NN, 64, 64,
                                    p_ea, p_eb, nullptr, nullptr, nullptr);

    // ---- edge head, CSR order ----
    k_edge<<<(EE * 16 + 255) / 256, 256>>>((const float4*)p_ea, (const float4*)p_eb,
                                           eb1, ew2, eb2, out);
}

// round 6
// speedup vs baseline: 3.0693x; 1.0271x over previous
#include <cuda_runtime.h>
#include <math.h>
#include <stdint.h>

#define NN 50000
#define EE 1600000
#define FIN 770
#define RR 3
#define KP1 800
#define SEG (RR * NN)               // 150000
#define SCANB ((SEG + 255) / 256)   // 586

// ---------------- scratch ------------------------------------------------------
__device__ float g_xr[(size_t)RR * NN * 64];
__device__ float g_bufa[(size_t)NN * 64];
__device__ float g_bufb[(size_t)NN * 64];
__device__ float g_ea[(size_t)NN * 64];
__device__ float g_eb[(size_t)NN * 64];
__device__ float g_invc[SEG];
__device__ int   g_cnt[SEG];
__device__ int   g_off[SEG];
__device__ int   g_fill[SEG];
__device__ int   g_bsum[1024];
__device__ int   g_srcl[EE];
__device__ int   g_dstl[EE];
__device__ int   g_eidl[EE];
__device__ int   g_row[EE];
__device__ int   g_col[EE];
__device__ int   g_et[EE];
__device__ int   g_is64;
__device__ float g_wt1[256 * KP1];
__device__ float g_wt2[256 * 64];
__device__ float g_wt3[256 * 64];
__device__ float g_wte[128 * 64];

// ---------------- helpers ------------------------------------------------------
__device__ __forceinline__ uint32_t smem_u32(const void* p) {
    uint32_t a;
    asm("{ .reg .u64 t; cvta.to.shared.u64 t, %1; cvt.u32.u64 %0, t; }" : "=r"(a) : "l"(p));
    return a;
}
__device__ __forceinline__ void cp16(uint32_t dst, const void* src, int sz) {
    asm volatile("cp.async.cg.shared.global [%0], [%1], 16, %2;"
                 :: "r"(dst), "l"(src), "r"(sz) : "memory");
}
__device__ __forceinline__ void cp8(uint32_t dst, const void* src, int sz) {
    asm volatile("cp.async.ca.shared.global [%0], [%1], 8, %2;"
                 :: "r"(dst), "l"(src), "r"(sz) : "memory");
}
__device__ __forceinline__ uint32_t cvt_tf32(float f) {
    uint32_t r;
    asm("cvt.rna.tf32.f32 %0, %1;" : "=r"(r) : "f"(f));
    return r;
}
__device__ __forceinline__ float tf32r(float x) { return __uint_as_float(cvt_tf32(x)); }
__device__ __forceinline__ void mma8(float* c, const uint32_t* a, uint32_t b0, uint32_t b1) {
    asm volatile(
        "mma.sync.aligned.m16n8k8.row.col.f32.tf32.tf32.f32 "
        "{%0,%1,%2,%3}, {%4,%5,%6,%7}, {%8,%9}, {%0,%1,%2,%3};"
        : "+f"(c[0]), "+f"(c[1]), "+f"(c[2]), "+f"(c[3])
        : "r"(a[0]), "r"(a[1]), "r"(a[2]), "r"(a[3]), "r"(b0), "r"(b1));
}

// ---------------- launch 1: detect dtype + zero counters ------------------------
__global__ void k_detzero(const unsigned int* __restrict__ ei) {
    int i = blockIdx.x * blockDim.x + threadIdx.x;
    if (i < SEG) { g_cnt[i] = 0; g_fill[i] = 0; }
    if (i == 0) {
        int is64 = 1;
        for (int j = 0; j < 64; j++)
            if (ei[2 * j + 1] != 0u) { is64 = 0; break; }
        g_is64 = is64;
    }
}
// ---------------- launch 2: convert + degree count ------------------------------
__global__ void k_convert(const void* __restrict__ ei, const void* __restrict__ et) {
    int i = blockIdx.x * blockDim.x + threadIdx.x;
    if (i >= EE) return;
    int r, c, t;
    if (g_is64) {
        const long long* p = (const long long*)ei;
        r = (int)p[i];
        c = (int)p[EE + i];
        t = (int)((const long long*)et)[i];
    } else {
        const int* p = (const int*)ei;
        r = p[i];
        c = p[EE + i];
        t = ((const int*)et)[i];
    }
    g_row[i] = r; g_col[i] = c; g_et[i] = t;
    atomicAdd(&g_cnt[t * NN + c], 1);
}

// ---------------- launch 3: pack ALL weights (tf32, K-major, k8-permuted) -------
__device__ __forceinline__ int slot2k(int grp, int s) {
    return grp * 8 + (s >> 1) + ((s & 1) << 2);
}
__global__ void k_pack_all(const float* __restrict__ W1, const float* __restrict__ root1,
                           const float* __restrict__ W2, const float* __restrict__ root2,
                           const float* __restrict__ W3, const float* __restrict__ root3,
                           const float* __restrict__ ew1) {
    int i = blockIdx.x * 256 + threadIdx.x;
    if (i < 256 * KP1) {                                 // wt1
        int n = i / KP1, s = i % KP1;
        int k = slot2k(s >> 3, s & 7);
        float v = 0.f;
        if (k < FIN)
            v = (n < 192) ? W1[(size_t)(n >> 6) * FIN * 64 + (size_t)k * 64 + (n & 63)]
                          : root1[(size_t)k * 64 + (n - 192)];
        g_wt1[i] = tf32r(v);
        return;
    }
    int j = i - 256 * KP1;
    if (j < 16384) {                                     // wt2
        int n = j >> 6, s = j & 63;
        int k = slot2k(s >> 3, s & 7);
        float v = (n < 192) ? W2[(n >> 6) * 4096 + k * 64 + (n & 63)]
                            : root2[k * 64 + (n - 192)];
        g_wt2[j] = tf32r(v);
        return;
    }
    j -= 16384;
    if (j < 16384) {                                     // wt3
        int n = j >> 6, s = j & 63;
        int k = slot2k(s >> 3, s & 7);
        float v = (n < 192) ? W3[(n >> 6) * 4096 + k * 64 + (n & 63)]
                            : root3[k * 64 + (n - 192)];
        g_wt3[j] = tf32r(v);
        return;
    }
    j -= 16384;
    if (j < 8192) {                                      // wte
        int n = j >> 6, s = j & 63;
        int k = slot2k(s >> 3, s & 7);
        float v = (n < 64) ? ew1[k * 64 + n] : ew1[(64 + k) * 64 + (n - 64)];
        g_wte[j] = tf32r(v);
    }
}

// ---------------- CSR build: hierarchical exclusive scan + scatter --------------
__global__ void k_bsum() {
    __shared__ int sh[256];
    int i = blockIdx.x * 256 + threadIdx.x;
    sh[threadIdx.x] = (i < SEG) ? g_cnt[i] : 0;
    __syncthreads();
    for (int o = 128; o > 0; o >>= 1) {
        if (threadIdx.x < o) sh[threadIdx.x] += sh[threadIdx.x + o];
        __syncthreads();
    }
    if (threadIdx.x == 0) g_bsum[blockIdx.x] = sh[0];
}
__global__ void k_bscan() {
    __shared__ int sh[1024];
    int tid = threadIdx.x;
    int v = (tid < SCANB) ? g_bsum[tid] : 0;
    sh[tid] = v;
    __syncthreads();
    for (int o = 1; o < 1024; o <<= 1) {
        int t = (tid >= o) ? sh[tid - o] : 0;
        __syncthreads();
        sh[tid] += t;
        __syncthreads();
    }
    if (tid < SCANB) g_bsum[tid] = sh[tid] - v;   // exclusive
}
__global__ void k_off() {
    __shared__ int sh[256];
    int tid = threadIdx.x;
    int i = blockIdx.x * 256 + tid;
    int v = (i < SEG) ? g_cnt[i] : 0;
    sh[tid] = v;
    __syncthreads();
    for (int o = 1; o < 256; o <<= 1) {
        int t = (tid >= o) ? sh[tid - o] : 0;
        __syncthreads();
        sh[tid] += t;
        __syncthreads();
    }
    if (i < SEG) {
        g_off[i] = sh[tid] - v + g_bsum[blockIdx.x];
        g_invc[i] = 1.0f / (float)(v > 0 ? v : 1);
    }
}
__global__ void k_scatter() {
    int e = blockIdx.x * blockDim.x + threadIdx.x;
    if (e >= EE) return;
    int c = g_col[e];
    int idx = g_et[e] * NN + c;
    int pos = g_off[idx] + atomicAdd(&g_fill[idx], 1);
    g_srcl[pos] = g_row[e];
    g_dstl[pos] = c;
    g_eidl[pos] = e;
}

// ---------------- tf32 mma.sync GEMM: [M,K] @ [N,Kp]^T, N = NT*64 ---------------
template<int NT>
__device__ __forceinline__ void issue_chunk(const float* __restrict__ X,
                                            const float* __restrict__ Wt,
                                            int M, int K, int Kp, int m0, int c, uint32_t sb) {
    int tid = threadIdx.x;
    int k0 = c * 32;
    uint32_t ab = sb + (uint32_t)(c & 1) * 18432u;
    uint32_t bb = sb + 36864u + (uint32_t)(c & 1) * (uint32_t)(NT * 10240);
#pragma unroll
    for (int i = 0; i < 8; i++) {
        int u = i * 256 + tid;
        int row = u >> 4, j = u & 15;
        int kk = k0 + j * 2;
        int ok = ((m0 + row) < M) && (kk < K);
        const float* src = ok ? (X + (size_t)(m0 + row) * K + kk) : X;
        int sz = ok ? ((K - kk >= 2) ? 8 : 4) : 0;
        cp8(ab + row * 144 + j * 8, src, sz);
    }
#pragma unroll
    for (int i = 0; i < 2 * NT; i++) {
        int u = i * 256 + tid;
        int row = u >> 3, j = u & 7;
        cp16(bb + row * 160 + j * 16, Wt + (size_t)row * Kp + k0 + j * 4, 16);
    }
    asm volatile("cp.async.commit_group;" ::: "memory");
}

template<int NT>
__global__ __launch_bounds__(256, 1) void k_mma(
    const float* __restrict__ X, const float* __restrict__ Wt,
    int M, int K, int Kp,
    float* __restrict__ o0, float* __restrict__ o1,
    float* __restrict__ o2, float* __restrict__ o3,
    const float* __restrict__ bias3)
{
    extern __shared__ float smf[];
    uint32_t sb = smem_u32(smf);
    const int MT = NT;
    int tid = threadIdx.x, wid = tid >> 5, lane = tid & 31;
    int g = lane >> 2, tig = lane & 3;
    int wn = wid % NT, wm = wid / NT;
    int rowbase = wm * MT * 16;
    int m0 = blockIdx.x * 128;
    int NC = (K + 31) / 32;

    float acc[MT][8][4];
#pragma unroll
    for (int mt = 0; mt < MT; mt++)
#pragma unroll
        for (int nt = 0; nt < 8; nt++)
#pragma unroll
            for (int q = 0; q < 4; q++) acc[mt][nt][q] = 0.f;

    issue_chunk<NT>(X, Wt, M, K, Kp, m0, 0, sb);

    for (int c = 0; c < NC; c++) {
        if (c + 1 < NC) {
            issue_chunk<NT>(X, Wt, M, K, Kp, m0, c + 1, sb);
            asm volatile("cp.async.wait_group 1;" ::: "memory");
        } else {
            asm volatile("cp.async.wait_group 0;" ::: "memory");
        }
        __syncthreads();

        int af = (c & 1) * 4608;
        int bf = 9216 + (c & 1) * (NT * 2560);
#pragma unroll
        for (int k8 = 0; k8 < 4; k8++) {
            uint32_t A[MT][4];
#pragma unroll
            for (int mt = 0; mt < MT; mt++) {
                int base = af + (rowbase + mt * 16 + g) * 36 + k8 * 8 + tig;
                A[mt][0] = cvt_tf32(smf[base]);
                A[mt][1] = cvt_tf32(smf[base + 8 * 36]);
                A[mt][2] = cvt_tf32(smf[base + 4]);
                A[mt][3] = cvt_tf32(smf[base + 8 * 36 + 4]);
            }
#pragma unroll
            for (int nt = 0; nt < 8; nt++) {
                int nb = bf + (wn * 64 + nt * 8 + g) * 40 + k8 * 8 + tig * 2;
                float2 bv = *(const float2*)&smf[nb];
                uint32_t b0 = __float_as_uint(bv.x);
                uint32_t b1 = __float_as_uint(bv.y);
#pragma unroll
                for (int mt = 0; mt < MT; mt++)
                    mma8(acc[mt][nt], A[mt], b0, b1);
            }
        }
        __syncthreads();
    }

    float* outs4[4] = {o0, o1, o2, o3};
    float* o = outs4[wn];
#pragma unroll
    for (int mt = 0; mt < MT; mt++) {
        int mA = m0 + rowbase + mt * 16 + g;
        int mB = mA + 8;
#pragma unroll
        for (int nt = 0; nt < 8; nt++) {
            int col = nt * 8 + tig * 2;
            float c0 = acc[mt][nt][0], c1 = acc[mt][nt][1];
            float c2 = acc[mt][nt][2], c3 = acc[mt][nt][3];
            if (bias3 && wn == NT - 1) {
                float bb0 = bias3[col], bb1 = bias3[col + 1];
                c0 += bb0; c1 += bb1; c2 += bb0; c3 += bb1;
            }
            if (mA < M) *(float2*)(o + (size_t)mA * 64 + col) = make_float2(c0, c1);
            if (mB < M) *(float2*)(o + (size_t)mB * 64 + col) = make_float2(c2, c3);
        }
    }
}

// ---------------- CSR aggregation core (warp per dst) ---------------------------
__device__ __forceinline__ void agg_core(const float* __restrict__ xr, int w, int lane,
                                         float& a0, float& a1) {
#pragma unroll
    for (int r = 0; r < RR; r++) {
        int idx = r * NN + w;
        int beg = g_off[idx], n = g_cnt[idx];
        const float* xrr = xr + (size_t)r * NN * 64;
        float s0 = 0.f, s1 = 0.f;
        for (int b = 0; b < n; b += 32) {
            int src = (b + lane < n) ? g_srcl[beg + b + lane] : 0;
            int m = min(32, n - b);
            int j = 0;
            for (; j + 8 <= m; j += 8) {
                const float* p[8];
#pragma unroll
                for (int q = 0; q < 8; q++)
                    p[q] = xrr + (size_t)__shfl_sync(~0u, src, j + q) * 64;
                float t0 = 0.f, t1 = 0.f;
#pragma unroll
                for (int q = 0; q < 8; q++) {
                    t0 += p[q][lane];
                    t1 += p[q][lane + 32];
                }
                s0 += t0; s1 += t1;
            }
            for (; j + 4 <= m; j += 4) {
                const float* p[4];
#pragma unroll
                for (int q = 0; q < 4; q++)
                    p[q] = xrr + (size_t)__shfl_sync(~0u, src, j + q) * 64;
#pragma unroll
                for (int q = 0; q < 4; q++) {
                    s0 += p[q][lane];
                    s1 += p[q][lane + 32];
                }
            }
            for (; j < m; j++) {
                const float* p0 = xrr + (size_t)__shfl_sync(~0u, src, j) * 64;
                s0 += p0[lane];
                s1 += p0[lane + 32];
            }
        }
        float ic = g_invc[idx];
        a0 += s0 * ic;
        a1 += s1 * ic;
    }
}

__global__ void k_agg(const float* __restrict__ xr, float* __restrict__ io) {
    int w = (blockIdx.x * blockDim.x + threadIdx.x) >> 5;
    int lane = threadIdx.x & 31;
    if (w >= NN) return;
    float a0 = 0.f, a1 = 0.f;
    agg_core(xr, w, lane, a0, a1);
    float v0 = fmaxf(io[(size_t)w * 64 + lane] + a0, 0.f);
    float v1 = fmaxf(io[(size_t)w * 64 + lane + 32] + a1, 0.f);
    io[(size_t)w * 64 + lane]      = v0;
    io[(size_t)w * 64 + lane + 32] = v1;
}

// ---------------- fused: agg(layer3) + LayerNorm + node head --------------------
__global__ void k_agg_ln_node(const float* __restrict__ xr, const float* __restrict__ io,
                              float* __restrict__ x3out,
                              const float* __restrict__ gg, const float* __restrict__ bb,
                              const float* __restrict__ nw1, const float* __restrict__ nb1,
                              const float* __restrict__ nw2, const float* __restrict__ nb2,
                              float* __restrict__ outp) {
    __shared__ float s_w1[64 * 32];
    __shared__ float s_b1[32], s_w2[64], s_b2[2], s_g[64], s_bb[64];
    int tid = threadIdx.x;
    for (int i = tid; i < 2048; i += blockDim.x) s_w1[i] = nw1[i];
    if (tid < 32) s_b1[tid] = nb1[tid];
    if (tid < 64) { s_w2[tid] = nw2[tid]; s_g[tid] = gg[tid]; s_bb[tid] = bb[tid]; }
    if (tid < 2)  s_b2[tid] = nb2[tid];
    __syncthreads();

    int w = (blockIdx.x * blockDim.x + tid) >> 5;
    int lane = tid & 31;
    if (w >= NN) return;
    float a0 = 0.f, a1 = 0.f;
    agg_core(xr, w, lane, a0, a1);
    float v0 = io[(size_t)w * 64 + lane] + a0;
    float v1 = io[(size_t)w * 64 + lane + 32] + a1;

    float s = v0 + v1;
#pragma unroll
    for (int off = 16; off; off >>= 1) s += __shfl_xor_sync(~0u, s, off);
    float mu = s * (1.f / 64.f);
    float d0 = v0 - mu, d1 = v1 - mu;
    float q = d0 * d0 + d1 * d1;
#pragma unroll
    for (int off = 16; off; off >>= 1) q += __shfl_xor_sync(~0u, q, off);
    float rs = rsqrtf(q * (1.f / 64.f) + 1e-5f);
    float xa = d0 * rs * s_g[lane] + s_bb[lane];
    float xb = d1 * rs * s_g[lane + 32] + s_bb[lane + 32];
    x3out[(size_t)w * 64 + lane]      = xa;
    x3out[(size_t)w * 64 + lane + 32] = xb;

    float acc = s_b1[lane];
#pragma unroll
    for (int k = 0; k < 32; k++) {
        float xv = __shfl_sync(~0u, xa, k);
        acc += xv * s_w1[k * 32 + lane];
    }
#pragma unroll
    for (int k = 0; k < 32; k++) {
        float xv = __shfl_sync(~0u, xb, k);
        acc += xv * s_w1[(k + 32) * 32 + lane];
    }
    float nh = fmaxf(acc, 0.f);
    float p0 = nh * s_w2[lane * 2 + 0];
    float p1 = nh * s_w2[lane * 2 + 1];
#pragma unroll
    for (int off = 16; off; off >>= 1) {
        p0 += __shfl_xor_sync(~0u, p0, off);
        p1 += __shfl_xor_sync(~0u, p1, off);
    }
    if (lane == 0) {
        float l0 = p0 + s_b2[0], l1 = p1 + s_b2[1];
        float mx = fmaxf(l0, l1);
        float lse = __logf(__expf(l0 - mx) + __expf(l1 - mx)) + mx;
        outp[(size_t)3 * EE + (size_t)w * 2 + 0] = l0 - lse;
        outp[(size_t)3 * EE + (size_t)w * 2 + 1] = l1 - lse;
    }
}

// ---------------- edge classifier, CSR order (16 lanes per entry) ---------------
__global__ void k_edge(const float4* __restrict__ ea4, const float4* __restrict__ eb4,
                       const float* __restrict__ eb1, const float* __restrict__ ew2,
                       const float* __restrict__ eb2, float* __restrict__ outp) {
    __shared__ float s_b1[64], s_w2[192], s_b2[3];
    int tid = threadIdx.x;
    if (tid < 64)  s_b1[tid] = eb1[tid];
    if (tid < 192) s_w2[tid] = ew2[tid];
    if (tid < 3)   s_b2[tid] = eb2[tid];
    __syncthreads();

    int gid = blockIdx.x * blockDim.x + tid;
    int p = gid >> 4, sub = tid & 15;
    if (p >= EE) return;
    int r  = g_srcl[p];
    int c  = g_dstl[p];
    int id = g_eidl[p];
    float4 va = ea4[(size_t)r * 16 + sub];
    float4 vb = eb4[(size_t)c * 16 + sub];
    float h[4];
    h[0] = fmaxf(va.x + vb.x + s_b1[sub * 4 + 0], 0.f);
    h[1] = fmaxf(va.y + vb.y + s_b1[sub * 4 + 1], 0.f);
    h[2] = fmaxf(va.z + vb.z + s_b1[sub * 4 + 2], 0.f);
    h[3] = fmaxf(va.w + vb.w + s_b1[sub * 4 + 3], 0.f);
    float p0 = 0.f, p1 = 0.f, p2 = 0.f;
#pragma unroll
    for (int i = 0; i < 4; i++) {
        int f = sub * 4 + i;
        p0 += h[i] * s_w2[f * 3 + 0];
        p1 += h[i] * s_w2[f * 3 + 1];
        p2 += h[i] * s_w2[f * 3 + 2];
    }
#pragma unroll
    for (int off = 8; off; off >>= 1) {
        p0 += __shfl_xor_sync(~0u, p0, off);
        p1 += __shfl_xor_sync(~0u, p1, off);
        p2 += __shfl_xor_sync(~0u, p2, off);
    }
    if (sub == 0) {
        float l0 = p0 + s_b2[0], l1 = p1 + s_b2[1], l2 = p2 + s_b2[2];
        float mx = fmaxf(l0, fmaxf(l1, l2));
        float lse = __logf(__expf(l0 - mx) + __expf(l1 - mx) + __expf(l2 - mx)) + mx;
        outp[(size_t)id * 3 + 0] = l0 - lse;
        outp[(size_t)id * 3 + 1] = l1 - lse;
        outp[(size_t)id * 3 + 2] = l2 - lse;
    }
}

// ---------------- host orchestration -------------------------------------------
extern "C" void kernel_launch(void* const* d_in, const int* in_sizes, int n_in,
                              void* d_out, int out_size) {
    const float* x     = (const float*)d_in[0];
    const void*  eidx  = d_in[1];
    const void*  etyp  = d_in[2];
    const float* W1    = (const float*)d_in[3];
    const float* root1 = (const float*)d_in[4];
    const float* b1    = (const float*)d_in[5];
    const float* W2    = (const float*)d_in[6];
    const float* root2 = (const float*)d_in[7];
    const float* b2    = (const float*)d_in[8];
    const float* W3    = (const float*)d_in[9];
    const float* root3 = (const float*)d_in[10];
    const float* b3    = (const float*)d_in[11];
    const float* ln_g  = (const float*)d_in[12];
    const float* ln_b  = (const float*)d_in[13];
    const float* ew1   = (const float*)d_in[14];
    const float* eb1   = (const float*)d_in[15];
    const float* ew2   = (const float*)d_in[16];
    const float* eb2   = (const float*)d_in[17];
    const float* nw1   = (const float*)d_in[18];
    const float* nb1   = (const float*)d_in[19];
    const float* nw2   = (const float*)d_in[20];
    const float* nb2   = (const float*)d_in[21];
    float* out = (float*)d_out;

    float *p_xr, *p_bufa, *p_bufb, *p_ea, *p_eb, *p_wt1, *p_wt2, *p_wt3, *p_wte;
    cudaGetSymbolAddress((void**)&p_xr,   g_xr);
    cudaGetSymbolAddress((void**)&p_bufa, g_bufa);
    cudaGetSymbolAddress((void**)&p_bufb, g_bufb);
    cudaGetSymbolAddress((void**)&p_ea,   g_ea);
    cudaGetSymbolAddress((void**)&p_eb,   g_eb);
    cudaGetSymbolAddress((void**)&p_wt1,  g_wt1);
    cudaGetSymbolAddress((void**)&p_wt2,  g_wt2);
    cudaGetSymbolAddress((void**)&p_wt3,  g_wt3);
    cudaGetSymbolAddress((void**)&p_wte,  g_wte);

    const int SMEM4 = 36864 + 2 * 4 * 10240;   // 118784 B
    const int SMEM2 = 36864 + 2 * 2 * 10240;   //  77824 B
    cudaFuncSetAttribute(k_mma<4>, cudaFuncAttributeMaxDynamicSharedMemorySize, SMEM4);
    cudaFuncSetAttribute(k_mma<2>, cudaFuncAttributeMaxDynamicSharedMemorySize, SMEM2);

    int tiles = (NN + 127) / 128;            // 391
    int warpNBlocks = (NN * 32 + 255) / 256;
    int packN = 256 * KP1 + 16384 + 16384 + 8192;
    size_t NH = (size_t)NN * 64;

    // 1-4: detect+zero, convert+count, pack all weights, layer-1 GEMM (profiled)
    k_detzero<<<(SEG + 255) / 256, 256>>>((const unsigned int*)eidx);
    k_convert<<<(EE + 255) / 256, 256>>>(eidx, etyp);
    k_pack_all<<<(packN + 255) / 256, 256>>>(W1, root1, W2, root2, W3, root3, ew1);
    k_mma<4><<<tiles, 256, SMEM4>>>(x, p_wt1, NN, FIN, KP1,
                                    p_xr, p_xr + NH, p_xr + 2 * NH, p_bufa, b1);

    // 5-8: CSR build
    k_bsum<<<SCANB, 256>>>();
    k_bscan<<<1, 1024>>>();
    k_off<<<SCANB, 256>>>();
    k_scatter<<<(EE + 255) / 256, 256>>>();

    // 9: layer-1 aggregate + relu
    k_agg<<<warpNBlocks, 256>>>(p_xr, p_bufa);

    // 10-11: layer 2
    k_mma<4><<<tiles, 256, SMEM4>>>(p_bufa, p_wt2, NN, 64, 64,
                                    p_xr, p_xr + NH, p_xr + 2 * NH, p_bufb, b2);
    k_agg<<<warpNBlocks, 256>>>(p_xr, p_bufb);

    // 12-13: layer 3 + fused agg/LN/node-head (x3 -> p_bufa)
    k_mma<4><<<tiles, 256, SMEM4>>>(p_bufb, p_wt3, NN, 64, 64,
                                    p_xr, p_xr + NH, p_xr + 2 * NH, p_bufa, b3);
    k_agg_ln_node<<<warpNBlocks, 256>>>(p_xr, p_bufa, p_bufb, ln_g, ln_b,
                                        nw1, nb1, nw2, nb2, out);

    // 14-15: edge head
    k_mma<2><<<tiles, 256, SMEM2>>>(p_bufb, p_wte, NN, 64, 64,
                                    p_ea, p_eb, nullptr, nullptr, nullptr);
    k_edge<<<(EE * 16 + 255) / 256, 256>>>((const float4*)p_ea, (const float4*)p_eb,
                                           eb1, ew2, eb2, out);
}

// round 7
// speedup vs baseline: 3.3372x; 1.0873x over previous
#include <cuda_runtime.h>
#include <math.h>
#include <stdint.h>

#define NN 50000
#define EE 1600000
#define FIN 770
#define RR 3
#define KP1 800
#define SEG (RR * NN)               // 150000
#define SCANB ((SEG + 255) / 256)   // 586

// ---------------- scratch ------------------------------------------------------
__device__ float g_xr[(size_t)RR * NN * 64];
__device__ float g_bufa[(size_t)NN * 64];
__device__ float g_bufb[(size_t)NN * 64];
__device__ float g_ea[(size_t)NN * 64];
__device__ float g_eb[(size_t)NN * 64];
__device__ float g_invc[SEG];
__device__ int   g_cnt[SEG];
__device__ int   g_off[SEG];
__device__ int   g_fill[SEG];
__device__ int   g_bsum[1024];
__device__ int   g_srcl[EE];
__device__ int   g_dstl[EE];
__device__ int   g_eidl[EE];
__device__ int   g_row[EE];
__device__ int   g_col[EE];
__device__ int   g_et[EE];
__device__ int   g_is64;
__device__ uint32_t g_wt1[256 * 400];   // bf16x2 pairs, [N][Kp/2]
__device__ uint32_t g_wt2[256 * 32];
__device__ uint32_t g_wt3[256 * 32];
__device__ uint32_t g_wte[128 * 32];

// ---------------- helpers ------------------------------------------------------
__device__ __forceinline__ uint32_t smem_u32(const void* p) {
    uint32_t a;
    asm("{ .reg .u64 t; cvta.to.shared.u64 t, %1; cvt.u32.u64 %0, t; }" : "=r"(a) : "l"(p));
    return a;
}
__device__ __forceinline__ void cp16(uint32_t dst, const void* src, int sz) {
    asm volatile("cp.async.cg.shared.global [%0], [%1], 16, %2;"
                 :: "r"(dst), "l"(src), "r"(sz) : "memory");
}
__device__ __forceinline__ void cp8(uint32_t dst, const void* src, int sz) {
    asm volatile("cp.async.ca.shared.global [%0], [%1], 8, %2;"
                 :: "r"(dst), "l"(src), "r"(sz) : "memory");
}
// pack two f32 -> bf16x2 (lo = first arg)
__device__ __forceinline__ uint32_t f2bf2(float lo, float hi) {
    uint32_t r;
    asm("cvt.rn.bf16x2.f32 %0, %1, %2;" : "=r"(r) : "f"(hi), "f"(lo));
    return r;
}
__device__ __forceinline__ void mma16(float* c, const uint32_t* a, uint32_t b0, uint32_t b1) {
    asm volatile(
        "mma.sync.aligned.m16n8k16.row.col.f32.bf16.bf16.f32 "
        "{%0,%1,%2,%3}, {%4,%5,%6,%7}, {%8,%9}, {%0,%1,%2,%3};"
        : "+f"(c[0]), "+f"(c[1]), "+f"(c[2]), "+f"(c[3])
        : "r"(a[0]), "r"(a[1]), "r"(a[2]), "r"(a[3]), "r"(b0), "r"(b1));
}

// ---------------- launch 1: detect dtype + zero counters ------------------------
__global__ void k_detzero(const unsigned int* __restrict__ ei) {
    int i = blockIdx.x * blockDim.x + threadIdx.x;
    if (i < SEG) { g_cnt[i] = 0; g_fill[i] = 0; }
    if (i == 0) {
        int is64 = 1;
        for (int j = 0; j < 64; j++)
            if (ei[2 * j + 1] != 0u) { is64 = 0; break; }
        g_is64 = is64;
    }
}
// ---------------- launch 2: convert + degree count ------------------------------
__global__ void k_convert(const void* __restrict__ ei, const void* __restrict__ et) {
    int i = blockIdx.x * blockDim.x + threadIdx.x;
    if (i >= EE) return;
    int r, c, t;
    if (g_is64) {
        const long long* p = (const long long*)ei;
        r = (int)p[i];
        c = (int)p[EE + i];
        t = (int)((const long long*)et)[i];
    } else {
        const int* p = (const int*)ei;
        r = p[i];
        c = p[EE + i];
        t = ((const int*)et)[i];
    }
    g_row[i] = r; g_col[i] = c; g_et[i] = t;
    atomicAdd(&g_cnt[t * NN + c], 1);
}

// ---------------- launch 3: pack ALL weights to bf16x2 pairs --------------------
// frag-order pack: within each 16-k group, uint32 slot j (0..7):
//   tig = j>>1, hi = j&1  ->  k0 = grp*16 + tig*2 + hi*8, pair (k0, k0+1)
__global__ void k_pack_all(const float* __restrict__ W1, const float* __restrict__ root1,
                           const float* __restrict__ W2, const float* __restrict__ root2,
                           const float* __restrict__ W3, const float* __restrict__ root3,
                           const float* __restrict__ ew1) {
    int i = blockIdx.x * 256 + threadIdx.x;
    if (i < 256 * 400) {                                 // wt1  [256][400]
        int n = i / 400, s = i % 400;
        int jj = s & 7, k0 = (s >> 3) * 16 + (jj >> 1) * 2 + (jj & 1) * 8;
        float lo = 0.f, hi = 0.f;
        if (n < 192) {
            if (k0 < FIN)     lo = W1[(size_t)(n >> 6) * FIN * 64 + (size_t)k0 * 64 + (n & 63)];
            if (k0 + 1 < FIN) hi = W1[(size_t)(n >> 6) * FIN * 64 + (size_t)(k0 + 1) * 64 + (n & 63)];
        } else {
            if (k0 < FIN)     lo = root1[(size_t)k0 * 64 + (n - 192)];
            if (k0 + 1 < FIN) hi = root1[(size_t)(k0 + 1) * 64 + (n - 192)];
        }
        g_wt1[i] = f2bf2(lo, hi);
        return;
    }
    int j = i - 256 * 400;
    if (j < 8192) {                                      // wt2 [256][32]
        int n = j >> 5, s = j & 31;
        int jj = s & 7, k0 = (s >> 3) * 16 + (jj >> 1) * 2 + (jj & 1) * 8;
        float lo, hi;
        if (n < 192) {
            lo = W2[(n >> 6) * 4096 + k0 * 64 + (n & 63)];
            hi = W2[(n >> 6) * 4096 + (k0 + 1) * 64 + (n & 63)];
        } else {
            lo = root2[k0 * 64 + (n - 192)];
            hi = root2[(k0 + 1) * 64 + (n - 192)];
        }
        g_wt2[j] = f2bf2(lo, hi);
        return;
    }
    j -= 8192;
    if (j < 8192) {                                      // wt3
        int n = j >> 5, s = j & 31;
        int jj = s & 7, k0 = (s >> 3) * 16 + (jj >> 1) * 2 + (jj & 1) * 8;
        float lo, hi;
        if (n < 192) {
            lo = W3[(n >> 6) * 4096 + k0 * 64 + (n & 63)];
            hi = W3[(n >> 6) * 4096 + (k0 + 1) * 64 + (n & 63)];
        } else {
            lo = root3[k0 * 64 + (n - 192)];
            hi = root3[(k0 + 1) * 64 + (n - 192)];
        }
        g_wt3[j] = f2bf2(lo, hi);
        return;
    }
    j -= 8192;
    if (j < 4096) {                                      // wte [128][32]
        int n = j >> 5, s = j & 31;
        int jj = s & 7, k0 = (s >> 3) * 16 + (jj >> 1) * 2 + (jj & 1) * 8;
        float lo, hi;
        if (n < 64) { lo = ew1[k0 * 64 + n];        hi = ew1[(k0 + 1) * 64 + n]; }
        else        { lo = ew1[(64 + k0) * 64 + (n - 64)]; hi = ew1[(64 + k0 + 1) * 64 + (n - 64)]; }
        g_wte[j] = f2bf2(lo, hi);
    }
}

// ---------------- CSR build ------------------------------------------------------
__global__ void k_bsum() {
    __shared__ int sh[256];
    int i = blockIdx.x * 256 + threadIdx.x;
    sh[threadIdx.x] = (i < SEG) ? g_cnt[i] : 0;
    __syncthreads();
    for (int o = 128; o > 0; o >>= 1) {
        if (threadIdx.x < o) sh[threadIdx.x] += sh[threadIdx.x + o];
        __syncthreads();
    }
    if (threadIdx.x == 0) g_bsum[blockIdx.x] = sh[0];
}
__global__ void k_bscan() {
    __shared__ int sh[1024];
    int tid = threadIdx.x;
    int v = (tid < SCANB) ? g_bsum[tid] : 0;
    sh[tid] = v;
    __syncthreads();
    for (int o = 1; o < 1024; o <<= 1) {
        int t = (tid >= o) ? sh[tid - o] : 0;
        __syncthreads();
        sh[tid] += t;
        __syncthreads();
    }
    if (tid < SCANB) g_bsum[tid] = sh[tid] - v;
}
__global__ void k_off() {
    __shared__ int sh[256];
    int tid = threadIdx.x;
    int i = blockIdx.x * 256 + tid;
    int v = (i < SEG) ? g_cnt[i] : 0;
    sh[tid] = v;
    __syncthreads();
    for (int o = 1; o < 256; o <<= 1) {
        int t = (tid >= o) ? sh[tid - o] : 0;
        __syncthreads();
        sh[tid] += t;
        __syncthreads();
    }
    if (i < SEG) {
        g_off[i] = sh[tid] - v + g_bsum[blockIdx.x];
        g_invc[i] = 1.0f / (float)(v > 0 ? v : 1);
    }
}
__global__ void k_scatter() {
    int e = blockIdx.x * blockDim.x + threadIdx.x;
    if (e >= EE) return;
    int c = g_col[e];
    int idx = g_et[e] * NN + c;
    int pos = g_off[idx] + atomicAdd(&g_fill[idx], 1);
    g_srcl[pos] = g_row[e];
    g_dstl[pos] = c;
    g_eidl[pos] = e;
}

// ---------------- bf16 mma.sync GEMM: [M,K]f32 @ bf16[N,Kp]^T, N = NT*64 --------
// 512 threads / 16 warps; MT = NT/2 row-tiles of 16 per warp; 3-stage cp.async.
// SMEM: A[3][128][40]f at 0 (20480 B/stage), B[3][NT*64][24]u32 at 61440.
template<int NT>
__device__ __forceinline__ void issue_chunk(const float* __restrict__ X,
                                            const uint32_t* __restrict__ Wt,
                                            int M, int K, int Kp2, int m0, int c, int buf,
                                            uint32_t sb) {
    int tid = threadIdx.x;
    int k0 = c * 32;
    uint32_t ab = sb + (uint32_t)buf * 20480u;
    uint32_t bb = sb + 61440u + (uint32_t)buf * (uint32_t)(NT * 6144);
#pragma unroll
    for (int i = 0; i < 4; i++) {
        int u = i * 512 + tid;               // 2048 units: 128 rows x 16 of 8B
        int row = u >> 4, j = u & 15;
        int kk = k0 + j * 2;
        int ok = ((m0 + row) < M) && (kk < K);
        const float* src = ok ? (X + (size_t)(m0 + row) * K + kk) : X;
        int sz = ok ? ((K - kk >= 2) ? 8 : 4) : 0;
        cp8(ab + row * 160 + j * 8, src, sz);
    }
#pragma unroll
    for (int i = 0; i < NT / 2; i++) {
        int u = i * 512 + tid;               // NT*64 rows x 4 units of 16B
        int row = u >> 2, j = u & 3;
        cp16(bb + row * 96 + j * 16, Wt + (size_t)row * Kp2 + c * 16 + j * 4, 16);
    }
    asm volatile("cp.async.commit_group;" ::: "memory");
}

template<int NT>
__global__ __launch_bounds__(512, 1) void k_mma(
    const float* __restrict__ X, const uint32_t* __restrict__ Wt,
    int M, int K, int Kp2,
    float* __restrict__ o0, float* __restrict__ o1,
    float* __restrict__ o2, float* __restrict__ o3,
    const float* __restrict__ bias3)
{
    extern __shared__ float smf[];
    const uint32_t* smu = (const uint32_t*)smf;
    uint32_t sb = smem_u32(smf);
    const int MT = NT / 2;
    int tid = threadIdx.x, wid = tid >> 5, lane = tid & 31;
    int g = lane >> 2, tig = lane & 3;
    int wn = wid % NT, wm = wid / NT;       // wm: 0..(16/NT - 1)
    int rowbase = wm * MT * 16;
    int m0 = blockIdx.x * 128;
    int NC = (K + 31) / 32;

    float acc[MT][8][4];
#pragma unroll
    for (int mt = 0; mt < MT; mt++)
#pragma unroll
        for (int nt = 0; nt < 8; nt++)
#pragma unroll
            for (int q = 0; q < 4; q++) acc[mt][nt][q] = 0.f;

    issue_chunk<NT>(X, Wt, M, K, Kp2, m0, 0, 0, sb);
    if (NC > 1) issue_chunk<NT>(X, Wt, M, K, Kp2, m0, 1, 1, sb);

    int buf = 0;
    for (int c = 0; c < NC; c++) {
        if (c + 2 < NC) {
            int b2 = buf + 2; if (b2 >= 3) b2 -= 3;
            issue_chunk<NT>(X, Wt, M, K, Kp2, m0, c + 2, b2, sb);
            asm volatile("cp.async.wait_group 2;" ::: "memory");
        } else if (c + 1 < NC) {
            asm volatile("cp.async.wait_group 1;" ::: "memory");
        } else {
            asm volatile("cp.async.wait_group 0;" ::: "memory");
        }
        __syncthreads();

        int af = buf * 5120;                       // float offset
        int bf = 15360 + buf * (NT * 1536);        // uint32 offset
#pragma unroll
        for (int st = 0; st < 2; st++) {           // two k16 steps per 32-chunk
            uint32_t A[MT][4];
#pragma unroll
            for (int mt = 0; mt < MT; mt++) {
                int base = af + (rowbase + mt * 16 + g) * 40 + st * 16 + 2 * tig;
                float2 x0 = *(const float2*)&smf[base];
                float2 x1 = *(const float2*)&smf[base + 8 * 40];
                float2 x2 = *(const float2*)&smf[base + 8];
                float2 x3 = *(const float2*)&smf[base + 8 * 40 + 8];
                A[mt][0] = f2bf2(x0.x, x0.y);
                A[mt][1] = f2bf2(x1.x, x1.y);
                A[mt][2] = f2bf2(x2.x, x2.y);
                A[mt][3] = f2bf2(x3.x, x3.y);
            }
#pragma unroll
            for (int nt = 0; nt < 8; nt++) {
                int nb = bf + (wn * 64 + nt * 8 + g) * 24 + st * 8 + tig * 2;
                uint2 bv = *(const uint2*)&smu[nb];
#pragma unroll
                for (int mt = 0; mt < MT; mt++)
                    mma16(acc[mt][nt], A[mt], bv.x, bv.y);
            }
        }
        __syncthreads();
        buf = (buf + 1 == 3) ? 0 : buf + 1;
    }

    float* outs4[4] = {o0, o1, o2, o3};
    float* o = outs4[wn];
#pragma unroll
    for (int mt = 0; mt < MT; mt++) {
        int mA = m0 + rowbase + mt * 16 + g;
        int mB = mA + 8;
#pragma unroll
        for (int nt = 0; nt < 8; nt++) {
            int col = nt * 8 + tig * 2;
            float c0 = acc[mt][nt][0], c1 = acc[mt][nt][1];
            float c2 = acc[mt][nt][2], c3 = acc[mt][nt][3];
            if (bias3 && wn == NT - 1) {
                float bb0 = bias3[col], bb1 = bias3[col + 1];
                c0 += bb0; c1 += bb1; c2 += bb0; c3 += bb1;
            }
            if (mA < M) *(float2*)(o + (size_t)mA * 64 + col) = make_float2(c0, c1);
            if (mB < M) *(float2*)(o + (size_t)mB * 64 + col) = make_float2(c2, c3);
        }
    }
}

// ---------------- CSR aggregation core (warp per dst) ---------------------------
__device__ __forceinline__ void agg_core(const float* __restrict__ xr, int w, int lane,
                                         float& a0, float& a1) {
#pragma unroll
    for (int r = 0; r < RR; r++) {
        int idx = r * NN + w;
        int beg = g_off[idx], n = g_cnt[idx];
        const float* xrr = xr + (size_t)r * NN * 64;
        float s0 = 0.f, s1 = 0.f;
        for (int b = 0; b < n; b += 32) {
            int src = (b + lane < n) ? g_srcl[beg + b + lane] : 0;
            int m = min(32, n - b);
            int j = 0;
            for (; j + 8 <= m; j += 8) {
                const float* p[8];
#pragma unroll
                for (int q = 0; q < 8; q++)
                    p[q] = xrr + (size_t)__shfl_sync(~0u, src, j + q) * 64;
                float t0 = 0.f, t1 = 0.f;
#pragma unroll
                for (int q = 0; q < 8; q++) {
                    t0 += p[q][lane];
                    t1 += p[q][lane + 32];
                }
                s0 += t0; s1 += t1;
            }
            for (; j + 4 <= m; j += 4) {
                const float* p[4];
#pragma unroll
                for (int q = 0; q < 4; q++)
                    p[q] = xrr + (size_t)__shfl_sync(~0u, src, j + q) * 64;
#pragma unroll
                for (int q = 0; q < 4; q++) {
                    s0 += p[q][lane];
                    s1 += p[q][lane + 32];
                }
            }
            for (; j < m; j++) {
                const float* p0 = xrr + (size_t)__shfl_sync(~0u, src, j) * 64;
                s0 += p0[lane];
                s1 += p0[lane + 32];
            }
        }
        float ic = g_invc[idx];
        a0 += s0 * ic;
        a1 += s1 * ic;
    }
}

__global__ void k_agg(const float* __restrict__ xr, float* __restrict__ io) {
    int w = (blockIdx.x * blockDim.x + threadIdx.x) >> 5;
    int lane = threadIdx.x & 31;
    if (w >= NN) return;
    float a0 = 0.f, a1 = 0.f;
    agg_core(xr, w, lane, a0, a1);
    float v0 = fmaxf(io[(size_t)w * 64 + lane] + a0, 0.f);
    float v1 = fmaxf(io[(size_t)w * 64 + lane + 32] + a1, 0.f);
    io[(size_t)w * 64 + lane]      = v0;
    io[(size_t)w * 64 + lane + 32] = v1;
}

// ---------------- fused: agg(layer3) + LayerNorm + node head --------------------
__global__ void k_agg_ln_node(const float* __restrict__ xr, const float* __restrict__ io,
                              float* __restrict__ x3out,
                              const float* __restrict__ gg, const float* __restrict__ bb,
                              const float* __restrict__ nw1, const float* __restrict__ nb1,
                              const float* __restrict__ nw2, const float* __restrict__ nb2,
                              float* __restrict__ outp) {
    __shared__ float s_w1[64 * 32];
    __shared__ float s_b1[32], s_w2[64], s_b2[2], s_g[64], s_bb[64];
    int tid = threadIdx.x;
    for (int i = tid; i < 2048; i += blockDim.x) s_w1[i] = nw1[i];
    if (tid < 32) s_b1[tid] = nb1[tid];
    if (tid < 64) { s_w2[tid] = nw2[tid]; s_g[tid] = gg[tid]; s_bb[tid] = bb[tid]; }
    if (tid < 2)  s_b2[tid] = nb2[tid];
    __syncthreads();

    int w = (blockIdx.x * blockDim.x + tid) >> 5;
    int lane = tid & 31;
    if (w >= NN) return;
    float a0 = 0.f, a1 = 0.f;
    agg_core(xr, w, lane, a0, a1);
    float v0 = io[(size_t)w * 64 + lane] + a0;
    float v1 = io[(size_t)w * 64 + lane + 32] + a1;

    float s = v0 + v1;
#pragma unroll
    for (int off = 16; off; off >>= 1) s += __shfl_xor_sync(~0u, s, off);
    float mu = s * (1.f / 64.f);
    float d0 = v0 - mu, d1 = v1 - mu;
    float q = d0 * d0 + d1 * d1;
#pragma unroll
    for (int off = 16; off; off >>= 1) q += __shfl_xor_sync(~0u, q, off);
    float rs = rsqrtf(q * (1.f / 64.f) + 1e-5f);
    float xa = d0 * rs * s_g[lane] + s_bb[lane];
    float xb = d1 * rs * s_g[lane + 32] + s_bb[lane + 32];
    x3out[(size_t)w * 64 + lane]      = xa;
    x3out[(size_t)w * 64 + lane + 32] = xb;

    float acc = s_b1[lane];
#pragma unroll
    for (int k = 0; k < 32; k++) {
        float xv = __shfl_sync(~0u, xa, k);
        acc += xv * s_w1[k * 32 + lane];
    }
#pragma unroll
    for (int k = 0; k < 32; k++) {
        float xv = __shfl_sync(~0u, xb, k);
        acc += xv * s_w1[(k + 32) * 32 + lane];
    }
    float nh = fmaxf(acc, 0.f);
    float p0 = nh * s_w2[lane * 2 + 0];
    float p1 = nh * s_w2[lane * 2 + 1];
#pragma unroll
    for (int off = 16; off; off >>= 1) {
        p0 += __shfl_xor_sync(~0u, p0, off);
        p1 += __shfl_xor_sync(~0u, p1, off);
    }
    if (lane == 0) {
        float l0 = p0 + s_b2[0], l1 = p1 + s_b2[1];
        float mx = fmaxf(l0, l1);
        float lse = __logf(__expf(l0 - mx) + __expf(l1 - mx)) + mx;
        outp[(size_t)3 * EE + (size_t)w * 2 + 0] = l0 - lse;
        outp[(size_t)3 * EE + (size_t)w * 2 + 1] = l1 - lse;
    }
}

// ---------------- edge classifier, CSR order (16 lanes per entry) ---------------
__global__ void k_edge(const float4* __restrict__ ea4, const float4* __restrict__ eb4,
                       const float* __restrict__ eb1, const float* __restrict__ ew2,
                       const float* __restrict__ eb2, float* __restrict__ outp) {
    __shared__ float s_b1[64], s_w2[192], s_b2[3];
    int tid = threadIdx.x;
    if (tid < 64)  s_b1[tid] = eb1[tid];
    if (tid < 192) s_w2[tid] = ew2[tid];
    if (tid < 3)   s_b2[tid] = eb2[tid];
    __syncthreads();

    int gid = blockIdx.x * blockDim.x + tid;
    int p = gid >> 4, sub = tid & 15;
    if (p >= EE) return;
    int r  = g_srcl[p];
    int c  = g_dstl[p];
    int id = g_eidl[p];
    float4 va = ea4[(size_t)r * 16 + sub];
    float4 vb = eb4[(size_t)c * 16 + sub];
    float h[4];
    h[0] = fmaxf(va.x + vb.x + s_b1[sub * 4 + 0], 0.f);
    h[1] = fmaxf(va.y + vb.y + s_b1[sub * 4 + 1], 0.f);
    h[2] = fmaxf(va.z + vb.z + s_b1[sub * 4 + 2], 0.f);
    h[3] = fmaxf(va.w + vb.w + s_b1[sub * 4 + 3], 0.f);
    float p0 = 0.f, p1 = 0.f, p2 = 0.f;
#pragma unroll
    for (int i = 0; i < 4; i++) {
        int f = sub * 4 + i;
        p0 += h[i] * s_w2[f * 3 + 0];
        p1 += h[i] * s_w2[f * 3 + 1];
        p2 += h[i] * s_w2[f * 3 + 2];
    }
#pragma unroll
    for (int off = 8; off; off >>= 1) {
        p0 += __shfl_xor_sync(~0u, p0, off);
        p1 += __shfl_xor_sync(~0u, p1, off);
        p2 += __shfl_xor_sync(~0u, p2, off);
    }
    if (sub == 0) {
        float l0 = p0 + s_b2[0], l1 = p1 + s_b2[1], l2 = p2 + s_b2[2];
        float mx = fmaxf(l0, fmaxf(l1, l2));
        float lse = __logf(__expf(l0 - mx) + __expf(l1 - mx) + __expf(l2 - mx)) + mx;
        outp[(size_t)id * 3 + 0] = l0 - lse;
        outp[(size_t)id * 3 + 1] = l1 - lse;
        outp[(size_t)id * 3 + 2] = l2 - lse;
    }
}

// ---------------- host orchestration -------------------------------------------
extern "C" void kernel_launch(void* const* d_in, const int* in_sizes, int n_in,
                              void* d_out, int out_size) {
    const float* x     = (const float*)d_in[0];
    const void*  eidx  = d_in[1];
    const void*  etyp  = d_in[2];
    const float* W1    = (const float*)d_in[3];
    const float* root1 = (const float*)d_in[4];
    const float* b1    = (const float*)d_in[5];
    const float* W2    = (const float*)d_in[6];
    const float* root2 = (const float*)d_in[7];
    const float* b2    = (const float*)d_in[8];
    const float* W3    = (const float*)d_in[9];
    const float* root3 = (const float*)d_in[10];
    const float* b3    = (const float*)d_in[11];
    const float* ln_g  = (const float*)d_in[12];
    const float* ln_b  = (const float*)d_in[13];
    const float* ew1   = (const float*)d_in[14];
    const float* eb1   = (const float*)d_in[15];
    const float* ew2   = (const float*)d_in[16];
    const float* eb2   = (const float*)d_in[17];
    const float* nw1   = (const float*)d_in[18];
    const float* nb1   = (const float*)d_in[19];
    const float* nw2   = (const float*)d_in[20];
    const float* nb2   = (const float*)d_in[21];
    float* out = (float*)d_out;

    float *p_xr, *p_bufa, *p_bufb, *p_ea, *p_eb;
    uint32_t *p_wt1, *p_wt2, *p_wt3, *p_wte;
    cudaGetSymbolAddress((void**)&p_xr,   g_xr);
    cudaGetSymbolAddress((void**)&p_bufa, g_bufa);
    cudaGetSymbolAddress((void**)&p_bufb, g_bufb);
    cudaGetSymbolAddress((void**)&p_ea,   g_ea);
    cudaGetSymbolAddress((void**)&p_eb,   g_eb);
    cudaGetSymbolAddress((void**)&p_wt1,  g_wt1);
    cudaGetSymbolAddress((void**)&p_wt2,  g_wt2);
    cudaGetSymbolAddress((void**)&p_wt3,  g_wt3);
    cudaGetSymbolAddress((void**)&p_wte,  g_wte);

    const int SMEM4 = 61440 + 3 * 4 * 6144;   // 135168 B
    const int SMEM2 = 61440 + 3 * 2 * 6144;   //  98304 B
    cudaFuncSetAttribute(k_mma<4>, cudaFuncAttributeMaxDynamicSharedMemorySize, SMEM4);
    cudaFuncSetAttribute(k_mma<2>, cudaFuncAttributeMaxDynamicSharedMemorySize, SMEM2);

    int tiles = (NN + 127) / 128;            // 391
    int warpNBlocks = (NN * 32 + 255) / 256;
    int packN = 256 * 400 + 8192 + 8192 + 4096;
    size_t NH = (size_t)NN * 64;

    // 1-4: detect+zero, convert+count, pack, layer-1 GEMM (profiled slot 4)
    k_detzero<<<(SEG + 255) / 256, 256>>>((const unsigned int*)eidx);
    k_convert<<<(EE + 255) / 256, 256>>>(eidx, etyp);
    k_pack_all<<<(packN + 255) / 256, 256>>>(W1, root1, W2, root2, W3, root3, ew1);
    k_mma<4><<<tiles, 512, SMEM4>>>(x, p_wt1, NN, FIN, 400,
                                    p_xr, p_xr + NH, p_xr + 2 * NH, p_bufa, b1);

    // 5-8: CSR build
    k_bsum<<<SCANB, 256>>>();
    k_bscan<<<1, 1024>>>();
    k_off<<<SCANB, 256>>>();
    k_scatter<<<(EE + 255) / 256, 256>>>();

    // 9: layer-1 aggregate + relu
    k_agg<<<warpNBlocks, 256>>>(p_xr, p_bufa);

    // 10-11: layer 2
    k_mma<4><<<tiles, 512, SMEM4>>>(p_bufa, p_wt2, NN, 64, 32,
                                    p_xr, p_xr + NH, p_xr + 2 * NH, p_bufb, b2);
    k_agg<<<warpNBlocks, 256>>>(p_xr, p_bufb);

    // 12-13: layer 3 + fused agg/LN/node-head (x3 -> p_bufb)
    k_mma<4><<<tiles, 512, SMEM4>>>(p_bufb, p_wt3, NN, 64, 32,
                                    p_xr, p_xr + NH, p_xr + 2 * NH, p_bufa, b3);
    k_agg_ln_node<<<warpNBlocks, 256>>>(p_xr, p_bufa, p_bufb, ln_g, ln_b,
                                        nw1, nb1, nw2, nb2, out);

    // 14-15: edge head
    k_mma<2><<<tiles, 512, SMEM2>>>(p_bufb, p_wte, NN, 64, 32,
                                    p_ea, p_eb, nullptr, nullptr, nullptr);
    k_edge<<<(EE * 16 + 255) / 256, 256>>>((const float4*)p_ea, (const float4*)p_eb,
                                           eb1, ew2, eb2, out);
}

// round 8
// speedup vs baseline: 3.6349x; 1.0892x over previous
#include <cuda_runtime.h>
#include <math.h>
#include <stdint.h>

#define NN 50000
#define EE 1600000
#define FIN 770
#define RR 3
#define SEG (RR * NN)               // 150000
#define SCANB ((SEG + 255) / 256)   // 586

// ---------------- scratch ------------------------------------------------------
__device__ uint32_t g_xr[(size_t)RR * NN * 32];   // bf16x2 rows (64 feat = 32 u32)
__device__ float    g_bufa[(size_t)NN * 64];
__device__ float    g_bufb[(size_t)NN * 64];
__device__ uint32_t g_ea[(size_t)NN * 32];        // bf16x2
__device__ uint32_t g_eb[(size_t)NN * 32];
__device__ float g_invc[SEG];
__device__ int   g_cnt[SEG];
__device__ int   g_off[SEG];
__device__ int   g_fill[SEG];
__device__ int   g_bsum[1024];
__device__ int   g_srcl[EE];
__device__ int   g_dstl[EE];
__device__ int   g_eidl[EE];
__device__ int   g_row[EE];
__device__ int   g_col[EE];
__device__ int   g_et[EE];
__device__ int   g_is64;
__device__ uint32_t g_wt1[256 * 400];   // bf16x2 pairs, [N][Kp/2]
__device__ uint32_t g_wt2[256 * 32];
__device__ uint32_t g_wt3[256 * 32];
__device__ uint32_t g_wte[128 * 32];

// ---------------- helpers ------------------------------------------------------
__device__ __forceinline__ uint32_t smem_u32(const void* p) {
    uint32_t a;
    asm("{ .reg .u64 t; cvta.to.shared.u64 t, %1; cvt.u32.u64 %0, t; }" : "=r"(a) : "l"(p));
    return a;
}
__device__ __forceinline__ void cp16(uint32_t dst, const void* src, int sz) {
    asm volatile("cp.async.cg.shared.global [%0], [%1], 16, %2;"
                 :: "r"(dst), "l"(src), "r"(sz) : "memory");
}
__device__ __forceinline__ void cp8(uint32_t dst, const void* src, int sz) {
    asm volatile("cp.async.ca.shared.global [%0], [%1], 8, %2;"
                 :: "r"(dst), "l"(src), "r"(sz) : "memory");
}
// pack two f32 -> bf16x2 (bits[15:0] = lo)
__device__ __forceinline__ uint32_t f2bf2(float lo, float hi) {
    uint32_t r;
    asm("cvt.rn.bf16x2.f32 %0, %1, %2;" : "=r"(r) : "f"(hi), "f"(lo));
    return r;
}
__device__ __forceinline__ float bflo(uint32_t v) { return __uint_as_float(v << 16); }
__device__ __forceinline__ float bfhi(uint32_t v) { return __uint_as_float(v & 0xFFFF0000u); }
__device__ __forceinline__ void mma16(float* c, const uint32_t* a, uint32_t b0, uint32_t b1) {
    asm volatile(
        "mma.sync.aligned.m16n8k16.row.col.f32.bf16.bf16.f32 "
        "{%0,%1,%2,%3}, {%4,%5,%6,%7}, {%8,%9}, {%0,%1,%2,%3};"
        : "+f"(c[0]), "+f"(c[1]), "+f"(c[2]), "+f"(c[3])
        : "r"(a[0]), "r"(a[1]), "r"(a[2]), "r"(a[3]), "r"(b0), "r"(b1));
}

// ---------------- launch 1: detect dtype + zero counters ------------------------
__global__ void k_detzero(const unsigned int* __restrict__ ei) {
    int i = blockIdx.x * blockDim.x + threadIdx.x;
    if (i < SEG) { g_cnt[i] = 0; g_fill[i] = 0; }
    if (i == 0) {
        int is64 = 1;
        for (int j = 0; j < 64; j++)
            if (ei[2 * j + 1] != 0u) { is64 = 0; break; }
        g_is64 = is64;
    }
}
// ---------------- launch 2: convert + degree count ------------------------------
__global__ void k_convert(const void* __restrict__ ei, const void* __restrict__ et) {
    int i = blockIdx.x * blockDim.x + threadIdx.x;
    if (i >= EE) return;
    int r, c, t;
    if (g_is64) {
        const long long* p = (const long long*)ei;
        r = (int)p[i];
        c = (int)p[EE + i];
        t = (int)((const long long*)et)[i];
    } else {
        const int* p = (const int*)ei;
        r = p[i];
        c = p[EE + i];
        t = ((const int*)et)[i];
    }
    g_row[i] = r; g_col[i] = c; g_et[i] = t;
    atomicAdd(&g_cnt[t * NN + c], 1);
}

// ---------------- launch 3: pack ALL weights to bf16x2 pairs --------------------
__global__ void k_pack_all(const float* __restrict__ W1, const float* __restrict__ root1,
                           const float* __restrict__ W2, const float* __restrict__ root2,
                           const float* __restrict__ W3, const float* __restrict__ root3,
                           const float* __restrict__ ew1) {
    int i = blockIdx.x * 256 + threadIdx.x;
    if (i < 256 * 400) {                                 // wt1  [256][400]
        int n = i / 400, s = i % 400;
        int jj = s & 7, k0 = (s >> 3) * 16 + (jj >> 1) * 2 + (jj & 1) * 8;
        float lo = 0.f, hi = 0.f;
        if (n < 192) {
            if (k0 < FIN)     lo = W1[(size_t)(n >> 6) * FIN * 64 + (size_t)k0 * 64 + (n & 63)];
            if (k0 + 1 < FIN) hi = W1[(size_t)(n >> 6) * FIN * 64 + (size_t)(k0 + 1) * 64 + (n & 63)];
        } else {
            if (k0 < FIN)     lo = root1[(size_t)k0 * 64 + (n - 192)];
            if (k0 + 1 < FIN) hi = root1[(size_t)(k0 + 1) * 64 + (n - 192)];
        }
        g_wt1[i] = f2bf2(lo, hi);
        return;
    }
    int j = i - 256 * 400;
    if (j < 8192) {                                      // wt2 [256][32]
        int n = j >> 5, s = j & 31;
        int jj = s & 7, k0 = (s >> 3) * 16 + (jj >> 1) * 2 + (jj & 1) * 8;
        float lo, hi;
        if (n < 192) {
            lo = W2[(n >> 6) * 4096 + k0 * 64 + (n & 63)];
            hi = W2[(n >> 6) * 4096 + (k0 + 1) * 64 + (n & 63)];
        } else {
            lo = root2[k0 * 64 + (n - 192)];
            hi = root2[(k0 + 1) * 64 + (n - 192)];
        }
        g_wt2[j] = f2bf2(lo, hi);
        return;
    }
    j -= 8192;
    if (j < 8192) {                                      // wt3
        int n = j >> 5, s = j & 31;
        int jj = s & 7, k0 = (s >> 3) * 16 + (jj >> 1) * 2 + (jj & 1) * 8;
        float lo, hi;
        if (n < 192) {
            lo = W3[(n >> 6) * 4096 + k0 * 64 + (n & 63)];
            hi = W3[(n >> 6) * 4096 + (k0 + 1) * 64 + (n & 63)];
        } else {
            lo = root3[k0 * 64 + (n - 192)];
            hi = root3[(k0 + 1) * 64 + (n - 192)];
        }
        g_wt3[j] = f2bf2(lo, hi);
        return;
    }
    j -= 8192;
    if (j < 4096) {                                      // wte [128][32]
        int n = j >> 5, s = j & 31;
        int jj = s & 7, k0 = (s >> 3) * 16 + (jj >> 1) * 2 + (jj & 1) * 8;
        float lo, hi;
        if (n < 64) { lo = ew1[k0 * 64 + n];        hi = ew1[(k0 + 1) * 64 + n]; }
        else        { lo = ew1[(64 + k0) * 64 + (n - 64)]; hi = ew1[(64 + k0 + 1) * 64 + (n - 64)]; }
        g_wte[j] = f2bf2(lo, hi);
    }
}

// ---------------- CSR build ------------------------------------------------------
__global__ void k_bsum() {
    __shared__ int sh[256];
    int i = blockIdx.x * 256 + threadIdx.x;
    sh[threadIdx.x] = (i < SEG) ? g_cnt[i] : 0;
    __syncthreads();
    for (int o = 128; o > 0; o >>= 1) {
        if (threadIdx.x < o) sh[threadIdx.x] += sh[threadIdx.x + o];
        __syncthreads();
    }
    if (threadIdx.x == 0) g_bsum[blockIdx.x] = sh[0];
}
__global__ void k_bscan() {
    __shared__ int sh[1024];
    int tid = threadIdx.x;
    int v = (tid < SCANB) ? g_bsum[tid] : 0;
    sh[tid] = v;
    __syncthreads();
    for (int o = 1; o < 1024; o <<= 1) {
        int t = (tid >= o) ? sh[tid - o] : 0;
        __syncthreads();
        sh[tid] += t;
        __syncthreads();
    }
    if (tid < SCANB) g_bsum[tid] = sh[tid] - v;
}
__global__ void k_off() {
    __shared__ int sh[256];
    int tid = threadIdx.x;
    int i = blockIdx.x * 256 + tid;
    int v = (i < SEG) ? g_cnt[i] : 0;
    sh[tid] = v;
    __syncthreads();
    for (int o = 1; o < 256; o <<= 1) {
        int t = (tid >= o) ? sh[tid - o] : 0;
        __syncthreads();
        sh[tid] += t;
        __syncthreads();
    }
    if (i < SEG) {
        g_off[i] = sh[tid] - v + g_bsum[blockIdx.x];
        g_invc[i] = 1.0f / (float)(v > 0 ? v : 1);
    }
}
__global__ void k_scatter() {
    int e = blockIdx.x * blockDim.x + threadIdx.x;
    if (e >= EE) return;
    int c = g_col[e];
    int idx = g_et[e] * NN + c;
    int pos = g_off[idx] + atomicAdd(&g_fill[idx], 1);
    g_srcl[pos] = g_row[e];
    g_dstl[pos] = c;
    g_eidl[pos] = e;
}

// ---------------- bf16 mma.sync GEMM: [M,K]f32 @ bf16[N,Kp]^T, N = NT*64 --------
// 512 threads / 16 warps; MT = NT/2 row-tiles of 16 per warp; 3-stage cp.async.
// Outputs wn < NT-1 (or o3fp==null): bf16x2 rows; wn == NT-1 with o3fp: fp32+bias.
template<int NT>
__device__ __forceinline__ void issue_chunk(const float* __restrict__ X,
                                            const uint32_t* __restrict__ Wt,
                                            int M, int K, int Kp2, int m0, int c, int buf,
                                            uint32_t sb) {
    int tid = threadIdx.x;
    int k0 = c * 32;
    uint32_t ab = sb + (uint32_t)buf * 20480u;
    uint32_t bb = sb + 61440u + (uint32_t)buf * (uint32_t)(NT * 6144);
#pragma unroll
    for (int i = 0; i < 4; i++) {
        int u = i * 512 + tid;               // 2048 units: 128 rows x 16 of 8B
        int row = u >> 4, j = u & 15;
        int kk = k0 + j * 2;
        int ok = ((m0 + row) < M) && (kk < K);
        const float* src = ok ? (X + (size_t)(m0 + row) * K + kk) : X;
        int sz = ok ? ((K - kk >= 2) ? 8 : 4) : 0;
        cp8(ab + row * 160 + j * 8, src, sz);
    }
#pragma unroll
    for (int i = 0; i < NT / 2; i++) {
        int u = i * 512 + tid;               // NT*64 rows x 4 units of 16B
        int row = u >> 2, j = u & 3;
        cp16(bb + row * 96 + j * 16, Wt + (size_t)row * Kp2 + c * 16 + j * 4, 16);
    }
    asm volatile("cp.async.commit_group;" ::: "memory");
}

template<int NT>
__global__ __launch_bounds__(512, 1) void k_mma(
    const float* __restrict__ X, const uint32_t* __restrict__ Wt,
    int M, int K, int Kp2,
    uint32_t* __restrict__ ob0, uint32_t* __restrict__ ob1,
    uint32_t* __restrict__ ob2, float* __restrict__ o3fp,
    const float* __restrict__ bias3)
{
    extern __shared__ float smf[];
    const uint32_t* smu = (const uint32_t*)smf;
    uint32_t sb = smem_u32(smf);
    const int MT = NT / 2;
    int tid = threadIdx.x, wid = tid >> 5, lane = tid & 31;
    int g = lane >> 2, tig = lane & 3;
    int wn = wid % NT, wm = wid / NT;
    int rowbase = wm * MT * 16;
    int m0 = blockIdx.x * 128;
    int NC = (K + 31) / 32;

    float acc[MT][8][4];
#pragma unroll
    for (int mt = 0; mt < MT; mt++)
#pragma unroll
        for (int nt = 0; nt < 8; nt++)
#pragma unroll
            for (int q = 0; q < 4; q++) acc[mt][nt][q] = 0.f;

    issue_chunk<NT>(X, Wt, M, K, Kp2, m0, 0, 0, sb);
    if (NC > 1) issue_chunk<NT>(X, Wt, M, K, Kp2, m0, 1, 1, sb);

    int buf = 0;
    for (int c = 0; c < NC; c++) {
        if (c + 2 < NC) {
            int b2 = buf + 2; if (b2 >= 3) b2 -= 3;
            issue_chunk<NT>(X, Wt, M, K, Kp2, m0, c + 2, b2, sb);
            asm volatile("cp.async.wait_group 2;" ::: "memory");
        } else if (c + 1 < NC) {
            asm volatile("cp.async.wait_group 1;" ::: "memory");
        } else {
            asm volatile("cp.async.wait_group 0;" ::: "memory");
        }
        __syncthreads();

        int af = buf * 5120;                       // float offset
        int bf = 15360 + buf * (NT * 1536);        // uint32 offset
#pragma unroll
        for (int st = 0; st < 2; st++) {
            uint32_t A[MT][4];
#pragma unroll
            for (int mt = 0; mt < MT; mt++) {
                int base = af + (rowbase + mt * 16 + g) * 40 + st * 16 + 2 * tig;
                float2 x0 = *(const float2*)&smf[base];
                float2 x1 = *(const float2*)&smf[base + 8 * 40];
                float2 x2 = *(const float2*)&smf[base + 8];
                float2 x3 = *(const float2*)&smf[base + 8 * 40 + 8];
                A[mt][0] = f2bf2(x0.x, x0.y);
                A[mt][1] = f2bf2(x1.x, x1.y);
                A[mt][2] = f2bf2(x2.x, x2.y);
                A[mt][3] = f2bf2(x3.x, x3.y);
            }
#pragma unroll
            for (int nt = 0; nt < 8; nt++) {
                int nb = bf + (wn * 64 + nt * 8 + g) * 24 + st * 8 + tig * 2;
                uint2 bv = *(const uint2*)&smu[nb];
#pragma unroll
                for (int mt = 0; mt < MT; mt++)
                    mma16(acc[mt][nt], A[mt], bv.x, bv.y);
            }
        }
        __syncthreads();
        buf = (buf + 1 == 3) ? 0 : buf + 1;
    }

    bool fp = (wn == NT - 1) && (o3fp != nullptr);
    uint32_t* ob = (wn == 0) ? ob0 : ((wn == 1) ? ob1 : ob2);
#pragma unroll
    for (int mt = 0; mt < MT; mt++) {
        int mA = m0 + rowbase + mt * 16 + g;
        int mB = mA + 8;
#pragma unroll
        for (int nt = 0; nt < 8; nt++) {
            int col = nt * 8 + tig * 2;
            float c0 = acc[mt][nt][0], c1 = acc[mt][nt][1];
            float c2 = acc[mt][nt][2], c3 = acc[mt][nt][3];
            if (fp) {
                float bb0 = bias3[col], bb1 = bias3[col + 1];
                c0 += bb0; c1 += bb1; c2 += bb0; c3 += bb1;
                if (mA < M) *(float2*)(o3fp + (size_t)mA * 64 + col) = make_float2(c0, c1);
                if (mB < M) *(float2*)(o3fp + (size_t)mB * 64 + col) = make_float2(c2, c3);
            } else {
                if (mA < M) ob[(size_t)mA * 32 + (col >> 1)] = f2bf2(c0, c1);
                if (mB < M) ob[(size_t)mB * 32 + (col >> 1)] = f2bf2(c2, c3);
            }
        }
    }
}

// ---------------- CSR aggregation core: bf16 gathers (feat 2l, 2l+1) ------------
__device__ __forceinline__ void agg_core(const uint32_t* __restrict__ xr, int w, int lane,
                                         float& a0, float& a1) {
#pragma unroll
    for (int r = 0; r < RR; r++) {
        int idx = r * NN + w;
        int beg = g_off[idx], n = g_cnt[idx];
        const uint32_t* xrr = xr + (size_t)r * NN * 32;
        float s0 = 0.f, s1 = 0.f;
        for (int b = 0; b < n; b += 32) {
            int src = (b + lane < n) ? g_srcl[beg + b + lane] : 0;
            int m = min(32, n - b);
            int j = 0;
            for (; j + 8 <= m; j += 8) {
                uint32_t v[8];
#pragma unroll
                for (int q = 0; q < 8; q++)
                    v[q] = xrr[(size_t)__shfl_sync(~0u, src, j + q) * 32 + lane];
                float t0 = 0.f, t1 = 0.f;
#pragma unroll
                for (int q = 0; q < 8; q++) {
                    t0 += bflo(v[q]);
                    t1 += bfhi(v[q]);
                }
                s0 += t0; s1 += t1;
            }
            for (; j + 4 <= m; j += 4) {
                uint32_t v[4];
#pragma unroll
                for (int q = 0; q < 4; q++)
                    v[q] = xrr[(size_t)__shfl_sync(~0u, src, j + q) * 32 + lane];
#pragma unroll
                for (int q = 0; q < 4; q++) {
                    s0 += bflo(v[q]);
                    s1 += bfhi(v[q]);
                }
            }
            for (; j < m; j++) {
                uint32_t v = xrr[(size_t)__shfl_sync(~0u, src, j) * 32 + lane];
                s0 += bflo(v);
                s1 += bfhi(v);
            }
        }
        float ic = g_invc[idx];
        a0 += s0 * ic;
        a1 += s1 * ic;
    }
}

__global__ void k_agg(const uint32_t* __restrict__ xr, float* __restrict__ io) {
    int w = (blockIdx.x * blockDim.x + threadIdx.x) >> 5;
    int lane = threadIdx.x & 31;
    if (w >= NN) return;
    float a0 = 0.f, a1 = 0.f;
    agg_core(xr, w, lane, a0, a1);
    float2 cur = *(const float2*)&io[(size_t)w * 64 + 2 * lane];
    cur.x = fmaxf(cur.x + a0, 0.f);
    cur.y = fmaxf(cur.y + a1, 0.f);
    *(float2*)&io[(size_t)w * 64 + 2 * lane] = cur;
}

// ---------------- fused: agg(layer3) + LayerNorm + node head --------------------
__global__ void k_agg_ln_node(const uint32_t* __restrict__ xr, const float* __restrict__ io,
                              float* __restrict__ x3out,
                              const float* __restrict__ gg, const float* __restrict__ bb,
                              const float* __restrict__ nw1, const float* __restrict__ nb1,
                              const float* __restrict__ nw2, const float* __restrict__ nb2,
                              float* __restrict__ outp) {
    __shared__ float s_w1[64 * 32];
    __shared__ float s_b1[32], s_w2[64], s_b2[2], s_g[64], s_bb[64];
    int tid = threadIdx.x;
    for (int i = tid; i < 2048; i += blockDim.x) s_w1[i] = nw1[i];
    if (tid < 32) s_b1[tid] = nb1[tid];
    if (tid < 64) { s_w2[tid] = nw2[tid]; s_g[tid] = gg[tid]; s_bb[tid] = bb[tid]; }
    if (tid < 2)  s_b2[tid] = nb2[tid];
    __syncthreads();

    int w = (blockIdx.x * blockDim.x + tid) >> 5;
    int lane = tid & 31;
    if (w >= NN) return;
    float a0 = 0.f, a1 = 0.f;
    agg_core(xr, w, lane, a0, a1);
    float2 cur = *(const float2*)&io[(size_t)w * 64 + 2 * lane];
    float v0 = cur.x + a0;
    float v1 = cur.y + a1;

    float s = v0 + v1;
#pragma unroll
    for (int off = 16; off; off >>= 1) s += __shfl_xor_sync(~0u, s, off);
    float mu = s * (1.f / 64.f);
    float d0 = v0 - mu, d1 = v1 - mu;
    float q = d0 * d0 + d1 * d1;
#pragma unroll
    for (int off = 16; off; off >>= 1) q += __shfl_xor_sync(~0u, q, off);
    float rs = rsqrtf(q * (1.f / 64.f) + 1e-5f);
    float xa = d0 * rs * s_g[2 * lane]     + s_bb[2 * lane];       // feat 2*lane
    float xb = d1 * rs * s_g[2 * lane + 1] + s_bb[2 * lane + 1];   // feat 2*lane+1
    *(float2*)&x3out[(size_t)w * 64 + 2 * lane] = make_float2(xa, xb);

    float acc = s_b1[lane];
#pragma unroll
    for (int k = 0; k < 32; k++) {
        float x0 = __shfl_sync(~0u, xa, k);   // feat 2k
        float x1 = __shfl_sync(~0u, xb, k);   // feat 2k+1
        acc += x0 * s_w1[(2 * k) * 32 + lane] + x1 * s_w1[(2 * k + 1) * 32 + lane];
    }
    float nh = fmaxf(acc, 0.f);
    float p0 = nh * s_w2[lane * 2 + 0];
    float p1 = nh * s_w2[lane * 2 + 1];
#pragma unroll
    for (int off = 16; off; off >>= 1) {
        p0 += __shfl_xor_sync(~0u, p0, off);
        p1 += __shfl_xor_sync(~0u, p1, off);
    }
    if (lane == 0) {
        float l0 = p0 + s_b2[0], l1 = p1 + s_b2[1];
        float mx = fmaxf(l0, l1);
        float lse = __logf(__expf(l0 - mx) + __expf(l1 - mx)) + mx;
        outp[(size_t)3 * EE + (size_t)w * 2 + 0] = l0 - lse;
        outp[(size_t)3 * EE + (size_t)w * 2 + 1] = l1 - lse;
    }
}

// ---------------- edge classifier, CSR order, bf16 gathers ----------------------
__global__ void k_edge(const uint2* __restrict__ ea2, const uint2* __restrict__ eb2v,
                       const float* __restrict__ eb1, const float* __restrict__ ew2,
                       const float* __restrict__ eb2, float* __restrict__ outp) {
    __shared__ float s_b1[64], s_w2[192], s_b2[3];
    int tid = threadIdx.x;
    if (tid < 64)  s_b1[tid] = eb1[tid];
    if (tid < 192) s_w2[tid] = ew2[tid];
    if (tid < 3)   s_b2[tid] = eb2[tid];
    __syncthreads();

    int gid = blockIdx.x * blockDim.x + tid;
    int p = gid >> 4, sub = tid & 15;
    if (p >= EE) return;
    int r  = g_srcl[p];
    int c  = g_dstl[p];
    int id = g_eidl[p];
    uint2 va = ea2[(size_t)r * 16 + sub];    // feats 4sub..4sub+3
    uint2 vb = eb2v[(size_t)c * 16 + sub];
    float h[4];
    h[0] = fmaxf(bflo(va.x) + bflo(vb.x) + s_b1[sub * 4 + 0], 0.f);
    h[1] = fmaxf(bfhi(va.x) + bfhi(vb.x) + s_b1[sub * 4 + 1], 0.f);
    h[2] = fmaxf(bflo(va.y) + bflo(vb.y) + s_b1[sub * 4 + 2], 0.f);
    h[3] = fmaxf(bfhi(va.y) + bfhi(vb.y) + s_b1[sub * 4 + 3], 0.f);
    float p0 = 0.f, p1 = 0.f, p2 = 0.f;
#pragma unroll
    for (int i = 0; i < 4; i++) {
        int f = sub * 4 + i;
        p0 += h[i] * s_w2[f * 3 + 0];
        p1 += h[i] * s_w2[f * 3 + 1];
        p2 += h[i] * s_w2[f * 3 + 2];
    }
#pragma unroll
    for (int off = 8; off; off >>= 1) {
        p0 += __shfl_xor_sync(~0u, p0, off);
        p1 += __shfl_xor_sync(~0u, p1, off);
        p2 += __shfl_xor_sync(~0u, p2, off);
    }
    if (sub == 0) {
        float l0 = p0 + s_b2[0], l1 = p1 + s_b2[1], l2 = p2 + s_b2[2];
        float mx = fmaxf(l0, fmaxf(l1, l2));
        float lse = __logf(__expf(l0 - mx) + __expf(l1 - mx) + __expf(l2 - mx)) + mx;
        outp[(size_t)id * 3 + 0] = l0 - lse;
        outp[(size_t)id * 3 + 1] = l1 - lse;
        outp[(size_t)id * 3 + 2] = l2 - lse;
    }
}

// ---------------- host orchestration -------------------------------------------
extern "C" void kernel_launch(void* const* d_in, const int* in_sizes, int n_in,
                              void* d_out, int out_size) {
    const float* x     = (const float*)d_in[0];
    const void*  eidx  = d_in[1];
    const void*  etyp  = d_in[2];
    const float* W1    = (const float*)d_in[3];
    const float* root1 = (const float*)d_in[4];
    const float* b1    = (const float*)d_in[5];
    const float* W2    = (const float*)d_in[6];
    const float* root2 = (const float*)d_in[7];
    const float* b2    = (const float*)d_in[8];
    const float* W3    = (const float*)d_in[9];
    const float* root3 = (const float*)d_in[10];
    const float* b3    = (const float*)d_in[11];
    const float* ln_g  = (const float*)d_in[12];
    const float* ln_b  = (const float*)d_in[13];
    const float* ew1   = (const float*)d_in[14];
    const float* eb1   = (const float*)d_in[15];
    const float* ew2   = (const float*)d_in[16];
    const float* eb2   = (const float*)d_in[17];
    const float* nw1   = (const float*)d_in[18];
    const float* nb1   = (const float*)d_in[19];
    const float* nw2   = (const float*)d_in[20];
    const float* nb2   = (const float*)d_in[21];
    float* out = (float*)d_out;

    float *p_bufa, *p_bufb;
    uint32_t *p_xr, *p_ea, *p_eb, *p_wt1, *p_wt2, *p_wt3, *p_wte;
    cudaGetSymbolAddress((void**)&p_xr,   g_xr);
    cudaGetSymbolAddress((void**)&p_bufa, g_bufa);
    cudaGetSymbolAddress((void**)&p_bufb, g_bufb);
    cudaGetSymbolAddress((void**)&p_ea,   g_ea);
    cudaGetSymbolAddress((void**)&p_eb,   g_eb);
    cudaGetSymbolAddress((void**)&p_wt1,  g_wt1);
    cudaGetSymbolAddress((void**)&p_wt2,  g_wt2);
    cudaGetSymbolAddress((void**)&p_wt3,  g_wt3);
    cudaGetSymbolAddress((void**)&p_wte,  g_wte);

    const int SMEM4 = 61440 + 3 * 4 * 6144;   // 135168 B
    const int SMEM2 = 61440 + 3 * 2 * 6144;   //  98304 B
    cudaFuncSetAttribute(k_mma<4>, cudaFuncAttributeMaxDynamicSharedMemorySize, SMEM4);
    cudaFuncSetAttribute(k_mma<2>, cudaFuncAttributeMaxDynamicSharedMemorySize, SMEM2);

    int tiles = (NN + 127) / 128;            // 391
    int warpNBlocks = (NN * 32 + 255) / 256;
    int packN = 256 * 400 + 8192 + 8192 + 4096;
    size_t NH32 = (size_t)NN * 32;

    // 1-4: detect+zero, convert+count, pack, layer-1 GEMM (profiled slot 4)
    k_detzero<<<(SEG + 255) / 256, 256>>>((const unsigned int*)eidx);
    k_convert<<<(EE + 255) / 256, 256>>>(eidx, etyp);
    k_pack_all<<<(packN + 255) / 256, 256>>>(W1, root1, W2, root2, W3, root3, ew1);
    k_mma<4><<<tiles, 512, SMEM4>>>(x, p_wt1, NN, FIN, 400,
                                    p_xr, p_xr + NH32, p_xr + 2 * NH32, p_bufa, b1);

    // 5-8: CSR build
    k_bsum<<<SCANB, 256>>>();
    k_bscan<<<1, 1024>>>();
    k_off<<<SCANB, 256>>>();
    k_scatter<<<(EE + 255) / 256, 256>>>();

    // 9: layer-1 aggregate + relu
    k_agg<<<warpNBlocks, 256>>>(p_xr, p_bufa);

    // 10-11: layer 2
    k_mma<4><<<tiles, 512, SMEM4>>>(p_bufa, p_wt2, NN, 64, 32,
                                    p_xr, p_xr + NH32, p_xr + 2 * NH32, p_bufb, b2);
    k_agg<<<warpNBlocks, 256>>>(p_xr, p_bufb);

    // 12-13: layer 3 + fused agg/LN/node-head (x3 -> p_bufa)
    k_mma<4><<<tiles, 512, SMEM4>>>(p_bufb, p_wt3, NN, 64, 32,
                                    p_xr, p_xr + NH32, p_xr + 2 * NH32, p_bufa, b3);
    k_agg_ln_node<<<warpNBlocks, 256>>>(p_xr, p_bufa, p_bufb, ln_g, ln_b,
                                        nw1, nb1, nw2, nb2, out);

    // 14-15: edge head (A = x3 fp32 in p_bufb; outputs bf16)
    k_mma<2><<<tiles, 512, SMEM2>>>(p_bufb, p_wte, NN, 64, 32,
                                    p_ea, p_eb, nullptr, nullptr, nullptr);
    k_edge<<<(EE * 16 + 255) / 256, 256>>>((const uint2*)p_ea, (const uint2*)p_eb,
                                           eb1, ew2, eb2, out);
}

// round 9
// speedup vs baseline: 3.6446x; 1.0027x over previous
#include <cuda_runtime.h>
#include <math.h>
#include <stdint.h>

#define NN 50000
#define EE 1600000
#define FIN 770
#define RR 3
#define SEG (RR * NN)               // 150000
#define SCANB ((SEG + 255) / 256)   // 586

// ---------------- scratch ------------------------------------------------------
__device__ uint32_t g_xr[(size_t)RR * NN * 32];   // bf16x2 rows (64 feat = 32 u32)
__device__ float    g_bufa[(size_t)NN * 64];      // fp32 root results
__device__ float    g_bufb[(size_t)NN * 64];
__device__ uint32_t g_hb[(size_t)NN * 32];        // bf16x2 activations (h1/h2/x3)
__device__ uint32_t g_ea[(size_t)NN * 32];        // bf16x2
__device__ uint32_t g_eb[(size_t)NN * 32];
__device__ float g_invc[SEG];
__device__ int   g_cnt[SEG];
__device__ int   g_off[SEG];
__device__ int   g_fill[SEG];
__device__ int   g_bsum[1024];
__device__ int   g_srcl[EE];
__device__ int   g_dstl[EE];
__device__ int   g_eidl[EE];
__device__ int   g_row[EE];
__device__ int   g_col[EE];
__device__ int   g_et[EE];
__device__ int   g_is64;
__device__ uint32_t g_wt1[256 * 400];   // bf16x2 pairs, [N][Kp2]
__device__ uint32_t g_wt2[256 * 32];
__device__ uint32_t g_wt3[256 * 32];
__device__ uint32_t g_wte[128 * 32];

// ---------------- helpers ------------------------------------------------------
__device__ __forceinline__ uint32_t smem_u32(const void* p) {
    uint32_t a;
    asm("{ .reg .u64 t; cvta.to.shared.u64 t, %1; cvt.u32.u64 %0, t; }" : "=r"(a) : "l"(p));
    return a;
}
__device__ __forceinline__ void cp16(uint32_t dst, const void* src, int sz) {
    asm volatile("cp.async.cg.shared.global [%0], [%1], 16, %2;"
                 :: "r"(dst), "l"(src), "r"(sz) : "memory");
}
__device__ __forceinline__ void cp8(uint32_t dst, const void* src, int sz) {
    asm volatile("cp.async.ca.shared.global [%0], [%1], 8, %2;"
                 :: "r"(dst), "l"(src), "r"(sz) : "memory");
}
__device__ __forceinline__ uint32_t f2bf2(float lo, float hi) {
    uint32_t r;
    asm("cvt.rn.bf16x2.f32 %0, %1, %2;" : "=r"(r) : "f"(hi), "f"(lo));
    return r;
}
__device__ __forceinline__ float bflo(uint32_t v) { return __uint_as_float(v << 16); }
__device__ __forceinline__ float bfhi(uint32_t v) { return __uint_as_float(v & 0xFFFF0000u); }
__device__ __forceinline__ void mma16(float* c, const uint32_t* a, uint32_t b0, uint32_t b1) {
    asm volatile(
        "mma.sync.aligned.m16n8k16.row.col.f32.bf16.bf16.f32 "
        "{%0,%1,%2,%3}, {%4,%5,%6,%7}, {%8,%9}, {%0,%1,%2,%3};"
        : "+f"(c[0]), "+f"(c[1]), "+f"(c[2]), "+f"(c[3])
        : "r"(a[0]), "r"(a[1]), "r"(a[2]), "r"(a[3]), "r"(b0), "r"(b1));
}

// ---------------- launch 1: fused detect+zero + weight pack ---------------------
__global__ void k_init(const unsigned int* __restrict__ ei,
                       const float* __restrict__ W1, const float* __restrict__ root1,
                       const float* __restrict__ W2, const float* __restrict__ root2,
                       const float* __restrict__ W3, const float* __restrict__ root3,
                       const float* __restrict__ ew1) {
    int b = blockIdx.x;
    if (b < SCANB) {
        int i = b * 256 + threadIdx.x;
        if (i < SEG) { g_cnt[i] = 0; g_fill[i] = 0; }
        if (i == 0) {
            int is64 = 1;
            for (int j = 0; j < 64; j++)
                if (ei[2 * j + 1] != 0u) { is64 = 0; break; }
            g_is64 = is64;
        }
        return;
    }
    int i = (b - SCANB) * 256 + threadIdx.x;
    if (i < 256 * 400) {                                 // wt1  [256][400]
        int n = i / 400, s = i % 400;
        int jj = s & 7, k0 = (s >> 3) * 16 + (jj >> 1) * 2 + (jj & 1) * 8;
        float lo = 0.f, hi = 0.f;
        if (n < 192) {
            if (k0 < FIN)     lo = W1[(size_t)(n >> 6) * FIN * 64 + (size_t)k0 * 64 + (n & 63)];
            if (k0 + 1 < FIN) hi = W1[(size_t)(n >> 6) * FIN * 64 + (size_t)(k0 + 1) * 64 + (n & 63)];
        } else {
            if (k0 < FIN)     lo = root1[(size_t)k0 * 64 + (n - 192)];
            if (k0 + 1 < FIN) hi = root1[(size_t)(k0 + 1) * 64 + (n - 192)];
        }
        g_wt1[i] = f2bf2(lo, hi);
        return;
    }
    int j = i - 256 * 400;
    if (j < 8192) {                                      // wt2 [256][32]
        int n = j >> 5, s = j & 31;
        int jj = s & 7, k0 = (s >> 3) * 16 + (jj >> 1) * 2 + (jj & 1) * 8;
        float lo, hi;
        if (n < 192) {
            lo = W2[(n >> 6) * 4096 + k0 * 64 + (n & 63)];
            hi = W2[(n >> 6) * 4096 + (k0 + 1) * 64 + (n & 63)];
        } else {
            lo = root2[k0 * 64 + (n - 192)];
            hi = root2[(k0 + 1) * 64 + (n - 192)];
        }
        g_wt2[j] = f2bf2(lo, hi);
        return;
    }
    j -= 8192;
    if (j < 8192) {                                      // wt3
        int n = j >> 5, s = j & 31;
        int jj = s & 7, k0 = (s >> 3) * 16 + (jj >> 1) * 2 + (jj & 1) * 8;
        float lo, hi;
        if (n < 192) {
            lo = W3[(n >> 6) * 4096 + k0 * 64 + (n & 63)];
            hi = W3[(n >> 6) * 4096 + (k0 + 1) * 64 + (n & 63)];
        } else {
            lo = root3[k0 * 64 + (n - 192)];
            hi = root3[(k0 + 1) * 64 + (n - 192)];
        }
        g_wt3[j] = f2bf2(lo, hi);
        return;
    }
    j -= 8192;
    if (j < 4096) {                                      // wte [128][32]
        int n = j >> 5, s = j & 31;
        int jj = s & 7, k0 = (s >> 3) * 16 + (jj >> 1) * 2 + (jj & 1) * 8;
        float lo, hi;
        if (n < 64) { lo = ew1[k0 * 64 + n];               hi = ew1[(k0 + 1) * 64 + n]; }
        else        { lo = ew1[(64 + k0) * 64 + (n - 64)]; hi = ew1[(64 + k0 + 1) * 64 + (n - 64)]; }
        g_wte[j] = f2bf2(lo, hi);
    }
}

// ---------------- launch 2: convert + degree count ------------------------------
__global__ void k_convert(const void* __restrict__ ei, const void* __restrict__ et) {
    int i = blockIdx.x * blockDim.x + threadIdx.x;
    if (i >= EE) return;
    int r, c, t;
    if (g_is64) {
        const long long* p = (const long long*)ei;
        r = (int)p[i];
        c = (int)p[EE + i];
        t = (int)((const long long*)et)[i];
    } else {
        const int* p = (const int*)ei;
        r = p[i];
        c = p[EE + i];
        t = ((const int*)et)[i];
    }
    g_row[i] = r; g_col[i] = c; g_et[i] = t;
    atomicAdd(&g_cnt[t * NN + c], 1);
}

// ---------------- CSR build ------------------------------------------------------
__global__ void k_bsum() {
    __shared__ int sh[256];
    int i = blockIdx.x * 256 + threadIdx.x;
    sh[threadIdx.x] = (i < SEG) ? g_cnt[i] : 0;
    __syncthreads();
    for (int o = 128; o > 0; o >>= 1) {
        if (threadIdx.x < o) sh[threadIdx.x] += sh[threadIdx.x + o];
        __syncthreads();
    }
    if (threadIdx.x == 0) g_bsum[blockIdx.x] = sh[0];
}
__global__ void k_bscan() {
    __shared__ int sh[1024];
    int tid = threadIdx.x;
    int v = (tid < SCANB) ? g_bsum[tid] : 0;
    sh[tid] = v;
    __syncthreads();
    for (int o = 1; o < 1024; o <<= 1) {
        int t = (tid >= o) ? sh[tid - o] : 0;
        __syncthreads();
        sh[tid] += t;
        __syncthreads();
    }
    if (tid < SCANB) g_bsum[tid] = sh[tid] - v;
}
__global__ void k_off() {
    __shared__ int sh[256];
    int tid = threadIdx.x;
    int i = blockIdx.x * 256 + tid;
    int v = (i < SEG) ? g_cnt[i] : 0;
    sh[tid] = v;
    __syncthreads();
    for (int o = 1; o < 256; o <<= 1) {
        int t = (tid >= o) ? sh[tid - o] : 0;
        __syncthreads();
        sh[tid] += t;
        __syncthreads();
    }
    if (i < SEG) {
        g_off[i] = sh[tid] - v + g_bsum[blockIdx.x];
        g_invc[i] = 1.0f / (float)(v > 0 ? v : 1);
    }
}
__global__ void k_scatter() {
    int e = blockIdx.x * blockDim.x + threadIdx.x;
    if (e >= EE) return;
    int c = g_col[e];
    int idx = g_et[e] * NN + c;
    int pos = g_off[idx] + atomicAdd(&g_fill[idx], 1);
    g_srcl[pos] = g_row[e];
    g_dstl[pos] = c;
    g_eidl[pos] = e;
}

// ---------------- GEMM: A (fp32 or bf16x2) @ bf16[N,Kp]^T, N = NT*64 ------------
// 512 threads / 16 warps; MT = NT/2 row-tiles of 16 per warp; 3-stage cp.async.
// ABF=0: A fp32, smem rows 160B stride. ABF=1: A bf16x2, smem rows 80B, ldmatrix.
template<int NT, int ABF>
__device__ __forceinline__ void issue_chunk(const void* __restrict__ X,
                                            const uint32_t* __restrict__ Wt,
                                            int M, int K, int Kp2, int m0, int c, int buf,
                                            uint32_t sb) {
    int tid = threadIdx.x;
    uint32_t bb = sb + (ABF ? 30720u : 61440u) + (uint32_t)buf * (uint32_t)(NT * 6144);
    if (ABF) {
        uint32_t ab = sb + (uint32_t)buf * 10240u;
        int row = tid >> 2, j = tid & 3;          // 512 units: 128 rows x 4 of 16B
        int ok = (m0 + row) < M;
        const uint32_t* src = (const uint32_t*)X + (size_t)(m0 + row) * Kp2 + c * 16 + j * 4;
        cp16(ab + row * 80 + j * 16, ok ? (const void*)src : X, ok ? 16 : 0);
    } else {
        uint32_t ab = sb + (uint32_t)buf * 20480u;
        int k0 = c * 32;
#pragma unroll
        for (int i = 0; i < 4; i++) {
            int u = i * 512 + tid;                // 2048 units: 128 rows x 16 of 8B
            int row = u >> 4, j = u & 15;
            int kk = k0 + j * 2;
            int ok = ((m0 + row) < M) && (kk < K);
            const float* src = ok ? ((const float*)X + (size_t)(m0 + row) * K + kk)
                                  : (const float*)X;
            int sz = ok ? ((K - kk >= 2) ? 8 : 4) : 0;
            cp8(ab + row * 160 + j * 8, src, sz);
        }
    }
#pragma unroll
    for (int i = 0; i < NT / 2; i++) {
        int u = i * 512 + tid;                    // NT*64 rows x 4 units of 16B
        int row = u >> 2, j = u & 3;
        cp16(bb + row * 96 + j * 16, Wt + (size_t)row * Kp2 + c * 16 + j * 4, 16);
    }
    asm volatile("cp.async.commit_group;" ::: "memory");
}

template<int NT, int ABF>
__global__ __launch_bounds__(512, 1) void k_mma(
    const void* __restrict__ X, const uint32_t* __restrict__ Wt,
    int M, int K, int Kp2,
    uint32_t* __restrict__ ob0, uint32_t* __restrict__ ob1,
    uint32_t* __restrict__ ob2, float* __restrict__ o3fp,
    const float* __restrict__ bias3)
{
    extern __shared__ float smf[];
    const uint32_t* smu = (const uint32_t*)smf;
    uint32_t sb = smem_u32(smf);
    const int MT = NT / 2;
    int tid = threadIdx.x, wid = tid >> 5, lane = tid & 31;
    int g = lane >> 2, tig = lane & 3;
    int wn = wid % NT, wm = wid / NT;
    int rowbase = wm * MT * 16;
    int m0 = blockIdx.x * 128;
    int NC = (K + 31) / 32;

    float acc[MT][8][4];
#pragma unroll
    for (int mt = 0; mt < MT; mt++)
#pragma unroll
        for (int nt = 0; nt < 8; nt++)
#pragma unroll
            for (int q = 0; q < 4; q++) acc[mt][nt][q] = 0.f;

    issue_chunk<NT, ABF>(X, Wt, M, K, Kp2, m0, 0, 0, sb);
    if (NC > 1) issue_chunk<NT, ABF>(X, Wt, M, K, Kp2, m0, 1, 1, sb);

    int buf = 0;
    for (int c = 0; c < NC; c++) {
        if (c + 2 < NC) {
            int b2 = buf + 2; if (b2 >= 3) b2 -= 3;
            issue_chunk<NT, ABF>(X, Wt, M, K, Kp2, m0, c + 2, b2, sb);
            asm volatile("cp.async.wait_group 2;" ::: "memory");
        } else if (c + 1 < NC) {
            asm volatile("cp.async.wait_group 1;" ::: "memory");
        } else {
            asm volatile("cp.async.wait_group 0;" ::: "memory");
        }
        __syncthreads();

        int bf = (ABF ? 7680 : 15360) + buf * (NT * 1536);   // u32 index
#pragma unroll
        for (int st = 0; st < 2; st++) {
            uint32_t A[MT][4];
#pragma unroll
            for (int mt = 0; mt < MT; mt++) {
                if (ABF) {
                    uint32_t addr = sb + (uint32_t)buf * 10240u
                        + (uint32_t)((rowbase + mt * 16 + (lane & 15)) * 80
                                     + (lane >> 4) * 16 + st * 32);
                    asm volatile(
                        "ldmatrix.sync.aligned.m8n8.x4.shared.b16 {%0,%1,%2,%3}, [%4];"
                        : "=r"(A[mt][0]), "=r"(A[mt][1]), "=r"(A[mt][2]), "=r"(A[mt][3])
                        : "r"(addr));
                } else {
                    int af = buf * 5120;
                    int base = af + (rowbase + mt * 16 + g) * 40 + st * 16 + 2 * tig;
                    float2 x0 = *(const float2*)&smf[base];
                    float2 x1 = *(const float2*)&smf[base + 8 * 40];
                    float2 x2 = *(const float2*)&smf[base + 8];
                    float2 x3 = *(const float2*)&smf[base + 8 * 40 + 8];
                    A[mt][0] = f2bf2(x0.x, x0.y);
                    A[mt][1] = f2bf2(x1.x, x1.y);
                    A[mt][2] = f2bf2(x2.x, x2.y);
                    A[mt][3] = f2bf2(x3.x, x3.y);
                }
            }
#pragma unroll
            for (int nt = 0; nt < 8; nt++) {
                int nb = bf + (wn * 64 + nt * 8 + g) * 24 + st * 8 + tig * 2;
                uint2 bv = *(const uint2*)&smu[nb];
#pragma unroll
                for (int mt = 0; mt < MT; mt++)
                    mma16(acc[mt][nt], A[mt], bv.x, bv.y);
            }
        }
        __syncthreads();
        buf = (buf + 1 == 3) ? 0 : buf + 1;
    }

    bool fp = (wn == NT - 1) && (o3fp != nullptr);
    uint32_t* ob = (wn == 0) ? ob0 : ((wn == 1) ? ob1 : ob2);
#pragma unroll
    for (int mt = 0; mt < MT; mt++) {
        int mA = m0 + rowbase + mt * 16 + g;
        int mB = mA + 8;
#pragma unroll
        for (int nt = 0; nt < 8; nt++) {
            int col = nt * 8 + tig * 2;
            float c0 = acc[mt][nt][0], c1 = acc[mt][nt][1];
            float c2 = acc[mt][nt][2], c3 = acc[mt][nt][3];
            if (fp) {
                float bb0 = bias3[col], bb1 = bias3[col + 1];
                c0 += bb0; c1 += bb1; c2 += bb0; c3 += bb1;
                if (mA < M) *(float2*)(o3fp + (size_t)mA * 64 + col) = make_float2(c0, c1);
                if (mB < M) *(float2*)(o3fp + (size_t)mB * 64 + col) = make_float2(c2, c3);
            } else {
                if (mA < M) ob[(size_t)mA * 32 + (col >> 1)] = f2bf2(c0, c1);
                if (mB < M) ob[(size_t)mB * 32 + (col >> 1)] = f2bf2(c2, c3);
            }
        }
    }
}

// ---------------- CSR aggregation core: bf16 gathers (feat 2l, 2l+1) ------------
__device__ __forceinline__ void agg_core(const uint32_t* __restrict__ xr, int w, int lane,
                                         float& a0, float& a1) {
#pragma unroll
    for (int r = 0; r < RR; r++) {
        int idx = r * NN + w;
        int beg = g_off[idx], n = g_cnt[idx];
        const uint32_t* xrr = xr + (size_t)r * NN * 32;
        float s0 = 0.f, s1 = 0.f;
        for (int b = 0; b < n; b += 32) {
            int src = (b + lane < n) ? g_srcl[beg + b + lane] : 0;
            int m = min(32, n - b);
            int j = 0;
            for (; j + 8 <= m; j += 8) {
                uint32_t v[8];
#pragma unroll
                for (int q = 0; q < 8; q++)
                    v[q] = xrr[(size_t)__shfl_sync(~0u, src, j + q) * 32 + lane];
                float t0 = 0.f, t1 = 0.f;
#pragma unroll
                for (int q = 0; q < 8; q++) {
                    t0 += bflo(v[q]);
                    t1 += bfhi(v[q]);
                }
                s0 += t0; s1 += t1;
            }
            for (; j + 4 <= m; j += 4) {
                uint32_t v[4];
#pragma unroll
                for (int q = 0; q < 4; q++)
                    v[q] = xrr[(size_t)__shfl_sync(~0u, src, j + q) * 32 + lane];
#pragma unroll
                for (int q = 0; q < 4; q++) {
                    s0 += bflo(v[q]);
                    s1 += bfhi(v[q]);
                }
            }
            for (; j < m; j++) {
                uint32_t v = xrr[(size_t)__shfl_sync(~0u, src, j) * 32 + lane];
                s0 += bflo(v);
                s1 += bfhi(v);
            }
        }
        float ic = g_invc[idx];
        a0 += s0 * ic;
        a1 += s1 * ic;
    }
}

// agg + relu -> bf16x2 activation buffer
__global__ void k_agg(const uint32_t* __restrict__ xr, const float* __restrict__ io,
                      uint32_t* __restrict__ outb) {
    int w = (blockIdx.x * blockDim.x + threadIdx.x) >> 5;
    int lane = threadIdx.x & 31;
    if (w >= NN) return;
    float a0 = 0.f, a1 = 0.f;
    agg_core(xr, w, lane, a0, a1);
    float2 cur = *(const float2*)&io[(size_t)w * 64 + 2 * lane];
    float v0 = fmaxf(cur.x + a0, 0.f);
    float v1 = fmaxf(cur.y + a1, 0.f);
    outb[(size_t)w * 32 + lane] = f2bf2(v0, v1);
}

// ---------------- fused: agg(layer3) + LayerNorm + node head --------------------
__global__ void k_agg_ln_node(const uint32_t* __restrict__ xr, const float* __restrict__ io,
                              uint32_t* __restrict__ x3out,
                              const float* __restrict__ gg, const float* __restrict__ bb,
                              const float* __restrict__ nw1, const float* __restrict__ nb1,
                              const float* __restrict__ nw2, const float* __restrict__ nb2,
                              float* __restrict__ outp) {
    __shared__ float s_w1[64 * 32];
    __shared__ float s_b1[32], s_w2[64], s_b2[2], s_g[64], s_bb[64];
    int tid = threadIdx.x;
    for (int i = tid; i < 2048; i += blockDim.x) s_w1[i] = nw1[i];
    if (tid < 32) s_b1[tid] = nb1[tid];
    if (tid < 64) { s_w2[tid] = nw2[tid]; s_g[tid] = gg[tid]; s_bb[tid] = bb[tid]; }
    if (tid < 2)  s_b2[tid] = nb2[tid];
    __syncthreads();

    int w = (blockIdx.x * blockDim.x + tid) >> 5;
    int lane = tid & 31;
    if (w >= NN) return;
    float a0 = 0.f, a1 = 0.f;
    agg_core(xr, w, lane, a0, a1);
    float2 cur = *(const float2*)&io[(size_t)w * 64 + 2 * lane];
    float v0 = cur.x + a0;
    float v1 = cur.y + a1;

    float s = v0 + v1;
#pragma unroll
    for (int off = 16; off; off >>= 1) s += __shfl_xor_sync(~0u, s, off);
    float mu = s * (1.f / 64.f);
    float d0 = v0 - mu, d1 = v1 - mu;
    float q = d0 * d0 + d1 * d1;
#pragma unroll
    for (int off = 16; off; off >>= 1) q += __shfl_xor_sync(~0u, q, off);
    float rs = rsqrtf(q * (1.f / 64.f) + 1e-5f);
    float xa = d0 * rs * s_g[2 * lane]     + s_bb[2 * lane];       // feat 2*lane
    float xb = d1 * rs * s_g[2 * lane + 1] + s_bb[2 * lane + 1];   // feat 2*lane+1
    x3out[(size_t)w * 32 + lane] = f2bf2(xa, xb);

    float acc = s_b1[lane];
#pragma unroll
    for (int k = 0; k < 32; k++) {
        float x0 = __shfl_sync(~0u, xa, k);   // feat 2k
        float x1 = __shfl_sync(~0u, xb, k);   // feat 2k+1
        acc += x0 * s_w1[(2 * k) * 32 + lane] + x1 * s_w1[(2 * k + 1) * 32 + lane];
    }
    float nh = fmaxf(acc, 0.f);
    float p0 = nh * s_w2[lane * 2 + 0];
    float p1 = nh * s_w2[lane * 2 + 1];
#pragma unroll
    for (int off = 16; off; off >>= 1) {
        p0 += __shfl_xor_sync(~0u, p0, off);
        p1 += __shfl_xor_sync(~0u, p1, off);
    }
    if (lane == 0) {
        float l0 = p0 + s_b2[0], l1 = p1 + s_b2[1];
        float mx = fmaxf(l0, l1);
        float lse = __logf(__expf(l0 - mx) + __expf(l1 - mx)) + mx;
        outp[(size_t)3 * EE + (size_t)w * 2 + 0] = l0 - lse;
        outp[(size_t)3 * EE + (size_t)w * 2 + 1] = l1 - lse;
    }
}

// ---------------- edge classifier, CSR order, bf16 gathers ----------------------
__global__ void k_edge(const uint2* __restrict__ ea2, const uint2* __restrict__ eb2v,
                       const float* __restrict__ eb1, const float* __restrict__ ew2,
                       const float* __restrict__ eb2, float* __restrict__ outp) {
    __shared__ float s_b1[64], s_w2[192], s_b2[3];
    int tid = threadIdx.x;
    if (tid < 64)  s_b1[tid] = eb1[tid];
    if (tid < 192) s_w2[tid] = ew2[tid];
    if (tid < 3)   s_b2[tid] = eb2[tid];
    __syncthreads();

    int gid = blockIdx.x * blockDim.x + tid;
    int p = gid >> 4, sub = tid & 15;
    if (p >= EE) return;
    int r  = g_srcl[p];
    int c  = g_dstl[p];
    int id = g_eidl[p];
    uint2 va = ea2[(size_t)r * 16 + sub];    // feats 4sub..4sub+3
    uint2 vb = eb2v[(size_t)c * 16 + sub];
    float h[4];
    h[0] = fmaxf(bflo(va.x) + bflo(vb.x) + s_b1[sub * 4 + 0], 0.f);
    h[1] = fmaxf(bfhi(va.x) + bfhi(vb.x) + s_b1[sub * 4 + 1], 0.f);
    h[2] = fmaxf(bflo(va.y) + bflo(vb.y) + s_b1[sub * 4 + 2], 0.f);
    h[3] = fmaxf(bfhi(va.y) + bfhi(vb.y) + s_b1[sub * 4 + 3], 0.f);
    float p0 = 0.f, p1 = 0.f, p2 = 0.f;
#pragma unroll
    for (int i = 0; i < 4; i++) {
        int f = sub * 4 + i;
        p0 += h[i] * s_w2[f * 3 + 0];
        p1 += h[i] * s_w2[f * 3 + 1];
        p2 += h[i] * s_w2[f * 3 + 2];
    }
#pragma unroll
    for (int off = 8; off; off >>= 1) {
        p0 += __shfl_xor_sync(~0u, p0, off);
        p1 += __shfl_xor_sync(~0u, p1, off);
        p2 += __shfl_xor_sync(~0u, p2, off);
    }
    if (sub == 0) {
        float l0 = p0 + s_b2[0], l1 = p1 + s_b2[1], l2 = p2 + s_b2[2];
        float mx = fmaxf(l0, fmaxf(l1, l2));
        float lse = __logf(__expf(l0 - mx) + __expf(l1 - mx) + __expf(l2 - mx)) + mx;
        outp[(size_t)id * 3 + 0] = l0 - lse;
        outp[(size_t)id * 3 + 1] = l1 - lse;
        outp[(size_t)id * 3 + 2] = l2 - lse;
    }
}

// ---------------- host orchestration -------------------------------------------
extern "C" void kernel_launch(void* const* d_in, const int* in_sizes, int n_in,
                              void* d_out, int out_size) {
    const float* x     = (const float*)d_in[0];
    const void*  eidx  = d_in[1];
    const void*  etyp  = d_in[2];
    const float* W1    = (const float*)d_in[3];
    const float* root1 = (const float*)d_in[4];
    const float* b1    = (const float*)d_in[5];
    const float* W2    = (const float*)d_in[6];
    const float* root2 = (const float*)d_in[7];
    const float* b2    = (const float*)d_in[8];
    const float* W3    = (const float*)d_in[9];
    const float* root3 = (const float*)d_in[10];
    const float* b3    = (const float*)d_in[11];
    const float* ln_g  = (const float*)d_in[12];
    const float* ln_b  = (const float*)d_in[13];
    const float* ew1   = (const float*)d_in[14];
    const float* eb1   = (const float*)d_in[15];
    const float* ew2   = (const float*)d_in[16];
    const float* eb2   = (const float*)d_in[17];
    const float* nw1   = (const float*)d_in[18];
    const float* nb1   = (const float*)d_in[19];
    const float* nw2   = (const float*)d_in[20];
    const float* nb2   = (const float*)d_in[21];
    float* out = (float*)d_out;

    float *p_bufa, *p_bufb;
    uint32_t *p_xr, *p_hb, *p_ea, *p_eb, *p_wt1, *p_wt2, *p_wt3, *p_wte;
    cudaGetSymbolAddress((void**)&p_xr,   g_xr);
    cudaGetSymbolAddress((void**)&p_bufa, g_bufa);
    cudaGetSymbolAddress((void**)&p_bufb, g_bufb);
    cudaGetSymbolAddress((void**)&p_hb,   g_hb);
    cudaGetSymbolAddress((void**)&p_ea,   g_ea);
    cudaGetSymbolAddress((void**)&p_eb,   g_eb);
    cudaGetSymbolAddress((void**)&p_wt1,  g_wt1);
    cudaGetSymbolAddress((void**)&p_wt2,  g_wt2);
    cudaGetSymbolAddress((void**)&p_wt3,  g_wt3);
    cudaGetSymbolAddress((void**)&p_wte,  g_wte);

    const int SMEM_F4 = 61440 + 3 * 4 * 6144;   // 135168 B (fp32-A, NT=4)
    const int SMEM_B4 = 30720 + 3 * 4 * 6144;   // 104448 B (bf16-A, NT=4)
    const int SMEM_B2 = 30720 + 3 * 2 * 6144;   //  67584 B (bf16-A, NT=2)
    cudaFuncSetAttribute((const void*)k_mma<4, 0>, cudaFuncAttributeMaxDynamicSharedMemorySize, SMEM_F4);
    cudaFuncSetAttribute((const void*)k_mma<4, 1>, cudaFuncAttributeMaxDynamicSharedMemorySize, SMEM_B4);
    cudaFuncSetAttribute((const void*)k_mma<2, 1>, cudaFuncAttributeMaxDynamicSharedMemorySize, SMEM_B2);

    int tiles = (NN + 127) / 128;            // 391
    int warpNBlocks = (NN * 32 + 255) / 256;
    int packN = 256 * 400 + 8192 + 8192 + 4096;
    int initB = SCANB + (packN + 255) / 256;
    size_t NH32 = (size_t)NN * 32;

    // 1-4: init(zero+detect+pack), convert+count, bsum, layer-1 GEMM (profiled)
    k_init<<<initB, 256>>>((const unsigned int*)eidx, W1, root1, W2, root2, W3, root3, ew1);
    k_convert<<<(EE + 255) / 256, 256>>>(eidx, etyp);
    k_bsum<<<SCANB, 256>>>();
    k_mma<4, 0><<<tiles, 512, SMEM_F4>>>(x, p_wt1, NN, FIN, 400,
                                         p_xr, p_xr + NH32, p_xr + 2 * NH32, p_bufa, b1);

    // 5-7: rest of CSR build
    k_bscan<<<1, 1024>>>();
    k_off<<<SCANB, 256>>>();
    k_scatter<<<(EE + 255) / 256, 256>>>();

    // 8: layer-1 aggregate + relu -> bf16 h1 (g_hb)
    k_agg<<<warpNBlocks, 256>>>(p_xr, p_bufa, p_hb);

    // 9-10: layer 2 (A = bf16 h1)
    k_mma<4, 1><<<tiles, 512, SMEM_B4>>>(p_hb, p_wt2, NN, 64, 32,
                                         p_xr, p_xr + NH32, p_xr + 2 * NH32, p_bufb, b2);
    k_agg<<<warpNBlocks, 256>>>(p_xr, p_bufb, p_hb);

    // 11-12: layer 3 + fused agg/LN/node-head (x3 bf16 -> g_hb)
    k_mma<4, 1><<<tiles, 512, SMEM_B4>>>(p_hb, p_wt3, NN, 64, 32,
                                         p_xr, p_xr + NH32, p_xr + 2 * NH32, p_bufa, b3);
    k_agg_ln_node<<<warpNBlocks, 256>>>(p_xr, p_bufa, p_hb, ln_g, ln_b,
                                        nw1, nb1, nw2, nb2, out);

    // 13-14: edge head (A = x3 bf16)
    k_mma<2, 1><<<tiles, 512, SMEM_B2>>>(p_hb, p_wte, NN, 64, 32,
                                         p_ea, p_eb, nullptr, nullptr, nullptr);
    k_edge<<<(EE * 16 + 255) / 256, 256>>>((const uint2*)p_ea, (const uint2*)p_eb,
                                           eb1, ew2, eb2, out);
}